// round 8
// baseline (speedup 1.0000x reference)
#include <cuda_runtime.h>
#include <cuda_fp16.h>
#include <math.h>

// ---------------------------------------------------------------------------
// Problem constants
// ---------------------------------------------------------------------------
#define BATCH   16384
#define LSEQ    200
#define CONCAT  244
#define KPAD    256    // padded K for fp16 GEMMs
#define NEXP    8
#define EHID    256
#define EOUT    128
#define NTASK   2
#define CHUNK   64
#define GLD     68     // K1 gather/h1 leading dim (fp32)
#define MLD     72     // K1 M leading dim
#define WLD     24     // K1 aW2 leading dim

// ---------------------------------------------------------------------------
// Scratch (static device globals — no allocation allowed)
// ---------------------------------------------------------------------------
__device__ float  g_S  [(long)BATCH * CONCAT];          // fp32 features (head)
__device__ __half g_Sh [(long)BATCH * KPAD];            // fp16 padded features (K2a)
__device__ __half g_ehh[(long)NEXP * BATCH * EHID];     // fp16 expert hidden
__device__ float  g_eo [(long)NEXP * BATCH * EOUT];     // fp32 expert out
__device__ __half g_W1t[(long)NEXP * EHID * KPAD];      // eW1 transposed [e][n][k]
__device__ __half g_W2t[(long)NEXP * EOUT * KPAD];      // eW2 transposed [e][n][k]

// ---------------------------------------------------------------------------
// cp.async helpers
// ---------------------------------------------------------------------------
__device__ __forceinline__ void cp_async16(void* smem_dst, const void* gsrc) {
    unsigned sm = (unsigned)__cvta_generic_to_shared(smem_dst);
    asm volatile("cp.async.cg.shared.global [%0], [%1], 16;\n" :: "r"(sm), "l"(gsrc));
}
__device__ __forceinline__ void cp_commit() {
    asm volatile("cp.async.commit_group;\n");
}
template <int N>
__device__ __forceinline__ void cp_wait() {
    asm volatile("cp.async.wait_group %0;\n" :: "n"(N));
}

// raw tf32 mma (K1): D += A(16x8,row) * B(8x8,col); fp32 bit patterns
__device__ __forceinline__ void mma_tf32(float* d, const float* a, const float* b) {
    asm volatile(
        "mma.sync.aligned.m16n8k8.row.col.f32.tf32.tf32.f32 "
        "{%0,%1,%2,%3}, {%4,%5,%6,%7}, {%8,%9}, {%0,%1,%2,%3};\n"
        : "+f"(d[0]), "+f"(d[1]), "+f"(d[2]), "+f"(d[3])
        : "r"(__float_as_uint(a[0])), "r"(__float_as_uint(a[1])),
          "r"(__float_as_uint(a[2])), "r"(__float_as_uint(a[3])),
          "r"(__float_as_uint(b[0])), "r"(__float_as_uint(b[1])));
}

// raw fp16 mma (K2): D += A(16x16,row) * B(16x8,col); packed half2 operands
//   A: a0={A[qr][2qc],A[qr][2qc+1]}  a1=rows+8  a2=cols+8  a3=both
//   B: b0={B[2qc][qr],B[2qc+1][qr]}  b1=k+8     (Bt[n][k] storage -> contiguous)
//   C: c0=C[qr][2qc] c1=C[qr][2qc+1] c2/c3=rows+8
__device__ __forceinline__ void mma_f16(float* d, const unsigned* a, const unsigned* b) {
    asm volatile(
        "mma.sync.aligned.m16n8k16.row.col.f32.f16.f16.f32 "
        "{%0,%1,%2,%3}, {%4,%5,%6,%7}, {%8,%9}, {%0,%1,%2,%3};\n"
        : "+f"(d[0]), "+f"(d[1]), "+f"(d[2]), "+f"(d[3])
        : "r"(a[0]), "r"(a[1]), "r"(a[2]), "r"(a[3]),
          "r"(b[0]), "r"(b[1]));
}

// ---------------------------------------------------------------------------
// Kernel 0: weight prep — transpose + fp16-convert expert weights (K padded)
// ---------------------------------------------------------------------------
__global__ void __launch_bounds__(256)
prep_weights(const float* __restrict__ eW1, const float* __restrict__ eW2,
             __half* __restrict__ W1t, __half* __restrict__ W2t)
{
    const int i = blockIdx.x * 256 + threadIdx.x;
    const int n1 = NEXP * EHID * KPAD;            // 524288
    if (i < n1) {
        const int e = i >> 16, n = (i >> 8) & 255, k = i & 255;
        const float v = (k < CONCAT) ? eW1[((long)e * CONCAT + k) * EHID + n] : 0.f;
        W1t[i] = __float2half(v);
    } else {
        const int j = i - n1;
        if (j < NEXP * EOUT * KPAD) {
            const int e = j >> 15, n = (j >> 8) & 127, k = j & 255;
            W2t[j] = __float2half(eW2[((long)e * EHID + k) * EOUT + n]);
        }
    }
}

// ---------------------------------------------------------------------------
// Kernel 1: DIN attention + fused online pooling + feature concat (tf32 mma)
// (unchanged from R6 except fp16 S copy in the epilogue)
// ---------------------------------------------------------------------------
struct AttnSmem {
    float gb[3][CHUNK * GLD];
    float h1[CHUNK * GLD];
    float M[64 * MLD];
    float aW2s[64 * WLD];
    float part[4][64];
    float ibuf[64];
    float tvec[64];
    float base[64];
    float poolred[64];
    float sc[CHUNK];
    float aW3s[16];
    float ab2s[16];
    float red[8];
    float denom;
    int   seqs[LSEQ];
};

__global__ void __launch_bounds__(256)
attn_kernel(const int* __restrict__ uid, const int* __restrict__ iid,
            const int* __restrict__ cid, const int* __restrict__ did,
            const float* __restrict__ udense, const float* __restrict__ idense,
            const int* __restrict__ hseq,
            const float* __restrict__ userE, const float* __restrict__ itemE,
            const float* __restrict__ catE,  const float* __restrict__ durE,
            const float* __restrict__ histE, const float* __restrict__ Wproj,
            const float* __restrict__ aW1, const float* __restrict__ ab1,
            const float* __restrict__ aW2, const float* __restrict__ ab2,
            const float* __restrict__ aW3, const float* __restrict__ ab3,
            float* __restrict__ Sout, __half* __restrict__ Shout)
{
    extern __shared__ unsigned char smem_raw[];
    AttnSmem& s = *reinterpret_cast<AttnSmem*>(smem_raw);

    const int b    = blockIdx.x;
    const int tid  = threadIdx.x;
    const int lane = tid & 31;
    const int warp = tid >> 5;
    const int qr   = lane >> 2;
    const int qc   = lane & 3;

    const int item = iid[b];
    if (tid < 64) s.ibuf[tid] = itemE[(long)item * 64 + tid];
    for (int i = tid; i < 64 * WLD; i += 256) {
        const int r = i / WLD, c = i - r * WLD;
        s.aW2s[i] = (c < 16) ? aW2[r * 16 + c] : 0.f;
    }
    if (tid < 16) { s.aW3s[tid] = aW3[tid]; s.ab2s[tid] = ab2[tid]; }
    for (int l = tid; l < LSEQ; l += 256) s.seqs[l] = hseq[(long)b * LSEQ + l];
    if (tid == 0) s.denom = 0.f;
    __syncthreads();

    #pragma unroll
    for (int h = 0; h < 4; h++) {
        const int idx = tid + h * 256;
        const int row = idx >> 4;
        const int c4  = (idx & 15) * 4;
        cp_async16(&s.gb[0][row * GLD + c4], histE + (long)s.seqs[row] * 64 + c4);
    }
    cp_commit();

    {
        const int j = tid & 63, q = tid >> 6;
        float acc = 0.f;
        #pragma unroll
        for (int k = q * 16; k < q * 16 + 16; k++)
            acc += s.ibuf[k] * Wproj[k * 64 + j];
        s.part[q][j] = acc;
    }
    __syncthreads();
    if (tid < 64)
        s.tvec[tid] = s.part[0][tid] + s.part[1][tid] + s.part[2][tid] + s.part[3][tid];
    __syncthreads();

    if (tid < 64) {
        float acc = ab1[tid];
        #pragma unroll 4
        for (int k = 0; k < 64; k++)
            acc += s.tvec[k] * (aW1[k * 64 + tid] + aW1[(128 + k) * 64 + tid]);
        s.base[tid] = acc;
    }
    for (int idx = tid; idx < 64 * 64; idx += 256) {
        const int k = idx >> 6, j = idx & 63;
        s.M[k * MLD + j] = aW1[(64 + k) * 64 + j] - aW1[(128 + k) * 64 + j]
                         + s.tvec[k] * aW1[(192 + k) * 64 + j];
    }
    s.part[tid >> 6][tid & 63] = 0.f;
    __syncthreads();

    const float ab3v = ab3[0];

    for (int c = 0; c < 4; c++) {
        if (c < 3) {
            const int c0n = (c + 1) * CHUNK;
            float* dst = s.gb[(c + 1) % 3];
            #pragma unroll
            for (int h = 0; h < 4; h++) {
                const int idx = tid + h * 256;
                const int row = idx >> 4;
                const int c4  = (idx & 15) * 4;
                const int l = c0n + row;
                const int sid = (l < LSEQ) ? s.seqs[l] : 0;
                cp_async16(&dst[row * GLD + c4], histE + (long)sid * 64 + c4);
            }
            cp_commit();
            cp_wait<1>();
        } else {
            cp_wait<0>();
        }
        __syncthreads();

        const float* gbuf = s.gb[c % 3];

        {
            const int r   = warp & 3;
            const int cpp = warp >> 2;
            const int rowA = (r * 16 + qr) * GLD;
            float acc1[4][4];
            #pragma unroll
            for (int ni = 0; ni < 4; ni++) {
                const int n0 = cpp * 32 + ni * 8;
                acc1[ni][0] = s.base[n0 + 2 * qc];
                acc1[ni][1] = s.base[n0 + 2 * qc + 1];
                acc1[ni][2] = acc1[ni][0];
                acc1[ni][3] = acc1[ni][1];
            }
            #pragma unroll
            for (int ks = 0; ks < 8; ks++) {
                float a[4];
                const float* ap = &gbuf[rowA + ks * 8 + qc];
                a[0] = ap[0];
                a[1] = ap[8 * GLD];
                a[2] = ap[4];
                a[3] = ap[8 * GLD + 4];
                #pragma unroll
                for (int ni = 0; ni < 4; ni++) {
                    float bv[2];
                    const float* bp = &s.M[(ks * 8 + qc) * MLD + cpp * 32 + ni * 8 + qr];
                    bv[0] = bp[0];
                    bv[1] = bp[4 * MLD];
                    mma_tf32(acc1[ni], a, bv);
                }
            }
            #pragma unroll
            for (int ni = 0; ni < 4; ni++) {
                const int n0 = cpp * 32 + ni * 8;
                float2 v0 = make_float2(fmaxf(acc1[ni][0], 0.f), fmaxf(acc1[ni][1], 0.f));
                float2 v1 = make_float2(fmaxf(acc1[ni][2], 0.f), fmaxf(acc1[ni][3], 0.f));
                *reinterpret_cast<float2*>(&s.h1[(r * 16 + qr) * GLD + n0 + 2 * qc]) = v0;
                *reinterpret_cast<float2*>(&s.h1[(r * 16 + qr + 8) * GLD + n0 + 2 * qc]) = v1;
            }
        }
        __syncthreads();

        if (warp < 4) {
            float acc2[2][4];
            #pragma unroll
            for (int ni = 0; ni < 2; ni++) {
                acc2[ni][0] = s.ab2s[ni * 8 + 2 * qc];
                acc2[ni][1] = s.ab2s[ni * 8 + 2 * qc + 1];
                acc2[ni][2] = acc2[ni][0];
                acc2[ni][3] = acc2[ni][1];
            }
            const int rowA = (warp * 16 + qr) * GLD;
            #pragma unroll
            for (int ks = 0; ks < 8; ks++) {
                float a[4];
                const float* ap = &s.h1[rowA + ks * 8 + qc];
                a[0] = ap[0];
                a[1] = ap[8 * GLD];
                a[2] = ap[4];
                a[3] = ap[8 * GLD + 4];
                #pragma unroll
                for (int ni = 0; ni < 2; ni++) {
                    float bv[2];
                    const float* bp = &s.aW2s[(ks * 8 + qc) * WLD + ni * 8 + qr];
                    bv[0] = bp[0];
                    bv[1] = bp[4 * WLD];
                    mma_tf32(acc2[ni], a, bv);
                }
            }
            float w0 = 0.f, w1 = 0.f;
            #pragma unroll
            for (int ni = 0; ni < 2; ni++) {
                const float g0 = s.aW3s[ni * 8 + 2 * qc];
                const float g1 = s.aW3s[ni * 8 + 2 * qc + 1];
                w0 += fmaxf(acc2[ni][0], 0.f) * g0 + fmaxf(acc2[ni][1], 0.f) * g1;
                w1 += fmaxf(acc2[ni][2], 0.f) * g0 + fmaxf(acc2[ni][3], 0.f) * g1;
            }
            w0 += __shfl_xor_sync(0xffffffffu, w0, 1);
            w0 += __shfl_xor_sync(0xffffffffu, w0, 2);
            w1 += __shfl_xor_sync(0xffffffffu, w1, 1);
            w1 += __shfl_xor_sync(0xffffffffu, w1, 2);
            float e0 = 0.f, e1 = 0.f;
            if (qc == 0) {
                const int l0 = c * CHUNK + warp * 16 + qr;
                const int l1 = l0 + 8;
                if (l0 < LSEQ && s.seqs[l0] != 0) e0 = __expf(w0 + ab3v);
                if (l1 < LSEQ && s.seqs[l1] != 0) e1 = __expf(w1 + ab3v);
                s.sc[warp * 16 + qr]     = e0;
                s.sc[warp * 16 + qr + 8] = e1;
            }
            float tot = e0 + e1;
            #pragma unroll
            for (int off = 16; off >= 1; off >>= 1)
                tot += __shfl_xor_sync(0xffffffffu, tot, off);
            if (lane == 0) s.red[warp] = tot;
        }
        __syncthreads();

        if (tid == 0) s.denom += s.red[0] + s.red[1] + s.red[2] + s.red[3];

        {
            const int d = tid & 63, g = tid >> 6;
            float acc = s.part[g][d];
            #pragma unroll
            for (int i = 0; i < 16; i++) {
                const int l = g * 16 + i;
                acc += s.sc[l] * gbuf[l * GLD + d];
            }
            s.part[g][d] = acc;
        }
    }
    __syncthreads();

    if (tid < 64)
        s.poolred[tid] = (s.part[0][tid] + s.part[1][tid] + s.part[2][tid] + s.part[3][tid])
                       * (1.f / s.denom);
    __syncthreads();

    {
        float v = 0.f;
        if (tid < CONCAT) {
            if      (tid < 64)  v = userE[(long)uid[b] * 64 + tid];
            else if (tid < 128) v = s.ibuf[tid - 64];
            else if (tid < 144) v = catE[(long)cid[b] * 16 + (tid - 128)];
            else if (tid < 152) v = durE[(long)did[b] * 8 + (tid - 144)];
            else if (tid < 177) v = udense[(long)b * 25 + (tid - 152)];
            else if (tid < 180) v = idense[(long)b * 3 + (tid - 177)];
            else                v = s.poolred[tid - 180];
            Sout[(long)b * CONCAT + tid] = v;
        }
        Shout[(long)b * KPAD + tid] = __float2half(v);   // fp16 padded copy
    }
}

// ---------------------------------------------------------------------------
// Kernel 2: batched fp16 GEMM + bias + ReLU (mma.m16n8k16), 4-stage cp.async.
// A [M][KPAD] fp16 row-major, Bt [N][KPAD] fp16 (transposed weights).
// Block tile 128x128, BK=16 halves, 8 warps (2x4), warp tile 64x32.
// ---------------------------------------------------------------------------
#define TBM 128
#define TBN 128
#define TBK 16
#define NSTG 4
#define HL  24       // halves per smem row (16 + 8 pad; bank-stride 12)

#define HGEMM_SMEM ((NSTG * TBM * HL + NSTG * TBN * HL) * 2)

template <bool OUT_HALF>
__global__ void __launch_bounds__(256, 2)
hgemm_bias_relu(const __half* __restrict__ A, const __half* __restrict__ Bt,
                const float* __restrict__ bias, void* __restrict__ Cout,
                int M, int N,
                size_t sA, size_t sB, size_t sBias, size_t sC)
{
    extern __shared__ __half smemh[];
    __half* As = smemh;                        // NSTG * TBM * HL
    __half* Bs = smemh + NSTG * TBM * HL;      // NSTG * TBN * HL

    const int z = blockIdx.z;
    A += (size_t)z * sA; Bt += (size_t)z * sB;
    bias += (size_t)z * sBias;

    const int m0 = blockIdx.y * TBM;
    const int n0 = blockIdx.x * TBN;
    const int tid = threadIdx.x;
    const int lane = tid & 31;
    const int warp = tid >> 5;
    const int wr = warp >> 2;            // 0..1 -> 64 rows
    const int wc = warp & 3;             // 0..3 -> 32 cols
    const int qr = lane >> 2;
    const int qc = lane & 3;

    const int nk = KPAD / TBK;           // 16

    const int l_row = tid >> 1;          // 0..127
    const int l_hc  = (tid & 1) * 8;     // half offset 0/8

    auto load_stage = [&](int st, int k0) {
        __half* as = As + st * TBM * HL;
        __half* bs = Bs + st * TBN * HL;
        cp_async16(&as[l_row * HL + l_hc], A  + (size_t)(m0 + l_row) * KPAD + k0 + l_hc);
        cp_async16(&bs[l_row * HL + l_hc], Bt + (size_t)(n0 + l_row) * KPAD + k0 + l_hc);
    };

    float acc[4][4][4];
    #pragma unroll
    for (int i = 0; i < 4; i++)
        #pragma unroll
        for (int j = 0; j < 4; j++)
            #pragma unroll
            for (int e = 0; e < 4; e++) acc[i][j][e] = 0.f;

    #pragma unroll
    for (int s0 = 0; s0 < NSTG - 1; s0++) {
        load_stage(s0, s0 * TBK);
        cp_commit();
    }

    for (int kt = 0; kt < nk; kt++) {
        cp_wait<NSTG - 2>();
        __syncthreads();

        const int knext = kt + NSTG - 1;
        if (knext < nk) load_stage(knext % NSTG, knext * TBK);
        cp_commit();

        const __half* as = As + (kt % NSTG) * TBM * HL;
        const __half* bs = Bs + (kt % NSTG) * TBN * HL;

        unsigned a[4][4], bfr[4][2];
        #pragma unroll
        for (int mi = 0; mi < 4; mi++) {
            const int r = wr * 64 + mi * 16 + qr;
            a[mi][0] = *reinterpret_cast<const unsigned*>(as + r * HL + 2 * qc);
            a[mi][1] = *reinterpret_cast<const unsigned*>(as + (r + 8) * HL + 2 * qc);
            a[mi][2] = *reinterpret_cast<const unsigned*>(as + r * HL + 2 * qc + 8);
            a[mi][3] = *reinterpret_cast<const unsigned*>(as + (r + 8) * HL + 2 * qc + 8);
        }
        #pragma unroll
        for (int ni = 0; ni < 4; ni++) {
            const int n = wc * 32 + ni * 8 + qr;
            bfr[ni][0] = *reinterpret_cast<const unsigned*>(bs + n * HL + 2 * qc);
            bfr[ni][1] = *reinterpret_cast<const unsigned*>(bs + n * HL + 2 * qc + 8);
        }
        #pragma unroll
        for (int mi = 0; mi < 4; mi++)
            #pragma unroll
            for (int ni = 0; ni < 4; ni++)
                mma_f16(acc[mi][ni], a[mi], bfr[ni]);

        __syncthreads();
    }

    // epilogue: bias + relu
    #pragma unroll
    for (int mi = 0; mi < 4; mi++) {
        #pragma unroll
        for (int ni = 0; ni < 4; ni++) {
            const int gm = m0 + wr * 64 + mi * 16 + qr;
            const int gn = n0 + wc * 32 + ni * 8 + qc * 2;
            const float b0 = bias[gn], b1 = bias[gn + 1];
            const float v0 = fmaxf(acc[mi][ni][0] + b0, 0.f);
            const float v1 = fmaxf(acc[mi][ni][1] + b1, 0.f);
            const float v2 = fmaxf(acc[mi][ni][2] + b0, 0.f);
            const float v3 = fmaxf(acc[mi][ni][3] + b1, 0.f);
            if (OUT_HALF) {
                __half* C = (__half*)Cout + (size_t)z * sC;
                *reinterpret_cast<__half2*>(C + (size_t)gm * N + gn) =
                    __floats2half2_rn(v0, v1);
                *reinterpret_cast<__half2*>(C + (size_t)(gm + 8) * N + gn) =
                    __floats2half2_rn(v2, v3);
            } else {
                float* C = (float*)Cout + (size_t)z * sC;
                *reinterpret_cast<float2*>(C + (size_t)gm * N + gn) = make_float2(v0, v1);
                *reinterpret_cast<float2*>(C + (size_t)(gm + 8) * N + gn) = make_float2(v2, v3);
            }
        }
    }
}

// ---------------------------------------------------------------------------
// Kernel 3: gates (softmax) + expert mix + towers + sigmoid
// ---------------------------------------------------------------------------
__global__ void __launch_bounds__(256)
head_kernel(const float* __restrict__ S, const float* __restrict__ eo,
            const float* __restrict__ gW, const float* __restrict__ gb,
            const float* __restrict__ tW1, const float* __restrict__ tb1,
            const float* __restrict__ tW2, const float* __restrict__ tb2,
            const float* __restrict__ tW3, const float* __restrict__ tb3,
            float* __restrict__ out)
{
    __shared__ float Srow[4][CONCAT];
    __shared__ float gate[4][16];
    __shared__ float ti[4][NTASK][EOUT];
    __shared__ float x1[4][NTASK][64];
    __shared__ float x2[4][NTASK][32];

    const int g = threadIdx.x >> 6;
    const int lane = threadIdx.x & 63;
    const int b = blockIdx.x * 4 + g;

    for (int c = lane; c < CONCAT; c += 64) Srow[g][c] = S[(long)b * CONCAT + c];
    __syncthreads();

    {
        const int o = lane >> 2;
        const int q = lane & 3;
        const int t = o >> 3, e = o & 7;
        const int c0 = q * 61;
        float acc = 0.f;
        #pragma unroll 8
        for (int c = c0; c < c0 + 61; c++)
            acc += Srow[g][c] * __ldg(&gW[((long)t * CONCAT + c) * 8 + e]);
        acc += __shfl_xor_sync(0xffffffffu, acc, 1);
        acc += __shfl_xor_sync(0xffffffffu, acc, 2);
        if (q == 0) gate[g][o] = acc + gb[t * 8 + e];
    }
    __syncthreads();
    if (lane < 2) {
        const int t = lane;
        float mx = -3.4e38f;
        for (int e = 0; e < 8; e++) mx = fmaxf(mx, gate[g][t * 8 + e]);
        float sum = 0.f, ex[8];
        for (int e = 0; e < 8; e++) { ex[e] = __expf(gate[g][t * 8 + e] - mx); sum += ex[e]; }
        const float is = 1.f / sum;
        for (int e = 0; e < 8; e++) gate[g][t * 8 + e] = ex[e] * is;
    }
    __syncthreads();

    {
        const int t = lane >> 5;
        const int o = (lane & 31) * 4;
        float4 acc = make_float4(0.f, 0.f, 0.f, 0.f);
        #pragma unroll
        for (int e = 0; e < 8; e++) {
            const float gv = gate[g][t * 8 + e];
            const float4 v = *reinterpret_cast<const float4*>(
                eo + ((long)e * BATCH + b) * EOUT + o);
            acc.x += gv * v.x; acc.y += gv * v.y;
            acc.z += gv * v.z; acc.w += gv * v.w;
        }
        *reinterpret_cast<float4*>(&ti[g][t][o]) = acc;
    }
    __syncthreads();

    for (int idx = lane; idx < NTASK * 64; idx += 64) {
        const int t = idx >> 6, j = idx & 63;
        float acc = tb1[t * 64 + j];
        #pragma unroll 8
        for (int o = 0; o < 128; o++)
            acc += ti[g][t][o] * __ldg(&tW1[((long)t * 128 + o) * 64 + j]);
        x1[g][t][j] = fmaxf(acc, 0.f);
    }
    __syncthreads();

    {
        const int t = lane >> 5, m = lane & 31;
        float acc = tb2[t * 32 + m];
        #pragma unroll 8
        for (int j = 0; j < 64; j++)
            acc += x1[g][t][j] * __ldg(&tW2[(t * 64 + j) * 32 + m]);
        x2[g][t][m] = fmaxf(acc, 0.f);
    }
    __syncthreads();

    if (lane < 2) {
        const int t = lane;
        float acc = tb3[t];
        #pragma unroll
        for (int m = 0; m < 32; m++) acc += x2[g][t][m] * tW3[t * 32 + m];
        out[(long)t * BATCH + b] = 1.f / (1.f + __expf(-acc));
    }
}

// ---------------------------------------------------------------------------
// Launch
// ---------------------------------------------------------------------------
extern "C" void kernel_launch(void* const* d_in, const int* in_sizes, int n_in,
                              void* d_out, int out_size)
{
    const int*   uid    = (const int*)  d_in[0];
    const int*   iid    = (const int*)  d_in[1];
    const int*   cid    = (const int*)  d_in[2];
    const int*   did    = (const int*)  d_in[3];
    const float* udense = (const float*)d_in[4];
    const float* idense = (const float*)d_in[5];
    const int*   hseq   = (const int*)  d_in[6];
    const float* userE  = (const float*)d_in[7];
    const float* itemE  = (const float*)d_in[8];
    const float* catE   = (const float*)d_in[9];
    const float* durE   = (const float*)d_in[10];
    const float* histE  = (const float*)d_in[11];
    const float* Wproj  = (const float*)d_in[12];
    const float* aW1    = (const float*)d_in[13];
    const float* ab1    = (const float*)d_in[14];
    const float* aW2    = (const float*)d_in[15];
    const float* ab2    = (const float*)d_in[16];
    const float* aW3    = (const float*)d_in[17];
    const float* ab3    = (const float*)d_in[18];
    const float* eW1    = (const float*)d_in[19];
    const float* eb1    = (const float*)d_in[20];
    const float* eW2    = (const float*)d_in[21];
    const float* eb2    = (const float*)d_in[22];
    const float* gW     = (const float*)d_in[23];
    const float* gb     = (const float*)d_in[24];
    const float* tW1    = (const float*)d_in[25];
    const float* tb1    = (const float*)d_in[26];
    const float* tW2    = (const float*)d_in[27];
    const float* tb2    = (const float*)d_in[28];
    const float* tW3    = (const float*)d_in[29];
    const float* tb3    = (const float*)d_in[30];
    float* out = (float*)d_out;

    float  *pS, *pEo;
    __half *pSh, *pEh, *pW1t, *pW2t;
    cudaGetSymbolAddress((void**)&pS,   g_S);
    cudaGetSymbolAddress((void**)&pSh,  g_Sh);
    cudaGetSymbolAddress((void**)&pEh,  g_ehh);
    cudaGetSymbolAddress((void**)&pEo,  g_eo);
    cudaGetSymbolAddress((void**)&pW1t, g_W1t);
    cudaGetSymbolAddress((void**)&pW2t, g_W2t);

    const int attn_smem = (int)sizeof(AttnSmem);
    cudaFuncSetAttribute(attn_kernel, cudaFuncAttributeMaxDynamicSharedMemorySize, attn_smem);
    cudaFuncSetAttribute(hgemm_bias_relu<true>,  cudaFuncAttributeMaxDynamicSharedMemorySize, HGEMM_SMEM);
    cudaFuncSetAttribute(hgemm_bias_relu<false>, cudaFuncAttributeMaxDynamicSharedMemorySize, HGEMM_SMEM);

    // K0: weight prep (fp16 transpose, K padded to 256)
    prep_weights<<<(NEXP * EHID * KPAD + NEXP * EOUT * KPAD) / 256, 256>>>(
        eW1, eW2, pW1t, pW2t);

    // K1: attention + feature concat (fp32 S + fp16 padded S)
    attn_kernel<<<BATCH, 256, attn_smem>>>(
        uid, iid, cid, did, udense, idense, hseq,
        userE, itemE, catE, durE, histE, Wproj,
        aW1, ab1, aW2, ab2, aW3, ab3, pS, pSh);

    // K2a: eh = relu(S @ eW1 + eb1), fp16 in/out (A shared across experts)
    hgemm_bias_relu<true><<<dim3(EHID / TBN, BATCH / TBM, NEXP), 256, HGEMM_SMEM>>>(
        pSh, pW1t, eb1, pEh,
        BATCH, EHID,
        (size_t)0, (size_t)EHID * KPAD, (size_t)EHID, (size_t)BATCH * EHID);

    // K2b: eo = relu(eh @ eW2 + eb2), fp16 in, fp32 out
    hgemm_bias_relu<false><<<dim3(EOUT / TBN, BATCH / TBM, NEXP), 256, HGEMM_SMEM>>>(
        pEh, pW2t, eb2, pEo,
        BATCH, EOUT,
        (size_t)BATCH * EHID, (size_t)EOUT * KPAD, (size_t)EOUT, (size_t)BATCH * EOUT);

    // K3: gates + mix + towers + sigmoid
    head_kernel<<<BATCH / 4, 256>>>(
        pS, pEo, gW, gb, tW1, tb1, tW2, tb2, tW3, tb3, out);
}

// round 9
// speedup vs baseline: 1.0002x; 1.0002x over previous
#include <cuda_runtime.h>
#include <cuda_fp16.h>
#include <math.h>

// ---------------------------------------------------------------------------
// Problem constants
// ---------------------------------------------------------------------------
#define BATCH   16384
#define LSEQ    200
#define CONCAT  244
#define KPAD    256    // padded K for fp16 GEMMs
#define NEXP    8
#define EHID    256
#define EOUT    128
#define NTASK   2
#define CHUNK   64
#define GLD     68     // K1 gather/h1 leading dim (fp32)
#define MLD     72     // K1 M leading dim
#define WLD     24     // K1 aW2 leading dim

// ---------------------------------------------------------------------------
// Scratch (static device globals — no allocation allowed)
// ---------------------------------------------------------------------------
__device__ float  g_S  [(long)BATCH * CONCAT];          // fp32 features (head)
__device__ __half g_Sh [(long)BATCH * KPAD];            // fp16 padded features (K2a)
__device__ __half g_ehh[(long)NEXP * BATCH * EHID];     // fp16 expert hidden
__device__ float  g_eo [(long)NEXP * BATCH * EOUT];     // fp32 expert out
__device__ __half g_W1t[(long)NEXP * EHID * KPAD];      // eW1 transposed [e][n][k]
__device__ __half g_W2t[(long)NEXP * EOUT * KPAD];      // eW2 transposed [e][n][k]

// ---------------------------------------------------------------------------
// cp.async helpers
// ---------------------------------------------------------------------------
__device__ __forceinline__ void cp_async16(void* smem_dst, const void* gsrc) {
    unsigned sm = (unsigned)__cvta_generic_to_shared(smem_dst);
    asm volatile("cp.async.cg.shared.global [%0], [%1], 16;\n" :: "r"(sm), "l"(gsrc));
}
__device__ __forceinline__ void cp_commit() {
    asm volatile("cp.async.commit_group;\n");
}
template <int N>
__device__ __forceinline__ void cp_wait() {
    asm volatile("cp.async.wait_group %0;\n" :: "n"(N));
}

// raw tf32 mma (K1): D += A(16x8,row) * B(8x8,col); fp32 bit patterns
__device__ __forceinline__ void mma_tf32(float* d, const float* a, const float* b) {
    asm volatile(
        "mma.sync.aligned.m16n8k8.row.col.f32.tf32.tf32.f32 "
        "{%0,%1,%2,%3}, {%4,%5,%6,%7}, {%8,%9}, {%0,%1,%2,%3};\n"
        : "+f"(d[0]), "+f"(d[1]), "+f"(d[2]), "+f"(d[3])
        : "r"(__float_as_uint(a[0])), "r"(__float_as_uint(a[1])),
          "r"(__float_as_uint(a[2])), "r"(__float_as_uint(a[3])),
          "r"(__float_as_uint(b[0])), "r"(__float_as_uint(b[1])));
}

// raw fp16 mma (K2): D += A(16x16,row) * B(16x8,col); packed half2 operands
//   A: a0={A[qr][2qc],A[qr][2qc+1]}  a1=rows+8  a2=cols+8  a3=both
//   B: b0={B[2qc][qr],B[2qc+1][qr]}  b1=k+8     (Bt[n][k] storage -> contiguous)
//   C: c0=C[qr][2qc] c1=C[qr][2qc+1] c2/c3=rows+8
__device__ __forceinline__ void mma_f16(float* d, const unsigned* a, const unsigned* b) {
    asm volatile(
        "mma.sync.aligned.m16n8k16.row.col.f32.f16.f16.f32 "
        "{%0,%1,%2,%3}, {%4,%5,%6,%7}, {%8,%9}, {%0,%1,%2,%3};\n"
        : "+f"(d[0]), "+f"(d[1]), "+f"(d[2]), "+f"(d[3])
        : "r"(a[0]), "r"(a[1]), "r"(a[2]), "r"(a[3]),
          "r"(b[0]), "r"(b[1]));
}

// ---------------------------------------------------------------------------
// Kernel 0: weight prep — transpose + fp16-convert expert weights (K padded)
// ---------------------------------------------------------------------------
__global__ void __launch_bounds__(256)
prep_weights(const float* __restrict__ eW1, const float* __restrict__ eW2,
             __half* __restrict__ W1t, __half* __restrict__ W2t)
{
    const int i = blockIdx.x * 256 + threadIdx.x;
    const int n1 = NEXP * EHID * KPAD;            // 524288
    if (i < n1) {
        const int e = i >> 16, n = (i >> 8) & 255, k = i & 255;
        const float v = (k < CONCAT) ? eW1[((long)e * CONCAT + k) * EHID + n] : 0.f;
        W1t[i] = __float2half(v);
    } else {
        const int j = i - n1;
        if (j < NEXP * EOUT * KPAD) {
            const int e = j >> 15, n = (j >> 8) & 127, k = j & 255;
            W2t[j] = __float2half(eW2[((long)e * EHID + k) * EOUT + n]);
        }
    }
}

// ---------------------------------------------------------------------------
// Kernel 1: DIN attention + fused online pooling + feature concat (tf32 mma)
// (unchanged from R6 except fp16 S copy in the epilogue)
// ---------------------------------------------------------------------------
struct AttnSmem {
    float gb[3][CHUNK * GLD];
    float h1[CHUNK * GLD];
    float M[64 * MLD];
    float aW2s[64 * WLD];
    float part[4][64];
    float ibuf[64];
    float tvec[64];
    float base[64];
    float poolred[64];
    float sc[CHUNK];
    float aW3s[16];
    float ab2s[16];
    float red[8];
    float denom;
    int   seqs[LSEQ];
};

__global__ void __launch_bounds__(256)
attn_kernel(const int* __restrict__ uid, const int* __restrict__ iid,
            const int* __restrict__ cid, const int* __restrict__ did,
            const float* __restrict__ udense, const float* __restrict__ idense,
            const int* __restrict__ hseq,
            const float* __restrict__ userE, const float* __restrict__ itemE,
            const float* __restrict__ catE,  const float* __restrict__ durE,
            const float* __restrict__ histE, const float* __restrict__ Wproj,
            const float* __restrict__ aW1, const float* __restrict__ ab1,
            const float* __restrict__ aW2, const float* __restrict__ ab2,
            const float* __restrict__ aW3, const float* __restrict__ ab3,
            float* __restrict__ Sout, __half* __restrict__ Shout)
{
    extern __shared__ unsigned char smem_raw[];
    AttnSmem& s = *reinterpret_cast<AttnSmem*>(smem_raw);

    const int b    = blockIdx.x;
    const int tid  = threadIdx.x;
    const int lane = tid & 31;
    const int warp = tid >> 5;
    const int qr   = lane >> 2;
    const int qc   = lane & 3;

    const int item = iid[b];
    if (tid < 64) s.ibuf[tid] = itemE[(long)item * 64 + tid];
    for (int i = tid; i < 64 * WLD; i += 256) {
        const int r = i / WLD, c = i - r * WLD;
        s.aW2s[i] = (c < 16) ? aW2[r * 16 + c] : 0.f;
    }
    if (tid < 16) { s.aW3s[tid] = aW3[tid]; s.ab2s[tid] = ab2[tid]; }
    for (int l = tid; l < LSEQ; l += 256) s.seqs[l] = hseq[(long)b * LSEQ + l];
    if (tid == 0) s.denom = 0.f;
    __syncthreads();

    #pragma unroll
    for (int h = 0; h < 4; h++) {
        const int idx = tid + h * 256;
        const int row = idx >> 4;
        const int c4  = (idx & 15) * 4;
        cp_async16(&s.gb[0][row * GLD + c4], histE + (long)s.seqs[row] * 64 + c4);
    }
    cp_commit();

    {
        const int j = tid & 63, q = tid >> 6;
        float acc = 0.f;
        #pragma unroll
        for (int k = q * 16; k < q * 16 + 16; k++)
            acc += s.ibuf[k] * Wproj[k * 64 + j];
        s.part[q][j] = acc;
    }
    __syncthreads();
    if (tid < 64)
        s.tvec[tid] = s.part[0][tid] + s.part[1][tid] + s.part[2][tid] + s.part[3][tid];
    __syncthreads();

    if (tid < 64) {
        float acc = ab1[tid];
        #pragma unroll 4
        for (int k = 0; k < 64; k++)
            acc += s.tvec[k] * (aW1[k * 64 + tid] + aW1[(128 + k) * 64 + tid]);
        s.base[tid] = acc;
    }
    for (int idx = tid; idx < 64 * 64; idx += 256) {
        const int k = idx >> 6, j = idx & 63;
        s.M[k * MLD + j] = aW1[(64 + k) * 64 + j] - aW1[(128 + k) * 64 + j]
                         + s.tvec[k] * aW1[(192 + k) * 64 + j];
    }
    s.part[tid >> 6][tid & 63] = 0.f;
    __syncthreads();

    const float ab3v = ab3[0];

    for (int c = 0; c < 4; c++) {
        if (c < 3) {
            const int c0n = (c + 1) * CHUNK;
            float* dst = s.gb[(c + 1) % 3];
            #pragma unroll
            for (int h = 0; h < 4; h++) {
                const int idx = tid + h * 256;
                const int row = idx >> 4;
                const int c4  = (idx & 15) * 4;
                const int l = c0n + row;
                const int sid = (l < LSEQ) ? s.seqs[l] : 0;
                cp_async16(&dst[row * GLD + c4], histE + (long)sid * 64 + c4);
            }
            cp_commit();
            cp_wait<1>();
        } else {
            cp_wait<0>();
        }
        __syncthreads();

        const float* gbuf = s.gb[c % 3];

        {
            const int r   = warp & 3;
            const int cpp = warp >> 2;
            const int rowA = (r * 16 + qr) * GLD;
            float acc1[4][4];
            #pragma unroll
            for (int ni = 0; ni < 4; ni++) {
                const int n0 = cpp * 32 + ni * 8;
                acc1[ni][0] = s.base[n0 + 2 * qc];
                acc1[ni][1] = s.base[n0 + 2 * qc + 1];
                acc1[ni][2] = acc1[ni][0];
                acc1[ni][3] = acc1[ni][1];
            }
            #pragma unroll
            for (int ks = 0; ks < 8; ks++) {
                float a[4];
                const float* ap = &gbuf[rowA + ks * 8 + qc];
                a[0] = ap[0];
                a[1] = ap[8 * GLD];
                a[2] = ap[4];
                a[3] = ap[8 * GLD + 4];
                #pragma unroll
                for (int ni = 0; ni < 4; ni++) {
                    float bv[2];
                    const float* bp = &s.M[(ks * 8 + qc) * MLD + cpp * 32 + ni * 8 + qr];
                    bv[0] = bp[0];
                    bv[1] = bp[4 * MLD];
                    mma_tf32(acc1[ni], a, bv);
                }
            }
            #pragma unroll
            for (int ni = 0; ni < 4; ni++) {
                const int n0 = cpp * 32 + ni * 8;
                float2 v0 = make_float2(fmaxf(acc1[ni][0], 0.f), fmaxf(acc1[ni][1], 0.f));
                float2 v1 = make_float2(fmaxf(acc1[ni][2], 0.f), fmaxf(acc1[ni][3], 0.f));
                *reinterpret_cast<float2*>(&s.h1[(r * 16 + qr) * GLD + n0 + 2 * qc]) = v0;
                *reinterpret_cast<float2*>(&s.h1[(r * 16 + qr + 8) * GLD + n0 + 2 * qc]) = v1;
            }
        }
        __syncthreads();

        if (warp < 4) {
            float acc2[2][4];
            #pragma unroll
            for (int ni = 0; ni < 2; ni++) {
                acc2[ni][0] = s.ab2s[ni * 8 + 2 * qc];
                acc2[ni][1] = s.ab2s[ni * 8 + 2 * qc + 1];
                acc2[ni][2] = acc2[ni][0];
                acc2[ni][3] = acc2[ni][1];
            }
            const int rowA = (warp * 16 + qr) * GLD;
            #pragma unroll
            for (int ks = 0; ks < 8; ks++) {
                float a[4];
                const float* ap = &s.h1[rowA + ks * 8 + qc];
                a[0] = ap[0];
                a[1] = ap[8 * GLD];
                a[2] = ap[4];
                a[3] = ap[8 * GLD + 4];
                #pragma unroll
                for (int ni = 0; ni < 2; ni++) {
                    float bv[2];
                    const float* bp = &s.aW2s[(ks * 8 + qc) * WLD + ni * 8 + qr];
                    bv[0] = bp[0];
                    bv[1] = bp[4 * WLD];
                    mma_tf32(acc2[ni], a, bv);
                }
            }
            float w0 = 0.f, w1 = 0.f;
            #pragma unroll
            for (int ni = 0; ni < 2; ni++) {
                const float g0 = s.aW3s[ni * 8 + 2 * qc];
                const float g1 = s.aW3s[ni * 8 + 2 * qc + 1];
                w0 += fmaxf(acc2[ni][0], 0.f) * g0 + fmaxf(acc2[ni][1], 0.f) * g1;
                w1 += fmaxf(acc2[ni][2], 0.f) * g0 + fmaxf(acc2[ni][3], 0.f) * g1;
            }
            w0 += __shfl_xor_sync(0xffffffffu, w0, 1);
            w0 += __shfl_xor_sync(0xffffffffu, w0, 2);
            w1 += __shfl_xor_sync(0xffffffffu, w1, 1);
            w1 += __shfl_xor_sync(0xffffffffu, w1, 2);
            float e0 = 0.f, e1 = 0.f;
            if (qc == 0) {
                const int l0 = c * CHUNK + warp * 16 + qr;
                const int l1 = l0 + 8;
                if (l0 < LSEQ && s.seqs[l0] != 0) e0 = __expf(w0 + ab3v);
                if (l1 < LSEQ && s.seqs[l1] != 0) e1 = __expf(w1 + ab3v);
                s.sc[warp * 16 + qr]     = e0;
                s.sc[warp * 16 + qr + 8] = e1;
            }
            float tot = e0 + e1;
            #pragma unroll
            for (int off = 16; off >= 1; off >>= 1)
                tot += __shfl_xor_sync(0xffffffffu, tot, off);
            if (lane == 0) s.red[warp] = tot;
        }
        __syncthreads();

        if (tid == 0) s.denom += s.red[0] + s.red[1] + s.red[2] + s.red[3];

        {
            const int d = tid & 63, g = tid >> 6;
            float acc = s.part[g][d];
            #pragma unroll
            for (int i = 0; i < 16; i++) {
                const int l = g * 16 + i;
                acc += s.sc[l] * gbuf[l * GLD + d];
            }
            s.part[g][d] = acc;
        }
    }
    __syncthreads();

    if (tid < 64)
        s.poolred[tid] = (s.part[0][tid] + s.part[1][tid] + s.part[2][tid] + s.part[3][tid])
                       * (1.f / s.denom);
    __syncthreads();

    {
        float v = 0.f;
        if (tid < CONCAT) {
            if      (tid < 64)  v = userE[(long)uid[b] * 64 + tid];
            else if (tid < 128) v = s.ibuf[tid - 64];
            else if (tid < 144) v = catE[(long)cid[b] * 16 + (tid - 128)];
            else if (tid < 152) v = durE[(long)did[b] * 8 + (tid - 144)];
            else if (tid < 177) v = udense[(long)b * 25 + (tid - 152)];
            else if (tid < 180) v = idense[(long)b * 3 + (tid - 177)];
            else                v = s.poolred[tid - 180];
            Sout[(long)b * CONCAT + tid] = v;
        }
        Shout[(long)b * KPAD + tid] = __float2half(v);   // fp16 padded copy
    }
}

// ---------------------------------------------------------------------------
// Kernel 2: batched fp16 GEMM + bias + ReLU (mma.m16n8k16), 4-stage cp.async.
// A [M][KPAD] fp16 row-major, Bt [N][KPAD] fp16 (transposed weights).
// Block tile 128x128, BK=16 halves, 8 warps (2x4), warp tile 64x32.
// ---------------------------------------------------------------------------
#define TBM 128
#define TBN 128
#define TBK 16
#define NSTG 4
#define HL  24       // halves per smem row (16 + 8 pad; bank-stride 12)

#define HGEMM_SMEM ((NSTG * TBM * HL + NSTG * TBN * HL) * 2)

template <bool OUT_HALF>
__global__ void __launch_bounds__(256, 2)
hgemm_bias_relu(const __half* __restrict__ A, const __half* __restrict__ Bt,
                const float* __restrict__ bias, void* __restrict__ Cout,
                int M, int N,
                size_t sA, size_t sB, size_t sBias, size_t sC)
{
    extern __shared__ __half smemh[];
    __half* As = smemh;                        // NSTG * TBM * HL
    __half* Bs = smemh + NSTG * TBM * HL;      // NSTG * TBN * HL

    const int z = blockIdx.z;
    A += (size_t)z * sA; Bt += (size_t)z * sB;
    bias += (size_t)z * sBias;

    const int m0 = blockIdx.y * TBM;
    const int n0 = blockIdx.x * TBN;
    const int tid = threadIdx.x;
    const int lane = tid & 31;
    const int warp = tid >> 5;
    const int wr = warp >> 2;            // 0..1 -> 64 rows
    const int wc = warp & 3;             // 0..3 -> 32 cols
    const int qr = lane >> 2;
    const int qc = lane & 3;

    const int nk = KPAD / TBK;           // 16

    const int l_row = tid >> 1;          // 0..127
    const int l_hc  = (tid & 1) * 8;     // half offset 0/8

    auto load_stage = [&](int st, int k0) {
        __half* as = As + st * TBM * HL;
        __half* bs = Bs + st * TBN * HL;
        cp_async16(&as[l_row * HL + l_hc], A  + (size_t)(m0 + l_row) * KPAD + k0 + l_hc);
        cp_async16(&bs[l_row * HL + l_hc], Bt + (size_t)(n0 + l_row) * KPAD + k0 + l_hc);
    };

    float acc[4][4][4];
    #pragma unroll
    for (int i = 0; i < 4; i++)
        #pragma unroll
        for (int j = 0; j < 4; j++)
            #pragma unroll
            for (int e = 0; e < 4; e++) acc[i][j][e] = 0.f;

    #pragma unroll
    for (int s0 = 0; s0 < NSTG - 1; s0++) {
        load_stage(s0, s0 * TBK);
        cp_commit();
    }

    for (int kt = 0; kt < nk; kt++) {
        cp_wait<NSTG - 2>();
        __syncthreads();

        const int knext = kt + NSTG - 1;
        if (knext < nk) load_stage(knext % NSTG, knext * TBK);
        cp_commit();

        const __half* as = As + (kt % NSTG) * TBM * HL;
        const __half* bs = Bs + (kt % NSTG) * TBN * HL;

        unsigned a[4][4], bfr[4][2];
        #pragma unroll
        for (int mi = 0; mi < 4; mi++) {
            const int r = wr * 64 + mi * 16 + qr;
            a[mi][0] = *reinterpret_cast<const unsigned*>(as + r * HL + 2 * qc);
            a[mi][1] = *reinterpret_cast<const unsigned*>(as + (r + 8) * HL + 2 * qc);
            a[mi][2] = *reinterpret_cast<const unsigned*>(as + r * HL + 2 * qc + 8);
            a[mi][3] = *reinterpret_cast<const unsigned*>(as + (r + 8) * HL + 2 * qc + 8);
        }
        #pragma unroll
        for (int ni = 0; ni < 4; ni++) {
            const int n = wc * 32 + ni * 8 + qr;
            bfr[ni][0] = *reinterpret_cast<const unsigned*>(bs + n * HL + 2 * qc);
            bfr[ni][1] = *reinterpret_cast<const unsigned*>(bs + n * HL + 2 * qc + 8);
        }
        #pragma unroll
        for (int mi = 0; mi < 4; mi++)
            #pragma unroll
            for (int ni = 0; ni < 4; ni++)
                mma_f16(acc[mi][ni], a[mi], bfr[ni]);

        __syncthreads();
    }

    // epilogue: bias + relu
    #pragma unroll
    for (int mi = 0; mi < 4; mi++) {
        #pragma unroll
        for (int ni = 0; ni < 4; ni++) {
            const int gm = m0 + wr * 64 + mi * 16 + qr;
            const int gn = n0 + wc * 32 + ni * 8 + qc * 2;
            const float b0 = bias[gn], b1 = bias[gn + 1];
            const float v0 = fmaxf(acc[mi][ni][0] + b0, 0.f);
            const float v1 = fmaxf(acc[mi][ni][1] + b1, 0.f);
            const float v2 = fmaxf(acc[mi][ni][2] + b0, 0.f);
            const float v3 = fmaxf(acc[mi][ni][3] + b1, 0.f);
            if (OUT_HALF) {
                __half* C = (__half*)Cout + (size_t)z * sC;
                *reinterpret_cast<__half2*>(C + (size_t)gm * N + gn) =
                    __floats2half2_rn(v0, v1);
                *reinterpret_cast<__half2*>(C + (size_t)(gm + 8) * N + gn) =
                    __floats2half2_rn(v2, v3);
            } else {
                float* C = (float*)Cout + (size_t)z * sC;
                *reinterpret_cast<float2*>(C + (size_t)gm * N + gn) = make_float2(v0, v1);
                *reinterpret_cast<float2*>(C + (size_t)(gm + 8) * N + gn) = make_float2(v2, v3);
            }
        }
    }
}

// ---------------------------------------------------------------------------
// Kernel 3: gates (softmax) + expert mix + towers + sigmoid
// ---------------------------------------------------------------------------
__global__ void __launch_bounds__(256)
head_kernel(const float* __restrict__ S, const float* __restrict__ eo,
            const float* __restrict__ gW, const float* __restrict__ gb,
            const float* __restrict__ tW1, const float* __restrict__ tb1,
            const float* __restrict__ tW2, const float* __restrict__ tb2,
            const float* __restrict__ tW3, const float* __restrict__ tb3,
            float* __restrict__ out)
{
    __shared__ float Srow[4][CONCAT];
    __shared__ float gate[4][16];
    __shared__ float ti[4][NTASK][EOUT];
    __shared__ float x1[4][NTASK][64];
    __shared__ float x2[4][NTASK][32];

    const int g = threadIdx.x >> 6;
    const int lane = threadIdx.x & 63;
    const int b = blockIdx.x * 4 + g;

    for (int c = lane; c < CONCAT; c += 64) Srow[g][c] = S[(long)b * CONCAT + c];
    __syncthreads();

    {
        const int o = lane >> 2;
        const int q = lane & 3;
        const int t = o >> 3, e = o & 7;
        const int c0 = q * 61;
        float acc = 0.f;
        #pragma unroll 8
        for (int c = c0; c < c0 + 61; c++)
            acc += Srow[g][c] * __ldg(&gW[((long)t * CONCAT + c) * 8 + e]);
        acc += __shfl_xor_sync(0xffffffffu, acc, 1);
        acc += __shfl_xor_sync(0xffffffffu, acc, 2);
        if (q == 0) gate[g][o] = acc + gb[t * 8 + e];
    }
    __syncthreads();
    if (lane < 2) {
        const int t = lane;
        float mx = -3.4e38f;
        for (int e = 0; e < 8; e++) mx = fmaxf(mx, gate[g][t * 8 + e]);
        float sum = 0.f, ex[8];
        for (int e = 0; e < 8; e++) { ex[e] = __expf(gate[g][t * 8 + e] - mx); sum += ex[e]; }
        const float is = 1.f / sum;
        for (int e = 0; e < 8; e++) gate[g][t * 8 + e] = ex[e] * is;
    }
    __syncthreads();

    {
        const int t = lane >> 5;
        const int o = (lane & 31) * 4;
        float4 acc = make_float4(0.f, 0.f, 0.f, 0.f);
        #pragma unroll
        for (int e = 0; e < 8; e++) {
            const float gv = gate[g][t * 8 + e];
            const float4 v = *reinterpret_cast<const float4*>(
                eo + ((long)e * BATCH + b) * EOUT + o);
            acc.x += gv * v.x; acc.y += gv * v.y;
            acc.z += gv * v.z; acc.w += gv * v.w;
        }
        *reinterpret_cast<float4*>(&ti[g][t][o]) = acc;
    }
    __syncthreads();

    for (int idx = lane; idx < NTASK * 64; idx += 64) {
        const int t = idx >> 6, j = idx & 63;
        float acc = tb1[t * 64 + j];
        #pragma unroll 8
        for (int o = 0; o < 128; o++)
            acc += ti[g][t][o] * __ldg(&tW1[((long)t * 128 + o) * 64 + j]);
        x1[g][t][j] = fmaxf(acc, 0.f);
    }
    __syncthreads();

    {
        const int t = lane >> 5, m = lane & 31;
        float acc = tb2[t * 32 + m];
        #pragma unroll 8
        for (int j = 0; j < 64; j++)
            acc += x1[g][t][j] * __ldg(&tW2[(t * 64 + j) * 32 + m]);
        x2[g][t][m] = fmaxf(acc, 0.f);
    }
    __syncthreads();

    if (lane < 2) {
        const int t = lane;
        float acc = tb3[t];
        #pragma unroll
        for (int m = 0; m < 32; m++) acc += x2[g][t][m] * tW3[t * 32 + m];
        out[(long)t * BATCH + b] = 1.f / (1.f + __expf(-acc));
    }
}

// ---------------------------------------------------------------------------
// Launch
// ---------------------------------------------------------------------------
extern "C" void kernel_launch(void* const* d_in, const int* in_sizes, int n_in,
                              void* d_out, int out_size)
{
    const int*   uid    = (const int*)  d_in[0];
    const int*   iid    = (const int*)  d_in[1];
    const int*   cid    = (const int*)  d_in[2];
    const int*   did    = (const int*)  d_in[3];
    const float* udense = (const float*)d_in[4];
    const float* idense = (const float*)d_in[5];
    const int*   hseq   = (const int*)  d_in[6];
    const float* userE  = (const float*)d_in[7];
    const float* itemE  = (const float*)d_in[8];
    const float* catE   = (const float*)d_in[9];
    const float* durE   = (const float*)d_in[10];
    const float* histE  = (const float*)d_in[11];
    const float* Wproj  = (const float*)d_in[12];
    const float* aW1    = (const float*)d_in[13];
    const float* ab1    = (const float*)d_in[14];
    const float* aW2    = (const float*)d_in[15];
    const float* ab2    = (const float*)d_in[16];
    const float* aW3    = (const float*)d_in[17];
    const float* ab3    = (const float*)d_in[18];
    const float* eW1    = (const float*)d_in[19];
    const float* eb1    = (const float*)d_in[20];
    const float* eW2    = (const float*)d_in[21];
    const float* eb2    = (const float*)d_in[22];
    const float* gW     = (const float*)d_in[23];
    const float* gb     = (const float*)d_in[24];
    const float* tW1    = (const float*)d_in[25];
    const float* tb1    = (const float*)d_in[26];
    const float* tW2    = (const float*)d_in[27];
    const float* tb2    = (const float*)d_in[28];
    const float* tW3    = (const float*)d_in[29];
    const float* tb3    = (const float*)d_in[30];
    float* out = (float*)d_out;

    float  *pS, *pEo;
    __half *pSh, *pEh, *pW1t, *pW2t;
    cudaGetSymbolAddress((void**)&pS,   g_S);
    cudaGetSymbolAddress((void**)&pSh,  g_Sh);
    cudaGetSymbolAddress((void**)&pEh,  g_ehh);
    cudaGetSymbolAddress((void**)&pEo,  g_eo);
    cudaGetSymbolAddress((void**)&pW1t, g_W1t);
    cudaGetSymbolAddress((void**)&pW2t, g_W2t);

    const int attn_smem = (int)sizeof(AttnSmem);
    cudaFuncSetAttribute(attn_kernel, cudaFuncAttributeMaxDynamicSharedMemorySize, attn_smem);
    cudaFuncSetAttribute(hgemm_bias_relu<true>,  cudaFuncAttributeMaxDynamicSharedMemorySize, HGEMM_SMEM);
    cudaFuncSetAttribute(hgemm_bias_relu<false>, cudaFuncAttributeMaxDynamicSharedMemorySize, HGEMM_SMEM);

    // K0: weight prep (fp16 transpose, K padded to 256)
    prep_weights<<<(NEXP * EHID * KPAD + NEXP * EOUT * KPAD) / 256, 256>>>(
        eW1, eW2, pW1t, pW2t);

    // K1: attention + feature concat (fp32 S + fp16 padded S)
    attn_kernel<<<BATCH, 256, attn_smem>>>(
        uid, iid, cid, did, udense, idense, hseq,
        userE, itemE, catE, durE, histE, Wproj,
        aW1, ab1, aW2, ab2, aW3, ab3, pS, pSh);

    // K2a: eh = relu(S @ eW1 + eb1), fp16 in/out (A shared across experts)
    hgemm_bias_relu<true><<<dim3(EHID / TBN, BATCH / TBM, NEXP), 256, HGEMM_SMEM>>>(
        pSh, pW1t, eb1, pEh,
        BATCH, EHID,
        (size_t)0, (size_t)EHID * KPAD, (size_t)EHID, (size_t)BATCH * EHID);

    // K2b: eo = relu(eh @ eW2 + eb2), fp16 in, fp32 out
    hgemm_bias_relu<false><<<dim3(EOUT / TBN, BATCH / TBM, NEXP), 256, HGEMM_SMEM>>>(
        pEh, pW2t, eb2, pEo,
        BATCH, EOUT,
        (size_t)BATCH * EHID, (size_t)EOUT * KPAD, (size_t)EOUT, (size_t)BATCH * EOUT);

    // K3: gates + mix + towers + sigmoid
    head_kernel<<<BATCH / 4, 256>>>(
        pS, pEo, gW, gb, tW1, tb1, tW2, tb2, tW3, tb3, out);
}

// round 11
// speedup vs baseline: 1.4563x; 1.4560x over previous
#include <cuda_runtime.h>
#include <cuda_fp16.h>
#include <math.h>

// ---------------------------------------------------------------------------
// Problem constants
// ---------------------------------------------------------------------------
#define BATCH   16384
#define LSEQ    200
#define CONCAT  244
#define KPAD    256
#define NEXP    8
#define EHID    256
#define EOUT    128
#define NTASK   2
#define CH      32       // positions per chunk
#define NCH     7        // 7*32 = 224 >= 200
#define SEQPAD  224
#define LLD     68       // landing buffer leading dim (fp32)
#define AL      136      // A / Bt1 leading dim (halves)
#define HL1     72       // h1 / aW2t leading dim (halves)

// ---------------------------------------------------------------------------
// Scratch (static device globals — no allocation allowed)
// ---------------------------------------------------------------------------
__device__ float  g_S   [(long)BATCH * CONCAT];
__device__ __half g_Sh  [(long)BATCH * KPAD];
__device__ __half g_ehh [(long)NEXP * BATCH * EHID];
__device__ float  g_eo  [(long)NEXP * BATCH * EOUT];
__device__ __half g_W1t [(long)NEXP * EHID * KPAD];
__device__ __half g_W2t [(long)NEXP * EOUT * KPAD];
__device__ __half g_t16 [(long)BATCH * 64];       // per-row target proj (fp16)
__device__ float  g_base[(long)BATCH * 64];       // per-row layer1 bias row
__device__ __half g_Bt1 [64 * 128];               // [n][k] : P | W3 transposed
__device__ __half g_aW2t[16 * 64];                // [n][k]
__device__ float  g_Wb  [64 * 64];                // W0 + W2 (fp32)

// ---------------------------------------------------------------------------
// cp.async helpers
// ---------------------------------------------------------------------------
__device__ __forceinline__ void cp_async16(void* smem_dst, const void* gsrc) {
    unsigned sm = (unsigned)__cvta_generic_to_shared(smem_dst);
    asm volatile("cp.async.cg.shared.global [%0], [%1], 16;\n" :: "r"(sm), "l"(gsrc));
}
__device__ __forceinline__ void cp_commit() {
    asm volatile("cp.async.commit_group;\n");
}
template <int N>
__device__ __forceinline__ void cp_wait() {
    asm volatile("cp.async.wait_group %0;\n" :: "n"(N));
}

// fp16 mma m16n8k16, fp32 accum.  A row-major, B as Bt[n][k].
__device__ __forceinline__ void mma_f16(float* d, const unsigned* a, const unsigned* b) {
    asm volatile(
        "mma.sync.aligned.m16n8k16.row.col.f32.f16.f16.f32 "
        "{%0,%1,%2,%3}, {%4,%5,%6,%7}, {%8,%9}, {%0,%1,%2,%3};\n"
        : "+f"(d[0]), "+f"(d[1]), "+f"(d[2]), "+f"(d[3])
        : "r"(a[0]), "r"(a[1]), "r"(a[2]), "r"(a[3]),
          "r"(b[0]), "r"(b[1]));
}

// ---------------------------------------------------------------------------
// Kernel 0: weight prep (fp16 transposes + shared attention matrices)
// ---------------------------------------------------------------------------
#define N_W1T (NEXP * EHID * KPAD)
#define N_W2T (NEXP * EOUT * KPAD)
#define N_BT1 (64 * 128)
#define N_AW2 (16 * 64)
#define N_WB  (64 * 64)
#define N_PREP (N_W1T + N_W2T + N_BT1 + N_AW2 + N_WB)

__global__ void __launch_bounds__(256)
prep_weights(const float* __restrict__ eW1, const float* __restrict__ eW2,
             const float* __restrict__ aW1, const float* __restrict__ aW2,
             __half* __restrict__ W1t, __half* __restrict__ W2t,
             __half* __restrict__ Bt1, __half* __restrict__ aW2t,
             float* __restrict__ Wb)
{
    int i = blockIdx.x * 256 + threadIdx.x;
    if (i < N_W1T) {
        const int e = i >> 16, n = (i >> 8) & 255, k = i & 255;
        const float v = (k < CONCAT) ? eW1[((long)e * CONCAT + k) * EHID + n] : 0.f;
        W1t[i] = __float2half(v);
        return;
    }
    i -= N_W1T;
    if (i < N_W2T) {
        const int e = i >> 15, n = (i >> 8) & 127, k = i & 255;
        W2t[i] = __float2half(eW2[((long)e * EHID + k) * EOUT + n]);
        return;
    }
    i -= N_W2T;
    if (i < N_BT1) {
        const int n = i >> 7, k = i & 127;
        float v;
        if (k < 64) v = aW1[(64 + k) * 64 + n] - aW1[(128 + k) * 64 + n];
        else        v = aW1[(192 + (k - 64)) * 64 + n];
        Bt1[i] = __float2half(v);
        return;
    }
    i -= N_BT1;
    if (i < N_AW2) {
        const int n = i >> 6, k = i & 63;
        aW2t[i] = __float2half(aW2[k * 16 + n]);
        return;
    }
    i -= N_AW2;
    if (i < N_WB) {
        const int k = i >> 6, j = i & 63;
        Wb[i] = aW1[k * 64 + j] + aW1[(128 + k) * 64 + j];
    }
}

// ---------------------------------------------------------------------------
// Kernel 0b: per-row t = i_emb @ Wproj (fp16) and base = ab1 + t @ Wb
// 64 rows per block, 256 threads.
// ---------------------------------------------------------------------------
struct TBSmem {
    float Wp[64 * LLD];
    float Wbs[64 * LLD];
    float I[64 * LLD];
    float T[64 * LLD];
    int   ids[64];
};

__global__ void __launch_bounds__(256)
tbase_kernel(const int* __restrict__ iid, const float* __restrict__ itemE,
             const float* __restrict__ Wproj, const float* __restrict__ Wb,
             const float* __restrict__ ab1,
             __half* __restrict__ t16, float* __restrict__ base)
{
    extern __shared__ unsigned char smem_raw[];
    TBSmem& s = *reinterpret_cast<TBSmem*>(smem_raw);
    const int tid = threadIdx.x;
    const int b0 = blockIdx.x * 64;

    if (tid < 64) s.ids[tid] = iid[b0 + tid];
    // stage Wproj, Wb: 64 rows x 16 float4 each = 1024 transfers per array
    #pragma unroll
    for (int h = 0; h < 4; h++) {
        const int idx = tid + h * 256;
        const int k = idx >> 4, f = (idx & 15) * 4;
        cp_async16(&s.Wp[k * LLD + f],  Wproj + k * 64 + f);
        cp_async16(&s.Wbs[k * LLD + f], Wb    + k * 64 + f);
    }
    cp_commit();
    __syncthreads();
    // gather item embeddings: 64 rows x 16 float4
    #pragma unroll
    for (int h = 0; h < 4; h++) {
        const int idx = tid + h * 256;
        const int r = idx >> 4, f = (idx & 15) * 4;
        cp_async16(&s.I[r * LLD + f], itemE + (long)s.ids[r] * 64 + f);
    }
    cp_commit();
    cp_wait<0>();
    __syncthreads();

    const int r = tid >> 2;
    const int jg = (tid & 3) * 16;
    {   // T = I @ Wproj
        float acc[16];
        #pragma unroll
        for (int j = 0; j < 16; j++) acc[j] = 0.f;
        #pragma unroll 4
        for (int k = 0; k < 64; k++) {
            const float ik = s.I[r * LLD + k];
            #pragma unroll
            for (int j = 0; j < 16; j++) acc[j] += ik * s.Wp[k * LLD + jg + j];
        }
        #pragma unroll
        for (int j = 0; j < 16; j++) {
            s.T[r * LLD + jg + j] = acc[j];
            t16[(long)(b0 + r) * 64 + jg + j] = __float2half(acc[j]);
        }
    }
    __syncthreads();
    {   // base = ab1 + T @ Wb
        float acc[16];
        #pragma unroll
        for (int j = 0; j < 16; j++) acc[j] = ab1[jg + j];
        #pragma unroll 4
        for (int k = 0; k < 64; k++) {
            const float tk = s.T[r * LLD + k];
            #pragma unroll
            for (int j = 0; j < 16; j++) acc[j] += tk * s.Wbs[k * LLD + jg + j];
        }
        #pragma unroll
        for (int j = 0; j < 16; j++)
            base[(long)(b0 + r) * 64 + jg + j] = acc[j];
    }
}

// ---------------------------------------------------------------------------
// Kernel 1: DIN attention (fp16 mma, shared weights) + pooling + concat
// One block per batch row, 256 threads (8 warps), ~53 KB smem, 4 blocks/SM.
// ---------------------------------------------------------------------------
struct AttnSmem {
    float  land[2][CH * LLD];      // fp32 gather landing (2 x 8.7 KB)
    __half A[CH * AL];             // [h | t*h] fp16 (8.7 KB)
    __half h1[CH * HL1];           // layer1 out fp16 (4.6 KB)
    __half Bt1[64 * AL];           // shared B (17.4 KB)
    __half aW2t[16 * HL1];         // (2.3 KB)
    float  t32[64];
    float  base[64];
    float  part[4][64];
    float  sc[CH];
    float  aW3s[16];
    float  ab2s[16];
    float  poolred[64];
    float  red[4];
    float  denom;
    int    seqs[SEQPAD];
};

__global__ void __launch_bounds__(256, 4)
attn_kernel(const int* __restrict__ uid, const int* __restrict__ iid,
            const int* __restrict__ cid, const int* __restrict__ did,
            const float* __restrict__ udense, const float* __restrict__ idense,
            const int* __restrict__ hseq,
            const float* __restrict__ userE, const float* __restrict__ itemE,
            const float* __restrict__ catE,  const float* __restrict__ durE,
            const float* __restrict__ histE,
            const __half* __restrict__ t16, const float* __restrict__ baseg,
            const __half* __restrict__ Bt1g, const __half* __restrict__ aW2tg,
            const float* __restrict__ aW3, const float* __restrict__ ab3,
            const float* __restrict__ ab2,
            float* __restrict__ Sout, __half* __restrict__ Shout)
{
    extern __shared__ unsigned char smem_raw[];
    AttnSmem& s = *reinterpret_cast<AttnSmem*>(smem_raw);

    const int b    = blockIdx.x;
    const int tid  = threadIdx.x;
    const int lane = tid & 31;
    const int warp = tid >> 5;
    const int qr   = lane >> 2;
    const int qc   = lane & 3;

    // ---- stage shared weights via cp.async (group W) ----
    {
        #pragma unroll
        for (int h = 0; h < 4; h++) {
            const int idx = tid + h * 256;
            const int n = idx >> 4, hc = (idx & 15) * 8;
            cp_async16(&s.Bt1[n * AL + hc], Bt1g + n * 128 + hc);
        }
        if (tid < 128) {
            const int n = tid >> 3, hc = (tid & 7) * 8;
            cp_async16(&s.aW2t[n * HL1 + hc], aW2tg + n * 64 + hc);
        }
    }
    cp_commit();

    // ---- stage per-row constants + sequence ids ----
    if (tid < 64) {
        s.t32[tid]  = __half2float(t16[(long)b * 64 + tid]);
        s.base[tid] = baseg[(long)b * 64 + tid];
    }
    if (tid < 16) { s.aW3s[tid] = aW3[tid]; s.ab2s[tid] = ab2[tid]; }
    if (tid < SEQPAD) s.seqs[tid] = (tid < LSEQ) ? hseq[(long)b * LSEQ + tid] : 0;
    s.part[tid >> 6][tid & 63] = 0.f;
    if (tid == 0) s.denom = 0.f;
    __syncthreads();     // seqs visible before gathers

    // ---- issue gathers for chunks 0, 1 : 32 rows x 16 float4 = 512 each ----
    #pragma unroll
    for (int ch = 0; ch < 2; ch++) {
        #pragma unroll
        for (int h = 0; h < 2; h++) {
            const int idx = tid + h * 256;
            const int r = idx >> 4;             // 0..31
            const int f = (idx & 15) * 4;       // 0..60
            const int sid = s.seqs[ch * CH + r];
            cp_async16(&s.land[ch][r * LLD + f], histE + (long)sid * 64 + f);
        }
        cp_commit();
    }

    const float ab3v = ab3[0];

    // ---- chunk loop ----
    for (int c = 0; c < NCH; c++) {
        const int buf = c & 1;
        cp_wait<1>();
        __syncthreads();

        // convert: A[r][k<64] = h ; A[r][64+k] = h * t32[k]   (fp16)
        {
            const int r = tid >> 3;
            const int h0 = (tid & 7) * 16;
            #pragma unroll
            for (int u = 0; u < 8; u++) {
                const int k = h0 + u * 2;
                float v0, v1;
                if (k < 64) {
                    v0 = s.land[buf][r * LLD + k];
                    v1 = s.land[buf][r * LLD + k + 1];
                } else {
                    v0 = s.land[buf][r * LLD + k - 64] * s.t32[k - 64];
                    v1 = s.land[buf][r * LLD + k - 63] * s.t32[k - 63];
                }
                *reinterpret_cast<__half2*>(&s.A[r * AL + k]) = __floats2half2_rn(v0, v1);
            }
        }
        __syncthreads();

        // layer 1: h1(32x64) = relu(A(32x128) @ B(128x64) + base), 8 warps
        {
            const int wm = warp & 1;
            const int wn = warp >> 1;
            const int n0 = wn * 16;
            float acc[2][4];
            #pragma unroll
            for (int ni = 0; ni < 2; ni++) {
                const int n8 = n0 + ni * 8;
                acc[ni][0] = s.base[n8 + 2 * qc];
                acc[ni][1] = s.base[n8 + 2 * qc + 1];
                acc[ni][2] = acc[ni][0];
                acc[ni][3] = acc[ni][1];
            }
            const int r0 = wm * 16 + qr;
            #pragma unroll
            for (int ks = 0; ks < 8; ks++) {
                unsigned a[4];
                const __half* ap = &s.A[r0 * AL + ks * 16 + 2 * qc];
                a[0] = *reinterpret_cast<const unsigned*>(ap);
                a[1] = *reinterpret_cast<const unsigned*>(ap + 8 * AL);
                a[2] = *reinterpret_cast<const unsigned*>(ap + 8);
                a[3] = *reinterpret_cast<const unsigned*>(ap + 8 * AL + 8);
                #pragma unroll
                for (int ni = 0; ni < 2; ni++) {
                    unsigned bv[2];
                    const __half* bp = &s.Bt1[(n0 + ni * 8 + qr) * AL + ks * 16 + 2 * qc];
                    bv[0] = *reinterpret_cast<const unsigned*>(bp);
                    bv[1] = *reinterpret_cast<const unsigned*>(bp + 8);
                    mma_f16(acc[ni], a, bv);
                }
            }
            #pragma unroll
            for (int ni = 0; ni < 2; ni++) {
                const int n8 = n0 + ni * 8;
                *reinterpret_cast<__half2*>(&s.h1[r0 * HL1 + n8 + 2 * qc]) =
                    __floats2half2_rn(fmaxf(acc[ni][0], 0.f), fmaxf(acc[ni][1], 0.f));
                *reinterpret_cast<__half2*>(&s.h1[(r0 + 8) * HL1 + n8 + 2 * qc]) =
                    __floats2half2_rn(fmaxf(acc[ni][2], 0.f), fmaxf(acc[ni][3], 0.f));
            }
        }
        __syncthreads();

        // layer 2 (mma) + layer 3 (registers): warps 0,1
        if (warp < 2) {
            float acc2[2][4];
            #pragma unroll
            for (int ni = 0; ni < 2; ni++) {
                acc2[ni][0] = s.ab2s[ni * 8 + 2 * qc];
                acc2[ni][1] = s.ab2s[ni * 8 + 2 * qc + 1];
                acc2[ni][2] = acc2[ni][0];
                acc2[ni][3] = acc2[ni][1];
            }
            const int r0 = warp * 16 + qr;
            #pragma unroll
            for (int ks = 0; ks < 4; ks++) {
                unsigned a[4];
                const __half* ap = &s.h1[r0 * HL1 + ks * 16 + 2 * qc];
                a[0] = *reinterpret_cast<const unsigned*>(ap);
                a[1] = *reinterpret_cast<const unsigned*>(ap + 8 * HL1);
                a[2] = *reinterpret_cast<const unsigned*>(ap + 8);
                a[3] = *reinterpret_cast<const unsigned*>(ap + 8 * HL1 + 8);
                #pragma unroll
                for (int ni = 0; ni < 2; ni++) {
                    unsigned bv[2];
                    const __half* bp = &s.aW2t[(ni * 8 + qr) * HL1 + ks * 16 + 2 * qc];
                    bv[0] = *reinterpret_cast<const unsigned*>(bp);
                    bv[1] = *reinterpret_cast<const unsigned*>(bp + 8);
                    mma_f16(acc2[ni], a, bv);
                }
            }
            float w0 = 0.f, w1 = 0.f;
            #pragma unroll
            for (int ni = 0; ni < 2; ni++) {
                const float g0 = s.aW3s[ni * 8 + 2 * qc];
                const float g1 = s.aW3s[ni * 8 + 2 * qc + 1];
                w0 += fmaxf(acc2[ni][0], 0.f) * g0 + fmaxf(acc2[ni][1], 0.f) * g1;
                w1 += fmaxf(acc2[ni][2], 0.f) * g0 + fmaxf(acc2[ni][3], 0.f) * g1;
            }
            w0 += __shfl_xor_sync(0xffffffffu, w0, 1);
            w0 += __shfl_xor_sync(0xffffffffu, w0, 2);
            w1 += __shfl_xor_sync(0xffffffffu, w1, 1);
            w1 += __shfl_xor_sync(0xffffffffu, w1, 2);
            float e0 = 0.f, e1 = 0.f;
            if (qc == 0) {
                const int l0 = c * CH + warp * 16 + qr;
                const int l1 = l0 + 8;
                if (l0 < LSEQ && s.seqs[l0] != 0) e0 = __expf(w0 + ab3v);
                if (l1 < LSEQ && s.seqs[l1] != 0) e1 = __expf(w1 + ab3v);
                s.sc[warp * 16 + qr]     = e0;
                s.sc[warp * 16 + qr + 8] = e1;
            }
            float tot = e0 + e1;
            #pragma unroll
            for (int off = 16; off >= 1; off >>= 1)
                tot += __shfl_xor_sync(0xffffffffu, tot, off);
            if (lane == 0) s.red[warp] = tot;
        }
        __syncthreads();

        if (tid == 0) s.denom += s.red[0] + s.red[1];

        // pooling accumulation from fp32 landing buffer
        {
            const int d = tid & 63, g = tid >> 6;
            float acc = s.part[g][d];
            #pragma unroll
            for (int i = 0; i < 8; i++) {
                const int l = g * 8 + i;
                acc += s.sc[l] * s.land[buf][l * LLD + d];
            }
            s.part[g][d] = acc;
        }
        __syncthreads();

        // issue gather for chunk c+2 (into the buffer just consumed)
        if (c + 2 < NCH) {
            const int c0n = (c + 2) * CH;
            #pragma unroll
            for (int h = 0; h < 2; h++) {
                const int idx = tid + h * 256;
                const int r = idx >> 4;             // 0..31
                const int f = (idx & 15) * 4;       // 0..60
                const int sid = s.seqs[c0n + r];
                cp_async16(&s.land[buf][r * LLD + f], histE + (long)sid * 64 + f);
            }
        }
        cp_commit();
    }

    // ---- pooled = accum / denom ----
    if (tid < 64)
        s.poolred[tid] = (s.part[0][tid] + s.part[1][tid] + s.part[2][tid] + s.part[3][tid])
                       * (1.f / s.denom);
    __syncthreads();

    // ---- write feature row (fp32 + fp16 padded) ----
    {
        const int item = iid[b];
        float v = 0.f;
        if (tid < CONCAT) {
            if      (tid < 64)  v = userE[(long)uid[b] * 64 + tid];
            else if (tid < 128) v = itemE[(long)item * 64 + (tid - 64)];
            else if (tid < 144) v = catE[(long)cid[b] * 16 + (tid - 128)];
            else if (tid < 152) v = durE[(long)did[b] * 8 + (tid - 144)];
            else if (tid < 177) v = udense[(long)b * 25 + (tid - 152)];
            else if (tid < 180) v = idense[(long)b * 3 + (tid - 177)];
            else                v = s.poolred[tid - 180];
            Sout[(long)b * CONCAT + tid] = v;
        }
        Shout[(long)b * KPAD + tid] = __float2half(v);
    }
}

// ---------------------------------------------------------------------------
// Kernel 2: batched fp16 GEMM + bias + ReLU (unchanged from R9, passing)
// ---------------------------------------------------------------------------
#define TBM 128
#define TBN 128
#define TBK 16
#define NSTG 4
#define HLG 24

#define HGEMM_SMEM ((NSTG * TBM * HLG + NSTG * TBN * HLG) * 2)

template <bool OUT_HALF>
__global__ void __launch_bounds__(256, 2)
hgemm_bias_relu(const __half* __restrict__ A, const __half* __restrict__ Bt,
                const float* __restrict__ bias, void* __restrict__ Cout,
                int M, int N,
                size_t sA, size_t sB, size_t sBias, size_t sC)
{
    extern __shared__ __half smemh[];
    __half* As = smemh;
    __half* Bs = smemh + NSTG * TBM * HLG;

    const int z = blockIdx.z;
    A += (size_t)z * sA; Bt += (size_t)z * sB;
    bias += (size_t)z * sBias;

    const int m0 = blockIdx.y * TBM;
    const int n0 = blockIdx.x * TBN;
    const int tid = threadIdx.x;
    const int lane = tid & 31;
    const int warp = tid >> 5;
    const int wr = warp >> 2;
    const int wc = warp & 3;
    const int qr = lane >> 2;
    const int qc = lane & 3;

    const int nk = KPAD / TBK;

    const int l_row = tid >> 1;
    const int l_hc  = (tid & 1) * 8;

    auto load_stage = [&](int st, int k0) {
        __half* as = As + st * TBM * HLG;
        __half* bs = Bs + st * TBN * HLG;
        cp_async16(&as[l_row * HLG + l_hc], A  + (size_t)(m0 + l_row) * KPAD + k0 + l_hc);
        cp_async16(&bs[l_row * HLG + l_hc], Bt + (size_t)(n0 + l_row) * KPAD + k0 + l_hc);
    };

    float acc[4][4][4];
    #pragma unroll
    for (int i = 0; i < 4; i++)
        #pragma unroll
        for (int j = 0; j < 4; j++)
            #pragma unroll
            for (int e = 0; e < 4; e++) acc[i][j][e] = 0.f;

    #pragma unroll
    for (int s0 = 0; s0 < NSTG - 1; s0++) {
        load_stage(s0, s0 * TBK);
        cp_commit();
    }

    for (int kt = 0; kt < nk; kt++) {
        cp_wait<NSTG - 2>();
        __syncthreads();

        const int knext = kt + NSTG - 1;
        if (knext < nk) load_stage(knext % NSTG, knext * TBK);
        cp_commit();

        const __half* as = As + (kt % NSTG) * TBM * HLG;
        const __half* bs = Bs + (kt % NSTG) * TBN * HLG;

        unsigned a[4][4], bfr[4][2];
        #pragma unroll
        for (int mi = 0; mi < 4; mi++) {
            const int r = wr * 64 + mi * 16 + qr;
            a[mi][0] = *reinterpret_cast<const unsigned*>(as + r * HLG + 2 * qc);
            a[mi][1] = *reinterpret_cast<const unsigned*>(as + (r + 8) * HLG + 2 * qc);
            a[mi][2] = *reinterpret_cast<const unsigned*>(as + r * HLG + 2 * qc + 8);
            a[mi][3] = *reinterpret_cast<const unsigned*>(as + (r + 8) * HLG + 2 * qc + 8);
        }
        #pragma unroll
        for (int ni = 0; ni < 4; ni++) {
            const int n = wc * 32 + ni * 8 + qr;
            bfr[ni][0] = *reinterpret_cast<const unsigned*>(bs + n * HLG + 2 * qc);
            bfr[ni][1] = *reinterpret_cast<const unsigned*>(bs + n * HLG + 2 * qc + 8);
        }
        #pragma unroll
        for (int mi = 0; mi < 4; mi++)
            #pragma unroll
            for (int ni = 0; ni < 4; ni++)
                mma_f16(acc[mi][ni], a[mi], bfr[ni]);

        __syncthreads();
    }

    #pragma unroll
    for (int mi = 0; mi < 4; mi++) {
        #pragma unroll
        for (int ni = 0; ni < 4; ni++) {
            const int gm = m0 + wr * 64 + mi * 16 + qr;
            const int gn = n0 + wc * 32 + ni * 8 + qc * 2;
            const float b0 = bias[gn], b1 = bias[gn + 1];
            const float v0 = fmaxf(acc[mi][ni][0] + b0, 0.f);
            const float v1 = fmaxf(acc[mi][ni][1] + b1, 0.f);
            const float v2 = fmaxf(acc[mi][ni][2] + b0, 0.f);
            const float v3 = fmaxf(acc[mi][ni][3] + b1, 0.f);
            if (OUT_HALF) {
                __half* C = (__half*)Cout + (size_t)z * sC;
                *reinterpret_cast<__half2*>(C + (size_t)gm * N + gn) =
                    __floats2half2_rn(v0, v1);
                *reinterpret_cast<__half2*>(C + (size_t)(gm + 8) * N + gn) =
                    __floats2half2_rn(v2, v3);
            } else {
                float* C = (float*)Cout + (size_t)z * sC;
                *reinterpret_cast<float2*>(C + (size_t)gm * N + gn) = make_float2(v0, v1);
                *reinterpret_cast<float2*>(C + (size_t)(gm + 8) * N + gn) = make_float2(v2, v3);
            }
        }
    }
}

// ---------------------------------------------------------------------------
// Kernel 3: gates (softmax) + expert mix + towers + sigmoid (unchanged)
// ---------------------------------------------------------------------------
__global__ void __launch_bounds__(256)
head_kernel(const float* __restrict__ S, const float* __restrict__ eo,
            const float* __restrict__ gW, const float* __restrict__ gb,
            const float* __restrict__ tW1, const float* __restrict__ tb1,
            const float* __restrict__ tW2, const float* __restrict__ tb2,
            const float* __restrict__ tW3, const float* __restrict__ tb3,
            float* __restrict__ out)
{
    __shared__ float Srow[4][CONCAT];
    __shared__ float gate[4][16];
    __shared__ float ti[4][NTASK][EOUT];
    __shared__ float x1[4][NTASK][64];
    __shared__ float x2[4][NTASK][32];

    const int g = threadIdx.x >> 6;
    const int lane = threadIdx.x & 63;
    const int b = blockIdx.x * 4 + g;

    for (int c = lane; c < CONCAT; c += 64) Srow[g][c] = S[(long)b * CONCAT + c];
    __syncthreads();

    {
        const int o = lane >> 2;
        const int q = lane & 3;
        const int t = o >> 3, e = o & 7;
        const int c0 = q * 61;
        float acc = 0.f;
        #pragma unroll 8
        for (int c = c0; c < c0 + 61; c++)
            acc += Srow[g][c] * __ldg(&gW[((long)t * CONCAT + c) * 8 + e]);
        acc += __shfl_xor_sync(0xffffffffu, acc, 1);
        acc += __shfl_xor_sync(0xffffffffu, acc, 2);
        if (q == 0) gate[g][o] = acc + gb[t * 8 + e];
    }
    __syncthreads();
    if (lane < 2) {
        const int t = lane;
        float mx = -3.4e38f;
        for (int e = 0; e < 8; e++) mx = fmaxf(mx, gate[g][t * 8 + e]);
        float sum = 0.f, ex[8];
        for (int e = 0; e < 8; e++) { ex[e] = __expf(gate[g][t * 8 + e] - mx); sum += ex[e]; }
        const float is = 1.f / sum;
        for (int e = 0; e < 8; e++) gate[g][t * 8 + e] = ex[e] * is;
    }
    __syncthreads();

    {
        const int t = lane >> 5;
        const int o = (lane & 31) * 4;
        float4 acc = make_float4(0.f, 0.f, 0.f, 0.f);
        #pragma unroll
        for (int e = 0; e < 8; e++) {
            const float gv = gate[g][t * 8 + e];
            const float4 v = *reinterpret_cast<const float4*>(
                eo + ((long)e * BATCH + b) * EOUT + o);
            acc.x += gv * v.x; acc.y += gv * v.y;
            acc.z += gv * v.z; acc.w += gv * v.w;
        }
        *reinterpret_cast<float4*>(&ti[g][t][o]) = acc;
    }
    __syncthreads();

    for (int idx = lane; idx < NTASK * 64; idx += 64) {
        const int t = idx >> 6, j = idx & 63;
        float acc = tb1[t * 64 + j];
        #pragma unroll 8
        for (int o = 0; o < 128; o++)
            acc += ti[g][t][o] * __ldg(&tW1[((long)t * 128 + o) * 64 + j]);
        x1[g][t][j] = fmaxf(acc, 0.f);
    }
    __syncthreads();

    {
        const int t = lane >> 5, m = lane & 31;
        float acc = tb2[t * 32 + m];
        #pragma unroll 8
        for (int j = 0; j < 64; j++)
            acc += x1[g][t][j] * __ldg(&tW2[(t * 64 + j) * 32 + m]);
        x2[g][t][m] = fmaxf(acc, 0.f);
    }
    __syncthreads();

    if (lane < 2) {
        const int t = lane;
        float acc = tb3[t];
        #pragma unroll
        for (int m = 0; m < 32; m++) acc += x2[g][t][m] * tW3[t * 32 + m];
        out[(long)t * BATCH + b] = 1.f / (1.f + __expf(-acc));
    }
}

// ---------------------------------------------------------------------------
// Launch
// ---------------------------------------------------------------------------
extern "C" void kernel_launch(void* const* d_in, const int* in_sizes, int n_in,
                              void* d_out, int out_size)
{
    const int*   uid    = (const int*)  d_in[0];
    const int*   iid    = (const int*)  d_in[1];
    const int*   cid    = (const int*)  d_in[2];
    const int*   did    = (const int*)  d_in[3];
    const float* udense = (const float*)d_in[4];
    const float* idense = (const float*)d_in[5];
    const int*   hseq   = (const int*)  d_in[6];
    const float* userE  = (const float*)d_in[7];
    const float* itemE  = (const float*)d_in[8];
    const float* catE   = (const float*)d_in[9];
    const float* durE   = (const float*)d_in[10];
    const float* histE  = (const float*)d_in[11];
    const float* Wproj  = (const float*)d_in[12];
    const float* aW1    = (const float*)d_in[13];
    const float* ab1    = (const float*)d_in[14];
    const float* aW2    = (const float*)d_in[15];
    const float* ab2    = (const float*)d_in[16];
    const float* aW3    = (const float*)d_in[17];
    const float* ab3    = (const float*)d_in[18];
    const float* eW1    = (const float*)d_in[19];
    const float* eb1    = (const float*)d_in[20];
    const float* eW2    = (const float*)d_in[21];
    const float* eb2    = (const float*)d_in[22];
    const float* gW     = (const float*)d_in[23];
    const float* gb     = (const float*)d_in[24];
    const float* tW1    = (const float*)d_in[25];
    const float* tb1    = (const float*)d_in[26];
    const float* tW2    = (const float*)d_in[27];
    const float* tb2    = (const float*)d_in[28];
    const float* tW3    = (const float*)d_in[29];
    const float* tb3    = (const float*)d_in[30];
    float* out = (float*)d_out;

    float  *pS, *pEo, *pBase, *pWb;
    __half *pSh, *pEh, *pW1t, *pW2t, *pT16, *pBt1, *pAW2t;
    cudaGetSymbolAddress((void**)&pS,    g_S);
    cudaGetSymbolAddress((void**)&pSh,   g_Sh);
    cudaGetSymbolAddress((void**)&pEh,   g_ehh);
    cudaGetSymbolAddress((void**)&pEo,   g_eo);
    cudaGetSymbolAddress((void**)&pW1t,  g_W1t);
    cudaGetSymbolAddress((void**)&pW2t,  g_W2t);
    cudaGetSymbolAddress((void**)&pT16,  g_t16);
    cudaGetSymbolAddress((void**)&pBase, g_base);
    cudaGetSymbolAddress((void**)&pBt1,  g_Bt1);
    cudaGetSymbolAddress((void**)&pAW2t, g_aW2t);
    cudaGetSymbolAddress((void**)&pWb,   g_Wb);

    const int attn_smem = (int)sizeof(AttnSmem);
    const int tb_smem   = (int)sizeof(TBSmem);
    cudaFuncSetAttribute(attn_kernel,  cudaFuncAttributeMaxDynamicSharedMemorySize, attn_smem);
    cudaFuncSetAttribute(tbase_kernel, cudaFuncAttributeMaxDynamicSharedMemorySize, tb_smem);
    cudaFuncSetAttribute(hgemm_bias_relu<true>,  cudaFuncAttributeMaxDynamicSharedMemorySize, HGEMM_SMEM);
    cudaFuncSetAttribute(hgemm_bias_relu<false>, cudaFuncAttributeMaxDynamicSharedMemorySize, HGEMM_SMEM);

    // K0: weight prep
    prep_weights<<<(N_PREP + 255) / 256, 256>>>(
        eW1, eW2, aW1, aW2, pW1t, pW2t, pBt1, pAW2t, pWb);

    // K0b: per-row t/base
    tbase_kernel<<<BATCH / 64, 256, tb_smem>>>(
        iid, itemE, Wproj, pWb, ab1, pT16, pBase);

    // K1: attention + feature concat
    attn_kernel<<<BATCH, 256, attn_smem>>>(
        uid, iid, cid, did, udense, idense, hseq,
        userE, itemE, catE, durE, histE,
        pT16, pBase, pBt1, pAW2t, aW3, ab3, ab2, pS, pSh);

    // K2a: eh = relu(S @ eW1 + eb1)
    hgemm_bias_relu<true><<<dim3(EHID / TBN, BATCH / TBM, NEXP), 256, HGEMM_SMEM>>>(
        pSh, pW1t, eb1, pEh,
        BATCH, EHID,
        (size_t)0, (size_t)EHID * KPAD, (size_t)EHID, (size_t)BATCH * EHID);

    // K2b: eo = relu(eh @ eW2 + eb2)
    hgemm_bias_relu<false><<<dim3(EOUT / TBN, BATCH / TBM, NEXP), 256, HGEMM_SMEM>>>(
        pEh, pW2t, eb2, pEo,
        BATCH, EOUT,
        (size_t)BATCH * EHID, (size_t)EOUT * KPAD, (size_t)EOUT, (size_t)BATCH * EOUT);

    // K3: gates + mix + towers + sigmoid
    head_kernel<<<BATCH / 4, 256>>>(
        pS, pEo, gW, gb, tW1, tb1, tW2, tb2, tW3, tb3, out);
}

// round 12
// speedup vs baseline: 2.3036x; 1.5819x over previous
#include <cuda_runtime.h>
#include <cuda_fp16.h>
#include <math.h>

// ---------------------------------------------------------------------------
// Problem constants
// ---------------------------------------------------------------------------
#define BATCH   16384
#define LSEQ    200
#define CONCAT  244
#define KPAD    256
#define NEXP    8
#define EHID    256
#define EOUT    128
#define NTASK   2
#define NITEMS1 100001   // N_ITEMS + 1 (hist embedding rows)
#define CH      32
#define NCH     7        // 7*32 = 224
#define SEQPAD  224
#define HLD2    72       // halves per row: h / h1 / Pt / W3t / aW2t
#define LLD     68       // fp32 leading dim (tbase kernel)

// ---------------------------------------------------------------------------
// Scratch (static device globals — no allocation allowed)
// ---------------------------------------------------------------------------
__device__ float  g_S   [(long)BATCH * CONCAT];
__device__ __half g_Sh  [(long)BATCH * KPAD];
__device__ __half g_ehh [(long)NEXP * BATCH * EHID];
__device__ float  g_eo  [(long)NEXP * BATCH * EOUT];
__device__ __half g_W1t [(long)NEXP * EHID * KPAD];
__device__ __half g_W2t [(long)NEXP * EOUT * KPAD];
__device__ __half g_t16 [(long)BATCH * 64];
__device__ float  g_base[(long)BATCH * 64];
__device__ __half g_hist16[(long)NITEMS1 * 64];   // fp16 history embeddings
__device__ __half g_Pt  [64 * 64];                // [n][k]: aW1[64+k]-aW1[128+k]
__device__ __half g_W3t [64 * 64];                // [n][k]: aW1[192+k]
__device__ __half g_aW2t[16 * 64];                // [n][k]
__device__ float  g_Wb  [64 * 64];                // W0 + W2 (fp32)

// ---------------------------------------------------------------------------
// cp.async helpers
// ---------------------------------------------------------------------------
__device__ __forceinline__ void cp_async16(void* smem_dst, const void* gsrc) {
    unsigned sm = (unsigned)__cvta_generic_to_shared(smem_dst);
    asm volatile("cp.async.cg.shared.global [%0], [%1], 16;\n" :: "r"(sm), "l"(gsrc));
}
__device__ __forceinline__ void cp_commit() {
    asm volatile("cp.async.commit_group;\n");
}
template <int N>
__device__ __forceinline__ void cp_wait() {
    asm volatile("cp.async.wait_group %0;\n" :: "n"(N));
}
__device__ __forceinline__ void cp_wait_n(int n) {
    switch (n) {
        case 0: cp_wait<0>(); break;
        case 1: cp_wait<1>(); break;
        case 2: cp_wait<2>(); break;
        case 3: cp_wait<3>(); break;
        case 4: cp_wait<4>(); break;
        case 5: cp_wait<5>(); break;
        default: cp_wait<6>(); break;
    }
}

// fp16 mma m16n8k16, fp32 accum.  A row-major, B as Bt[n][k].
__device__ __forceinline__ void mma_f16(float* d, const unsigned* a, const unsigned* b) {
    asm volatile(
        "mma.sync.aligned.m16n8k16.row.col.f32.f16.f16.f32 "
        "{%0,%1,%2,%3}, {%4,%5,%6,%7}, {%8,%9}, {%0,%1,%2,%3};\n"
        : "+f"(d[0]), "+f"(d[1]), "+f"(d[2]), "+f"(d[3])
        : "r"(a[0]), "r"(a[1]), "r"(a[2]), "r"(a[3]),
          "r"(b[0]), "r"(b[1]));
}

// ---------------------------------------------------------------------------
// Kernel 0: weight prep
// ---------------------------------------------------------------------------
#define N_W1T (NEXP * EHID * KPAD)
#define N_W2T (NEXP * EOUT * KPAD)
#define N_PT  (64 * 64)
#define N_W3  (64 * 64)
#define N_AW2 (16 * 64)
#define N_WB  (64 * 64)
#define N_PREP (N_W1T + N_W2T + N_PT + N_W3 + N_AW2 + N_WB)

__global__ void __launch_bounds__(256)
prep_weights(const float* __restrict__ eW1, const float* __restrict__ eW2,
             const float* __restrict__ aW1, const float* __restrict__ aW2,
             __half* __restrict__ W1t, __half* __restrict__ W2t,
             __half* __restrict__ Pt, __half* __restrict__ W3t,
             __half* __restrict__ aW2t, float* __restrict__ Wb)
{
    int i = blockIdx.x * 256 + threadIdx.x;
    if (i < N_W1T) {
        const int e = i >> 16, n = (i >> 8) & 255, k = i & 255;
        const float v = (k < CONCAT) ? eW1[((long)e * CONCAT + k) * EHID + n] : 0.f;
        W1t[i] = __float2half(v);
        return;
    }
    i -= N_W1T;
    if (i < N_W2T) {
        const int e = i >> 15, n = (i >> 8) & 127, k = i & 255;
        W2t[i] = __float2half(eW2[((long)e * EHID + k) * EOUT + n]);
        return;
    }
    i -= N_W2T;
    if (i < N_PT) {
        const int n = i >> 6, k = i & 63;
        Pt[i] = __float2half(aW1[(64 + k) * 64 + n] - aW1[(128 + k) * 64 + n]);
        return;
    }
    i -= N_PT;
    if (i < N_W3) {
        const int n = i >> 6, k = i & 63;
        W3t[i] = __float2half(aW1[(192 + k) * 64 + n]);
        return;
    }
    i -= N_W3;
    if (i < N_AW2) {
        const int n = i >> 6, k = i & 63;
        aW2t[i] = __float2half(aW2[k * 16 + n]);
        return;
    }
    i -= N_AW2;
    if (i < N_WB) {
        const int k = i >> 6, j = i & 63;
        Wb[i] = aW1[k * 64 + j] + aW1[(128 + k) * 64 + j];
    }
}

// ---------------------------------------------------------------------------
// Kernel 0c: convert histE to fp16 (one-time, 12.8 MB)
// ---------------------------------------------------------------------------
#define N_HIST2 ((long)NITEMS1 * 32)   // half2 count

__global__ void __launch_bounds__(256)
conv_hist(const float* __restrict__ histE, __half* __restrict__ h16)
{
    const long i = (long)blockIdx.x * 256 + threadIdx.x;
    if (i < N_HIST2) {
        const float2 v = reinterpret_cast<const float2*>(histE)[i];
        reinterpret_cast<__half2*>(h16)[i] = __floats2half2_rn(v.x, v.y);
    }
}

// ---------------------------------------------------------------------------
// Kernel 0b: per-row t = i_emb @ Wproj (fp16) and base = ab1 + t @ Wb
// ---------------------------------------------------------------------------
struct TBSmem {
    float Wp[64 * LLD];
    float Wbs[64 * LLD];
    float I[64 * LLD];
    float T[64 * LLD];
    int   ids[64];
};

__global__ void __launch_bounds__(256)
tbase_kernel(const int* __restrict__ iid, const float* __restrict__ itemE,
             const float* __restrict__ Wproj, const float* __restrict__ Wb,
             const float* __restrict__ ab1,
             __half* __restrict__ t16, float* __restrict__ base)
{
    extern __shared__ unsigned char smem_raw[];
    TBSmem& s = *reinterpret_cast<TBSmem*>(smem_raw);
    const int tid = threadIdx.x;
    const int b0 = blockIdx.x * 64;

    if (tid < 64) s.ids[tid] = iid[b0 + tid];
    #pragma unroll
    for (int h = 0; h < 4; h++) {
        const int idx = tid + h * 256;
        const int k = idx >> 4, f = (idx & 15) * 4;
        cp_async16(&s.Wp[k * LLD + f],  Wproj + k * 64 + f);
        cp_async16(&s.Wbs[k * LLD + f], Wb    + k * 64 + f);
    }
    cp_commit();
    __syncthreads();
    #pragma unroll
    for (int h = 0; h < 4; h++) {
        const int idx = tid + h * 256;
        const int r = idx >> 4, f = (idx & 15) * 4;
        cp_async16(&s.I[r * LLD + f], itemE + (long)s.ids[r] * 64 + f);
    }
    cp_commit();
    cp_wait<0>();
    __syncthreads();

    const int r = tid >> 2;
    const int jg = (tid & 3) * 16;
    {
        float acc[16];
        #pragma unroll
        for (int j = 0; j < 16; j++) acc[j] = 0.f;
        #pragma unroll 4
        for (int k = 0; k < 64; k++) {
            const float ik = s.I[r * LLD + k];
            #pragma unroll
            for (int j = 0; j < 16; j++) acc[j] += ik * s.Wp[k * LLD + jg + j];
        }
        #pragma unroll
        for (int j = 0; j < 16; j++) {
            s.T[r * LLD + jg + j] = acc[j];
            t16[(long)(b0 + r) * 64 + jg + j] = __float2half(acc[j]);
        }
    }
    __syncthreads();
    {
        float acc[16];
        #pragma unroll
        for (int j = 0; j < 16; j++) acc[j] = ab1[jg + j];
        #pragma unroll 4
        for (int k = 0; k < 64; k++) {
            const float tk = s.T[r * LLD + k];
            #pragma unroll
            for (int j = 0; j < 16; j++) acc[j] += tk * s.Wbs[k * LLD + jg + j];
        }
        #pragma unroll
        for (int j = 0; j < 16; j++)
            base[(long)(b0 + r) * 64 + jg + j] = acc[j];
    }
}

// ---------------------------------------------------------------------------
// Kernel 1: DIN attention — all gathers prefetched, fp16 end-to-end,
// u = t*h fragments computed in registers.  ~64 KB smem, 3 blocks/SM.
// ---------------------------------------------------------------------------
struct AttnSmem {
    __half h[SEQPAD * HLD2];       // resident history (32.3 KB)
    __half h1[2][CH * HLD2];       // layer1 out, double buffer (9.2 KB)
    __half Pt[64 * HLD2];          // (9.2 KB)
    __half W3t[64 * HLD2];         // (9.2 KB)
    __half aW2t[16 * HLD2];        // (2.3 KB)
    __half2 t2s[32];
    float base[64];
    float sc[SEQPAD];
    float part[4][64];
    float poolred[64];
    float aW3s[16];
    float ab2s[16];
    float red[8];
    float denom;
    int   seqs[SEQPAD];
};

__global__ void __launch_bounds__(256, 3)
attn_kernel(const int* __restrict__ uid, const int* __restrict__ iid,
            const int* __restrict__ cid, const int* __restrict__ did,
            const float* __restrict__ udense, const float* __restrict__ idense,
            const int* __restrict__ hseq,
            const float* __restrict__ userE, const float* __restrict__ itemE,
            const float* __restrict__ catE,  const float* __restrict__ durE,
            const __half* __restrict__ hist16,
            const __half* __restrict__ t16, const float* __restrict__ baseg,
            const __half* __restrict__ Ptg, const __half* __restrict__ W3tg,
            const __half* __restrict__ aW2tg,
            const float* __restrict__ aW3, const float* __restrict__ ab3,
            const float* __restrict__ ab2,
            float* __restrict__ Sout, __half* __restrict__ Shout)
{
    extern __shared__ unsigned char smem_raw[];
    AttnSmem& s = *reinterpret_cast<AttnSmem*>(smem_raw);

    const int b    = blockIdx.x;
    const int tid  = threadIdx.x;
    const int lane = tid & 31;
    const int warp = tid >> 5;
    const int qr   = lane >> 2;
    const int qc   = lane & 3;

    // ---- group 0: shared weights ----
    #pragma unroll
    for (int h = 0; h < 2; h++) {
        const int idx = tid + h * 256;            // 0..511
        const int n = idx >> 3, k8 = (idx & 7) * 8;
        cp_async16(&s.Pt[n * HLD2 + k8],  Ptg  + n * 64 + k8);
        cp_async16(&s.W3t[n * HLD2 + k8], W3tg + n * 64 + k8);
    }
    if (tid < 128) {
        const int n = tid >> 3, k8 = (tid & 7) * 8;
        cp_async16(&s.aW2t[n * HLD2 + k8], aW2tg + n * 64 + k8);
    }
    cp_commit();

    // ---- per-row constants + sequence ids ----
    if (tid < 32)
        s.t2s[tid] = reinterpret_cast<const __half2*>(t16 + (long)b * 64)[tid];
    if (tid < 64) s.base[tid] = baseg[(long)b * 64 + tid];
    if (tid < 16) { s.aW3s[tid] = aW3[tid]; s.ab2s[tid] = ab2[tid]; }
    if (tid < SEQPAD) s.seqs[tid] = (tid < LSEQ) ? hseq[(long)b * LSEQ + tid] : 0;
    s.part[tid >> 6][tid & 63] = 0.f;
    __syncthreads();    // seqs visible

    // ---- groups 1..7: all chunk gathers (fp16, 256 transfers each) ----
    #pragma unroll
    for (int ch = 0; ch < NCH; ch++) {
        const int r = tid >> 3;                   // 0..31
        const int f8 = (tid & 7) * 8;             // 0..56
        const int sid = s.seqs[ch * CH + r];
        cp_async16(&s.h[(ch * CH + r) * HLD2 + f8], hist16 + (long)sid * 64 + f8);
        cp_commit();
    }

    const float ab3v = ab3[0];

    // ---- chunk loop (unrolled so cp_wait_n folds to immediates) ----
    #pragma unroll
    for (int c = 0; c < NCH; c++) {
        cp_wait_n(NCH - 1 - c);
        __syncthreads();

        // layer 1: h1 = relu(h@P + (t*h)@W3 + base) ; 8 warps (2 row x 4 col)
        {
            const int wm = warp & 1;
            const int wn = warp >> 1;
            const int n0 = wn * 16;
            const int r0 = c * CH + wm * 16 + qr;
            float acc[2][4];
            #pragma unroll
            for (int ni = 0; ni < 2; ni++) {
                const int n8 = n0 + ni * 8;
                acc[ni][0] = s.base[n8 + 2 * qc];
                acc[ni][1] = s.base[n8 + 2 * qc + 1];
                acc[ni][2] = acc[ni][0];
                acc[ni][3] = acc[ni][1];
            }
            #pragma unroll
            for (int ks = 0; ks < 4; ks++) {
                unsigned a[4], ua[4];
                const __half* ap = &s.h[r0 * HLD2 + ks * 16 + 2 * qc];
                a[0] = *reinterpret_cast<const unsigned*>(ap);
                a[1] = *reinterpret_cast<const unsigned*>(ap + 8 * HLD2);
                a[2] = *reinterpret_cast<const unsigned*>(ap + 8);
                a[3] = *reinterpret_cast<const unsigned*>(ap + 8 * HLD2 + 8);
                const __half2 tlo = s.t2s[ks * 8 + qc];
                const __half2 thi = s.t2s[ks * 8 + qc + 4];
                __half2 u0 = __hmul2(*reinterpret_cast<const __half2*>(&a[0]), tlo);
                __half2 u1 = __hmul2(*reinterpret_cast<const __half2*>(&a[1]), tlo);
                __half2 u2 = __hmul2(*reinterpret_cast<const __half2*>(&a[2]), thi);
                __half2 u3 = __hmul2(*reinterpret_cast<const __half2*>(&a[3]), thi);
                ua[0] = *reinterpret_cast<const unsigned*>(&u0);
                ua[1] = *reinterpret_cast<const unsigned*>(&u1);
                ua[2] = *reinterpret_cast<const unsigned*>(&u2);
                ua[3] = *reinterpret_cast<const unsigned*>(&u3);
                #pragma unroll
                for (int ni = 0; ni < 2; ni++) {
                    const int n = n0 + ni * 8 + qr;
                    unsigned bv[2];
                    const __half* bp = &s.Pt[n * HLD2 + ks * 16 + 2 * qc];
                    bv[0] = *reinterpret_cast<const unsigned*>(bp);
                    bv[1] = *reinterpret_cast<const unsigned*>(bp + 8);
                    mma_f16(acc[ni], a, bv);
                    const __half* wp = &s.W3t[n * HLD2 + ks * 16 + 2 * qc];
                    bv[0] = *reinterpret_cast<const unsigned*>(wp);
                    bv[1] = *reinterpret_cast<const unsigned*>(wp + 8);
                    mma_f16(acc[ni], ua, bv);
                }
            }
            __half* h1b = s.h1[c & 1];
            const int rr = wm * 16 + qr;
            #pragma unroll
            for (int ni = 0; ni < 2; ni++) {
                const int n8 = n0 + ni * 8;
                *reinterpret_cast<__half2*>(&h1b[rr * HLD2 + n8 + 2 * qc]) =
                    __floats2half2_rn(fmaxf(acc[ni][0], 0.f), fmaxf(acc[ni][1], 0.f));
                *reinterpret_cast<__half2*>(&h1b[(rr + 8) * HLD2 + n8 + 2 * qc]) =
                    __floats2half2_rn(fmaxf(acc[ni][2], 0.f), fmaxf(acc[ni][3], 0.f));
            }
        }
        __syncthreads();

        // layer 2 (mma) + layer 3 (registers): warps 0,1
        if (warp < 2) {
            const __half* h1b = s.h1[c & 1];
            float acc2[2][4];
            #pragma unroll
            for (int ni = 0; ni < 2; ni++) {
                acc2[ni][0] = s.ab2s[ni * 8 + 2 * qc];
                acc2[ni][1] = s.ab2s[ni * 8 + 2 * qc + 1];
                acc2[ni][2] = acc2[ni][0];
                acc2[ni][3] = acc2[ni][1];
            }
            const int r0 = warp * 16 + qr;
            #pragma unroll
            for (int ks = 0; ks < 4; ks++) {
                unsigned a[4];
                const __half* ap = &h1b[r0 * HLD2 + ks * 16 + 2 * qc];
                a[0] = *reinterpret_cast<const unsigned*>(ap);
                a[1] = *reinterpret_cast<const unsigned*>(ap + 8 * HLD2);
                a[2] = *reinterpret_cast<const unsigned*>(ap + 8);
                a[3] = *reinterpret_cast<const unsigned*>(ap + 8 * HLD2 + 8);
                #pragma unroll
                for (int ni = 0; ni < 2; ni++) {
                    unsigned bv[2];
                    const __half* bp = &s.aW2t[(ni * 8 + qr) * HLD2 + ks * 16 + 2 * qc];
                    bv[0] = *reinterpret_cast<const unsigned*>(bp);
                    bv[1] = *reinterpret_cast<const unsigned*>(bp + 8);
                    mma_f16(acc2[ni], a, bv);
                }
            }
            float w0 = 0.f, w1 = 0.f;
            #pragma unroll
            for (int ni = 0; ni < 2; ni++) {
                const float g0 = s.aW3s[ni * 8 + 2 * qc];
                const float g1 = s.aW3s[ni * 8 + 2 * qc + 1];
                w0 += fmaxf(acc2[ni][0], 0.f) * g0 + fmaxf(acc2[ni][1], 0.f) * g1;
                w1 += fmaxf(acc2[ni][2], 0.f) * g0 + fmaxf(acc2[ni][3], 0.f) * g1;
            }
            w0 += __shfl_xor_sync(0xffffffffu, w0, 1);
            w0 += __shfl_xor_sync(0xffffffffu, w0, 2);
            w1 += __shfl_xor_sync(0xffffffffu, w1, 1);
            w1 += __shfl_xor_sync(0xffffffffu, w1, 2);
            if (qc == 0) {
                const int l0 = c * CH + warp * 16 + qr;
                const int l1 = l0 + 8;
                float e0 = 0.f, e1 = 0.f;
                if (l0 < LSEQ && s.seqs[l0] != 0) e0 = __expf(w0 + ab3v);
                if (l1 < LSEQ && s.seqs[l1] != 0) e1 = __expf(w1 + ab3v);
                s.sc[l0] = e0;
                s.sc[l1] = e1;
            }
        }
        // no trailing sync: next chunk's barrier orders h1 reuse (2-chunk gap)
    }
    __syncthreads();

    // ---- denom = sum sc ----
    {
        float sv = (tid < SEQPAD) ? s.sc[tid] : 0.f;
        #pragma unroll
        for (int off = 16; off >= 1; off >>= 1)
            sv += __shfl_xor_sync(0xffffffffu, sv, off);
        if (lane == 0) s.red[warp] = sv;
    }
    __syncthreads();
    if (tid == 0) {
        float ss = 0.f;
        #pragma unroll
        for (int w = 0; w < 8; w++) ss += s.red[w];
        s.denom = 1.f / ss;
    }

    // ---- pooling over resident h (fp16) ----
    {
        const int d = tid & 63, g = tid >> 6;
        float acc = 0.f;
        #pragma unroll 8
        for (int i = 0; i < 56; i++) {
            const int l = g * 56 + i;
            acc += s.sc[l] * __half2float(s.h[l * HLD2 + d]);
        }
        s.part[g][d] = acc;
    }
    __syncthreads();
    if (tid < 64)
        s.poolred[tid] = (s.part[0][tid] + s.part[1][tid] + s.part[2][tid] + s.part[3][tid])
                       * s.denom;
    __syncthreads();

    // ---- write feature row (fp32 + fp16 padded) ----
    {
        const int item = iid[b];
        float v = 0.f;
        if (tid < CONCAT) {
            if      (tid < 64)  v = userE[(long)uid[b] * 64 + tid];
            else if (tid < 128) v = itemE[(long)item * 64 + (tid - 64)];
            else if (tid < 144) v = catE[(long)cid[b] * 16 + (tid - 128)];
            else if (tid < 152) v = durE[(long)did[b] * 8 + (tid - 144)];
            else if (tid < 177) v = udense[(long)b * 25 + (tid - 152)];
            else if (tid < 180) v = idense[(long)b * 3 + (tid - 177)];
            else                v = s.poolred[tid - 180];
            Sout[(long)b * CONCAT + tid] = v;
        }
        Shout[(long)b * KPAD + tid] = __float2half(v);
    }
}

// ---------------------------------------------------------------------------
// Kernel 2: batched fp16 GEMM + bias + ReLU (unchanged, passing)
// ---------------------------------------------------------------------------
#define TBM 128
#define TBN 128
#define TBK 16
#define NSTG 4
#define HLG 24

#define HGEMM_SMEM ((NSTG * TBM * HLG + NSTG * TBN * HLG) * 2)

template <bool OUT_HALF>
__global__ void __launch_bounds__(256, 2)
hgemm_bias_relu(const __half* __restrict__ A, const __half* __restrict__ Bt,
                const float* __restrict__ bias, void* __restrict__ Cout,
                int M, int N,
                size_t sA, size_t sB, size_t sBias, size_t sC)
{
    extern __shared__ __half smemh[];
    __half* As = smemh;
    __half* Bs = smemh + NSTG * TBM * HLG;

    const int z = blockIdx.z;
    A += (size_t)z * sA; Bt += (size_t)z * sB;
    bias += (size_t)z * sBias;

    const int m0 = blockIdx.y * TBM;
    const int n0 = blockIdx.x * TBN;
    const int tid = threadIdx.x;
    const int lane = tid & 31;
    const int warp = tid >> 5;
    const int wr = warp >> 2;
    const int wc = warp & 3;
    const int qr = lane >> 2;
    const int qc = lane & 3;

    const int nk = KPAD / TBK;

    const int l_row = tid >> 1;
    const int l_hc  = (tid & 1) * 8;

    auto load_stage = [&](int st, int k0) {
        __half* as = As + st * TBM * HLG;
        __half* bs = Bs + st * TBN * HLG;
        cp_async16(&as[l_row * HLG + l_hc], A  + (size_t)(m0 + l_row) * KPAD + k0 + l_hc);
        cp_async16(&bs[l_row * HLG + l_hc], Bt + (size_t)(n0 + l_row) * KPAD + k0 + l_hc);
    };

    float acc[4][4][4];
    #pragma unroll
    for (int i = 0; i < 4; i++)
        #pragma unroll
        for (int j = 0; j < 4; j++)
            #pragma unroll
            for (int e = 0; e < 4; e++) acc[i][j][e] = 0.f;

    #pragma unroll
    for (int s0 = 0; s0 < NSTG - 1; s0++) {
        load_stage(s0, s0 * TBK);
        cp_commit();
    }

    for (int kt = 0; kt < nk; kt++) {
        cp_wait<NSTG - 2>();
        __syncthreads();

        const int knext = kt + NSTG - 1;
        if (knext < nk) load_stage(knext % NSTG, knext * TBK);
        cp_commit();

        const __half* as = As + (kt % NSTG) * TBM * HLG;
        const __half* bs = Bs + (kt % NSTG) * TBN * HLG;

        unsigned a[4][4], bfr[4][2];
        #pragma unroll
        for (int mi = 0; mi < 4; mi++) {
            const int r = wr * 64 + mi * 16 + qr;
            a[mi][0] = *reinterpret_cast<const unsigned*>(as + r * HLG + 2 * qc);
            a[mi][1] = *reinterpret_cast<const unsigned*>(as + (r + 8) * HLG + 2 * qc);
            a[mi][2] = *reinterpret_cast<const unsigned*>(as + r * HLG + 2 * qc + 8);
            a[mi][3] = *reinterpret_cast<const unsigned*>(as + (r + 8) * HLG + 2 * qc + 8);
        }
        #pragma unroll
        for (int ni = 0; ni < 4; ni++) {
            const int n = wc * 32 + ni * 8 + qr;
            bfr[ni][0] = *reinterpret_cast<const unsigned*>(bs + n * HLG + 2 * qc);
            bfr[ni][1] = *reinterpret_cast<const unsigned*>(bs + n * HLG + 2 * qc + 8);
        }
        #pragma unroll
        for (int mi = 0; mi < 4; mi++)
            #pragma unroll
            for (int ni = 0; ni < 4; ni++)
                mma_f16(acc[mi][ni], a[mi], bfr[ni]);

        __syncthreads();
    }

    #pragma unroll
    for (int mi = 0; mi < 4; mi++) {
        #pragma unroll
        for (int ni = 0; ni < 4; ni++) {
            const int gm = m0 + wr * 64 + mi * 16 + qr;
            const int gn = n0 + wc * 32 + ni * 8 + qc * 2;
            const float b0 = bias[gn], b1 = bias[gn + 1];
            const float v0 = fmaxf(acc[mi][ni][0] + b0, 0.f);
            const float v1 = fmaxf(acc[mi][ni][1] + b1, 0.f);
            const float v2 = fmaxf(acc[mi][ni][2] + b0, 0.f);
            const float v3 = fmaxf(acc[mi][ni][3] + b1, 0.f);
            if (OUT_HALF) {
                __half* C = (__half*)Cout + (size_t)z * sC;
                *reinterpret_cast<__half2*>(C + (size_t)gm * N + gn) =
                    __floats2half2_rn(v0, v1);
                *reinterpret_cast<__half2*>(C + (size_t)(gm + 8) * N + gn) =
                    __floats2half2_rn(v2, v3);
            } else {
                float* C = (float*)Cout + (size_t)z * sC;
                *reinterpret_cast<float2*>(C + (size_t)gm * N + gn) = make_float2(v0, v1);
                *reinterpret_cast<float2*>(C + (size_t)(gm + 8) * N + gn) = make_float2(v2, v3);
            }
        }
    }
}

// ---------------------------------------------------------------------------
// Kernel 3: gates (softmax) + expert mix + towers + sigmoid (unchanged)
// ---------------------------------------------------------------------------
__global__ void __launch_bounds__(256)
head_kernel(const float* __restrict__ S, const float* __restrict__ eo,
            const float* __restrict__ gW, const float* __restrict__ gb,
            const float* __restrict__ tW1, const float* __restrict__ tb1,
            const float* __restrict__ tW2, const float* __restrict__ tb2,
            const float* __restrict__ tW3, const float* __restrict__ tb3,
            float* __restrict__ out)
{
    __shared__ float Srow[4][CONCAT];
    __shared__ float gate[4][16];
    __shared__ float ti[4][NTASK][EOUT];
    __shared__ float x1[4][NTASK][64];
    __shared__ float x2[4][NTASK][32];

    const int g = threadIdx.x >> 6;
    const int lane = threadIdx.x & 63;
    const int b = blockIdx.x * 4 + g;

    for (int c = lane; c < CONCAT; c += 64) Srow[g][c] = S[(long)b * CONCAT + c];
    __syncthreads();

    {
        const int o = lane >> 2;
        const int q = lane & 3;
        const int t = o >> 3, e = o & 7;
        const int c0 = q * 61;
        float acc = 0.f;
        #pragma unroll 8
        for (int c = c0; c < c0 + 61; c++)
            acc += Srow[g][c] * __ldg(&gW[((long)t * CONCAT + c) * 8 + e]);
        acc += __shfl_xor_sync(0xffffffffu, acc, 1);
        acc += __shfl_xor_sync(0xffffffffu, acc, 2);
        if (q == 0) gate[g][o] = acc + gb[t * 8 + e];
    }
    __syncthreads();
    if (lane < 2) {
        const int t = lane;
        float mx = -3.4e38f;
        for (int e = 0; e < 8; e++) mx = fmaxf(mx, gate[g][t * 8 + e]);
        float sum = 0.f, ex[8];
        for (int e = 0; e < 8; e++) { ex[e] = __expf(gate[g][t * 8 + e] - mx); sum += ex[e]; }
        const float is = 1.f / sum;
        for (int e = 0; e < 8; e++) gate[g][t * 8 + e] = ex[e] * is;
    }
    __syncthreads();

    {
        const int t = lane >> 5;
        const int o = (lane & 31) * 4;
        float4 acc = make_float4(0.f, 0.f, 0.f, 0.f);
        #pragma unroll
        for (int e = 0; e < 8; e++) {
            const float gv = gate[g][t * 8 + e];
            const float4 v = *reinterpret_cast<const float4*>(
                eo + ((long)e * BATCH + b) * EOUT + o);
            acc.x += gv * v.x; acc.y += gv * v.y;
            acc.z += gv * v.z; acc.w += gv * v.w;
        }
        *reinterpret_cast<float4*>(&ti[g][t][o]) = acc;
    }
    __syncthreads();

    for (int idx = lane; idx < NTASK * 64; idx += 64) {
        const int t = idx >> 6, j = idx & 63;
        float acc = tb1[t * 64 + j];
        #pragma unroll 8
        for (int o = 0; o < 128; o++)
            acc += ti[g][t][o] * __ldg(&tW1[((long)t * 128 + o) * 64 + j]);
        x1[g][t][j] = fmaxf(acc, 0.f);
    }
    __syncthreads();

    {
        const int t = lane >> 5, m = lane & 31;
        float acc = tb2[t * 32 + m];
        #pragma unroll 8
        for (int j = 0; j < 64; j++)
            acc += x1[g][t][j] * __ldg(&tW2[(t * 64 + j) * 32 + m]);
        x2[g][t][m] = fmaxf(acc, 0.f);
    }
    __syncthreads();

    if (lane < 2) {
        const int t = lane;
        float acc = tb3[t];
        #pragma unroll
        for (int m = 0; m < 32; m++) acc += x2[g][t][m] * tW3[t * 32 + m];
        out[(long)t * BATCH + b] = 1.f / (1.f + __expf(-acc));
    }
}

// ---------------------------------------------------------------------------
// Launch
// ---------------------------------------------------------------------------
extern "C" void kernel_launch(void* const* d_in, const int* in_sizes, int n_in,
                              void* d_out, int out_size)
{
    const int*   uid    = (const int*)  d_in[0];
    const int*   iid    = (const int*)  d_in[1];
    const int*   cid    = (const int*)  d_in[2];
    const int*   did    = (const int*)  d_in[3];
    const float* udense = (const float*)d_in[4];
    const float* idense = (const float*)d_in[5];
    const int*   hseq   = (const int*)  d_in[6];
    const float* userE  = (const float*)d_in[7];
    const float* itemE  = (const float*)d_in[8];
    const float* catE   = (const float*)d_in[9];
    const float* durE   = (const float*)d_in[10];
    const float* histE  = (const float*)d_in[11];
    const float* Wproj  = (const float*)d_in[12];
    const float* aW1    = (const float*)d_in[13];
    const float* ab1    = (const float*)d_in[14];
    const float* aW2    = (const float*)d_in[15];
    const float* ab2    = (const float*)d_in[16];
    const float* aW3    = (const float*)d_in[17];
    const float* ab3    = (const float*)d_in[18];
    const float* eW1    = (const float*)d_in[19];
    const float* eb1    = (const float*)d_in[20];
    const float* eW2    = (const float*)d_in[21];
    const float* eb2    = (const float*)d_in[22];
    const float* gW     = (const float*)d_in[23];
    const float* gb     = (const float*)d_in[24];
    const float* tW1    = (const float*)d_in[25];
    const float* tb1    = (const float*)d_in[26];
    const float* tW2    = (const float*)d_in[27];
    const float* tb2    = (const float*)d_in[28];
    const float* tW3    = (const float*)d_in[29];
    const float* tb3    = (const float*)d_in[30];
    float* out = (float*)d_out;

    float  *pS, *pEo, *pBase, *pWb;
    __half *pSh, *pEh, *pW1t, *pW2t, *pT16, *pPt, *pW3t, *pAW2t, *pH16;
    cudaGetSymbolAddress((void**)&pS,    g_S);
    cudaGetSymbolAddress((void**)&pSh,   g_Sh);
    cudaGetSymbolAddress((void**)&pEh,   g_ehh);
    cudaGetSymbolAddress((void**)&pEo,   g_eo);
    cudaGetSymbolAddress((void**)&pW1t,  g_W1t);
    cudaGetSymbolAddress((void**)&pW2t,  g_W2t);
    cudaGetSymbolAddress((void**)&pT16,  g_t16);
    cudaGetSymbolAddress((void**)&pBase, g_base);
    cudaGetSymbolAddress((void**)&pPt,   g_Pt);
    cudaGetSymbolAddress((void**)&pW3t,  g_W3t);
    cudaGetSymbolAddress((void**)&pAW2t, g_aW2t);
    cudaGetSymbolAddress((void**)&pWb,   g_Wb);
    cudaGetSymbolAddress((void**)&pH16,  g_hist16);

    const int attn_smem = (int)sizeof(AttnSmem);
    const int tb_smem   = (int)sizeof(TBSmem);
    cudaFuncSetAttribute(attn_kernel,  cudaFuncAttributeMaxDynamicSharedMemorySize, attn_smem);
    cudaFuncSetAttribute(tbase_kernel, cudaFuncAttributeMaxDynamicSharedMemorySize, tb_smem);
    cudaFuncSetAttribute(hgemm_bias_relu<true>,  cudaFuncAttributeMaxDynamicSharedMemorySize, HGEMM_SMEM);
    cudaFuncSetAttribute(hgemm_bias_relu<false>, cudaFuncAttributeMaxDynamicSharedMemorySize, HGEMM_SMEM);

    // K0: weight prep + history fp16 conversion + per-row t/base
    prep_weights<<<(N_PREP + 255) / 256, 256>>>(
        eW1, eW2, aW1, aW2, pW1t, pW2t, pPt, pW3t, pAW2t, pWb);
    conv_hist<<<(int)((N_HIST2 + 255) / 256), 256>>>(histE, pH16);
    tbase_kernel<<<BATCH / 64, 256, tb_smem>>>(
        iid, itemE, Wproj, pWb, ab1, pT16, pBase);

    // K1: attention + feature concat
    attn_kernel<<<BATCH, 256, attn_smem>>>(
        uid, iid, cid, did, udense, idense, hseq,
        userE, itemE, catE, durE, pH16,
        pT16, pBase, pPt, pW3t, pAW2t, aW3, ab3, ab2, pS, pSh);

    // K2a: eh = relu(S @ eW1 + eb1)
    hgemm_bias_relu<true><<<dim3(EHID / TBN, BATCH / TBM, NEXP), 256, HGEMM_SMEM>>>(
        pSh, pW1t, eb1, pEh,
        BATCH, EHID,
        (size_t)0, (size_t)EHID * KPAD, (size_t)EHID, (size_t)BATCH * EHID);

    // K2b: eo = relu(eh @ eW2 + eb2)
    hgemm_bias_relu<false><<<dim3(EOUT / TBN, BATCH / TBM, NEXP), 256, HGEMM_SMEM>>>(
        pEh, pW2t, eb2, pEo,
        BATCH, EOUT,
        (size_t)BATCH * EHID, (size_t)EOUT * KPAD, (size_t)EOUT, (size_t)BATCH * EOUT);

    // K3: gates + mix + towers + sigmoid
    head_kernel<<<BATCH / 4, 256>>>(
        pS, pEo, gW, gb, tW1, tb1, tW2, tb2, tW3, tb3, out);
}

// round 13
// speedup vs baseline: 2.4959x; 1.0835x over previous
#include <cuda_runtime.h>
#include <cuda_fp16.h>
#include <math.h>

// ---------------------------------------------------------------------------
// Problem constants
// ---------------------------------------------------------------------------
#define BATCH   16384
#define LSEQ    200
#define CONCAT  244
#define KPAD    256
#define NEXP    8
#define EHID    256
#define EOUT    128
#define NTASK   2
#define NITEMS1 100001
#define CH      32
#define NCH     7
#define SEQPAD  224
#define HLD2    72       // halves per row: h / h1 / aW2t
#define LLD     68       // fp32 leading dim (tbase kernel)

// ---------------------------------------------------------------------------
// Scratch (static device globals — no allocation allowed)
// ---------------------------------------------------------------------------
__device__ float  g_S   [(long)BATCH * CONCAT];
__device__ __half g_Sh  [(long)BATCH * KPAD];
__device__ __half g_ehh [(long)NEXP * BATCH * EHID];
__device__ float  g_eo  [(long)NEXP * BATCH * EOUT];
__device__ __half g_W1t [(long)NEXP * EHID * KPAD];
__device__ __half g_W2t [(long)NEXP * EOUT * KPAD];
__device__ __half g_t16 [(long)BATCH * 64];
__device__ float  g_base[(long)BATCH * 64];
__device__ __half g_hist16[(long)NITEMS1 * 64];
__device__ __half g_Pt  [64 * 64];                // [n][k]: aW1[64+k]-aW1[128+k]
__device__ __half g_W3t [64 * 64];                // [n][k]: aW1[192+k]
__device__ __half g_aW2t[16 * 64];                // [n][k]
__device__ float  g_Wb  [64 * 64];

// ---------------------------------------------------------------------------
// cp.async / ldmatrix / mma helpers
// ---------------------------------------------------------------------------
__device__ __forceinline__ void cp_async16(void* smem_dst, const void* gsrc) {
    unsigned sm = (unsigned)__cvta_generic_to_shared(smem_dst);
    asm volatile("cp.async.cg.shared.global [%0], [%1], 16;\n" :: "r"(sm), "l"(gsrc));
}
__device__ __forceinline__ void cp_commit() {
    asm volatile("cp.async.commit_group;\n");
}
template <int N>
__device__ __forceinline__ void cp_wait() {
    asm volatile("cp.async.wait_group %0;\n" :: "n"(N));
}
__device__ __forceinline__ void cp_wait_n(int n) {
    switch (n) {
        case 0: cp_wait<0>(); break;
        case 1: cp_wait<1>(); break;
        case 2: cp_wait<2>(); break;
        case 3: cp_wait<3>(); break;
        case 4: cp_wait<4>(); break;
        case 5: cp_wait<5>(); break;
        case 6: cp_wait<6>(); break;
        default: cp_wait<7>(); break;
    }
}

// ldmatrix x4: loads a 16x16 fp16 A-tile; per-lane address encodes
// rows 0-7/8-15 x k 0-7/8-15 quadrants in standard mma order.
__device__ __forceinline__ void ldsm_x4(unsigned* r, const void* p) {
    unsigned addr = (unsigned)__cvta_generic_to_shared(p);
    asm volatile("ldmatrix.sync.aligned.m8n8.x4.shared.b16 {%0,%1,%2,%3}, [%4];\n"
                 : "=r"(r[0]), "=r"(r[1]), "=r"(r[2]), "=r"(r[3]) : "r"(addr));
}

// fp16 mma m16n8k16, fp32 accum.
__device__ __forceinline__ void mma_f16(float* d, const unsigned* a, const unsigned* b) {
    asm volatile(
        "mma.sync.aligned.m16n8k16.row.col.f32.f16.f16.f32 "
        "{%0,%1,%2,%3}, {%4,%5,%6,%7}, {%8,%9}, {%0,%1,%2,%3};\n"
        : "+f"(d[0]), "+f"(d[1]), "+f"(d[2]), "+f"(d[3])
        : "r"(a[0]), "r"(a[1]), "r"(a[2]), "r"(a[3]),
          "r"(b[0]), "r"(b[1]));
}

// ---------------------------------------------------------------------------
// Kernel 0: weight prep
// ---------------------------------------------------------------------------
#define N_W1T (NEXP * EHID * KPAD)
#define N_W2T (NEXP * EOUT * KPAD)
#define N_PT  (64 * 64)
#define N_W3  (64 * 64)
#define N_AW2 (16 * 64)
#define N_WB  (64 * 64)
#define N_PREP (N_W1T + N_W2T + N_PT + N_W3 + N_AW2 + N_WB)

__global__ void __launch_bounds__(256)
prep_weights(const float* __restrict__ eW1, const float* __restrict__ eW2,
             const float* __restrict__ aW1, const float* __restrict__ aW2,
             __half* __restrict__ W1t, __half* __restrict__ W2t,
             __half* __restrict__ Pt, __half* __restrict__ W3t,
             __half* __restrict__ aW2t, float* __restrict__ Wb)
{
    int i = blockIdx.x * 256 + threadIdx.x;
    if (i < N_W1T) {
        const int e = i >> 16, n = (i >> 8) & 255, k = i & 255;
        const float v = (k < CONCAT) ? eW1[((long)e * CONCAT + k) * EHID + n] : 0.f;
        W1t[i] = __float2half(v);
        return;
    }
    i -= N_W1T;
    if (i < N_W2T) {
        const int e = i >> 15, n = (i >> 8) & 127, k = i & 255;
        W2t[i] = __float2half(eW2[((long)e * EHID + k) * EOUT + n]);
        return;
    }
    i -= N_W2T;
    if (i < N_PT) {
        const int n = i >> 6, k = i & 63;
        Pt[i] = __float2half(aW1[(64 + k) * 64 + n] - aW1[(128 + k) * 64 + n]);
        return;
    }
    i -= N_PT;
    if (i < N_W3) {
        const int n = i >> 6, k = i & 63;
        W3t[i] = __float2half(aW1[(192 + k) * 64 + n]);
        return;
    }
    i -= N_W3;
    if (i < N_AW2) {
        const int n = i >> 6, k = i & 63;
        aW2t[i] = __float2half(aW2[k * 16 + n]);
        return;
    }
    i -= N_AW2;
    if (i < N_WB) {
        const int k = i >> 6, j = i & 63;
        Wb[i] = aW1[k * 64 + j] + aW1[(128 + k) * 64 + j];
    }
}

// ---------------------------------------------------------------------------
// Kernel 0c: convert histE to fp16
// ---------------------------------------------------------------------------
#define N_HIST2 ((long)NITEMS1 * 32)

__global__ void __launch_bounds__(256)
conv_hist(const float* __restrict__ histE, __half* __restrict__ h16)
{
    const long i = (long)blockIdx.x * 256 + threadIdx.x;
    if (i < N_HIST2) {
        const float2 v = reinterpret_cast<const float2*>(histE)[i];
        reinterpret_cast<__half2*>(h16)[i] = __floats2half2_rn(v.x, v.y);
    }
}

// ---------------------------------------------------------------------------
// Kernel 0b: per-row t = i_emb @ Wproj (fp16) and base = ab1 + t @ Wb
// ---------------------------------------------------------------------------
struct TBSmem {
    float Wp[64 * LLD];
    float Wbs[64 * LLD];
    float I[64 * LLD];
    float T[64 * LLD];
    int   ids[64];
};

__global__ void __launch_bounds__(256)
tbase_kernel(const int* __restrict__ iid, const float* __restrict__ itemE,
             const float* __restrict__ Wproj, const float* __restrict__ Wb,
             const float* __restrict__ ab1,
             __half* __restrict__ t16, float* __restrict__ base)
{
    extern __shared__ unsigned char smem_raw[];
    TBSmem& s = *reinterpret_cast<TBSmem*>(smem_raw);
    const int tid = threadIdx.x;
    const int b0 = blockIdx.x * 64;

    if (tid < 64) s.ids[tid] = iid[b0 + tid];
    #pragma unroll
    for (int h = 0; h < 4; h++) {
        const int idx = tid + h * 256;
        const int k = idx >> 4, f = (idx & 15) * 4;
        cp_async16(&s.Wp[k * LLD + f],  Wproj + k * 64 + f);
        cp_async16(&s.Wbs[k * LLD + f], Wb    + k * 64 + f);
    }
    cp_commit();
    __syncthreads();
    #pragma unroll
    for (int h = 0; h < 4; h++) {
        const int idx = tid + h * 256;
        const int r = idx >> 4, f = (idx & 15) * 4;
        cp_async16(&s.I[r * LLD + f], itemE + (long)s.ids[r] * 64 + f);
    }
    cp_commit();
    cp_wait<0>();
    __syncthreads();

    const int r = tid >> 2;
    const int jg = (tid & 3) * 16;
    {
        float acc[16];
        #pragma unroll
        for (int j = 0; j < 16; j++) acc[j] = 0.f;
        #pragma unroll 4
        for (int k = 0; k < 64; k++) {
            const float ik = s.I[r * LLD + k];
            #pragma unroll
            for (int j = 0; j < 16; j++) acc[j] += ik * s.Wp[k * LLD + jg + j];
        }
        #pragma unroll
        for (int j = 0; j < 16; j++) {
            s.T[r * LLD + jg + j] = acc[j];
            t16[(long)(b0 + r) * 64 + jg + j] = __float2half(acc[j]);
        }
    }
    __syncthreads();
    {
        float acc[16];
        #pragma unroll
        for (int j = 0; j < 16; j++) acc[j] = ab1[jg + j];
        #pragma unroll 4
        for (int k = 0; k < 64; k++) {
            const float tk = s.T[r * LLD + k];
            #pragma unroll
            for (int j = 0; j < 16; j++) acc[j] += tk * s.Wbs[k * LLD + jg + j];
        }
        #pragma unroll
        for (int j = 0; j < 16; j++)
            base[(long)(b0 + r) * 64 + jg + j] = acc[j];
    }
}

// ---------------------------------------------------------------------------
// Kernel 1: DIN attention — ldmatrix A-loads, register-resident B fragments
// (loaded straight from L2-hot global), warp-per-n8 layout. ~47 KB smem.
// ---------------------------------------------------------------------------
struct AttnSmem {
    __half h[SEQPAD * HLD2];       // resident history (32.3 KB)
    __half h1[2][CH * HLD2];       // layer1 out, double buffer (9.2 KB)
    __half aW2t[16 * HLD2];        // (2.3 KB)
    __half2 t2s[32];
    float base[64];
    float sc[SEQPAD];
    float part8[8][64];
    float poolred[64];
    float aW3s[16];
    float ab2s[16];
    float red[8];
    float denom;
    int   seqs[SEQPAD];
};

__global__ void __launch_bounds__(256, 4)
attn_kernel(const int* __restrict__ uid, const int* __restrict__ iid,
            const int* __restrict__ cid, const int* __restrict__ did,
            const float* __restrict__ udense, const float* __restrict__ idense,
            const int* __restrict__ hseq,
            const float* __restrict__ userE, const float* __restrict__ itemE,
            const float* __restrict__ catE,  const float* __restrict__ durE,
            const __half* __restrict__ hist16,
            const __half* __restrict__ t16, const float* __restrict__ baseg,
            const __half* __restrict__ Ptg, const __half* __restrict__ W3tg,
            const __half* __restrict__ aW2tg,
            const float* __restrict__ aW3, const float* __restrict__ ab3,
            const float* __restrict__ ab2,
            float* __restrict__ Sout, __half* __restrict__ Shout)
{
    extern __shared__ unsigned char smem_raw[];
    AttnSmem& s = *reinterpret_cast<AttnSmem*>(smem_raw);

    const int b    = blockIdx.x;
    const int tid  = threadIdx.x;
    const int lane = tid & 31;
    const int warp = tid >> 5;
    const int qr   = lane >> 2;
    const int qc   = lane & 3;

    // ---- group 0: stage aW2t ----
    if (tid < 128) {
        const int n = tid >> 3, k8 = (tid & 7) * 8;
        cp_async16(&s.aW2t[n * HLD2 + k8], aW2tg + n * 64 + k8);
    }
    cp_commit();

    // ---- per-row constants + sequence ids ----
    if (tid < 32)
        s.t2s[tid] = reinterpret_cast<const __half2*>(t16 + (long)b * 64)[tid];
    if (tid < 64) s.base[tid] = baseg[(long)b * 64 + tid];
    if (tid < 16) { s.aW3s[tid] = aW3[tid]; s.ab2s[tid] = ab2[tid]; }
    if (tid < SEQPAD) s.seqs[tid] = (tid < LSEQ) ? hseq[(long)b * LSEQ + tid] : 0;
    __syncthreads();    // seqs visible

    // ---- groups 1..7: all chunk gathers (fp16, 256 transfers each) ----
    #pragma unroll
    for (int ch = 0; ch < NCH; ch++) {
        const int r = tid >> 3;
        const int f8 = (tid & 7) * 8;
        const int sid = s.seqs[ch * CH + r];
        cp_async16(&s.h[(ch * CH + r) * HLD2 + f8], hist16 + (long)sid * 64 + f8);
        cp_commit();
    }

    // ---- hoist B fragments for this warp's n8 columns (L2-hot global) ----
    unsigned bPt[4][2], bW3[4][2];
    {
        const int n = warp * 8 + qr;
        #pragma unroll
        for (int ks = 0; ks < 4; ks++) {
            bPt[ks][0] = *reinterpret_cast<const unsigned*>(Ptg  + n * 64 + ks * 16 + 2 * qc);
            bPt[ks][1] = *reinterpret_cast<const unsigned*>(Ptg  + n * 64 + ks * 16 + 2 * qc + 8);
            bW3[ks][0] = *reinterpret_cast<const unsigned*>(W3tg + n * 64 + ks * 16 + 2 * qc);
            bW3[ks][1] = *reinterpret_cast<const unsigned*>(W3tg + n * 64 + ks * 16 + 2 * qc + 8);
        }
    }

    const float ab3v = ab3[0];
    // ldmatrix lane-address components
    const int lrow = (lane & 7) + ((lane >> 3) & 1) * 8;   // row within 16
    const int lkof = (lane >> 4) * 8;                      // k offset 0/8

    // ---- chunk loop ----
    #pragma unroll
    for (int c = 0; c < NCH; c++) {
        cp_wait_n(NCH - 1 - c);
        __syncthreads();

        // layer 1: h1 = relu(h@P + (t*h)@W3 + base); warp w -> cols w*8..w*8+7
        {
            const int n8 = warp * 8;
            float acc[2][4];
            #pragma unroll
            for (int mi = 0; mi < 2; mi++) {
                acc[mi][0] = s.base[n8 + 2 * qc];
                acc[mi][1] = s.base[n8 + 2 * qc + 1];
                acc[mi][2] = acc[mi][0];
                acc[mi][3] = acc[mi][1];
            }
            #pragma unroll
            for (int mi = 0; mi < 2; mi++) {
                const int rowb = c * CH + mi * 16;
                #pragma unroll
                for (int ks = 0; ks < 4; ks++) {
                    unsigned a[4], ua[4];
                    ldsm_x4(a, &s.h[(rowb + lrow) * HLD2 + ks * 16 + lkof]);
                    const __half2 tlo = s.t2s[ks * 8 + qc];
                    const __half2 thi = s.t2s[ks * 8 + qc + 4];
                    __half2 u0 = __hmul2(*reinterpret_cast<const __half2*>(&a[0]), tlo);
                    __half2 u1 = __hmul2(*reinterpret_cast<const __half2*>(&a[1]), tlo);
                    __half2 u2 = __hmul2(*reinterpret_cast<const __half2*>(&a[2]), thi);
                    __half2 u3 = __hmul2(*reinterpret_cast<const __half2*>(&a[3]), thi);
                    ua[0] = *reinterpret_cast<const unsigned*>(&u0);
                    ua[1] = *reinterpret_cast<const unsigned*>(&u1);
                    ua[2] = *reinterpret_cast<const unsigned*>(&u2);
                    ua[3] = *reinterpret_cast<const unsigned*>(&u3);
                    mma_f16(acc[mi], a,  bPt[ks]);
                    mma_f16(acc[mi], ua, bW3[ks]);
                }
            }
            __half* h1b = s.h1[c & 1];
            #pragma unroll
            for (int mi = 0; mi < 2; mi++) {
                const int rr = mi * 16 + qr;
                *reinterpret_cast<__half2*>(&h1b[rr * HLD2 + n8 + 2 * qc]) =
                    __floats2half2_rn(fmaxf(acc[mi][0], 0.f), fmaxf(acc[mi][1], 0.f));
                *reinterpret_cast<__half2*>(&h1b[(rr + 8) * HLD2 + n8 + 2 * qc]) =
                    __floats2half2_rn(fmaxf(acc[mi][2], 0.f), fmaxf(acc[mi][3], 0.f));
            }
        }
        __syncthreads();

        // layer 2 (mma) + layer 3 (registers): warps 0,1
        if (warp < 2) {
            const __half* h1b = s.h1[c & 1];
            float acc2[2][4];
            #pragma unroll
            for (int ni = 0; ni < 2; ni++) {
                acc2[ni][0] = s.ab2s[ni * 8 + 2 * qc];
                acc2[ni][1] = s.ab2s[ni * 8 + 2 * qc + 1];
                acc2[ni][2] = acc2[ni][0];
                acc2[ni][3] = acc2[ni][1];
            }
            const int rowb = warp * 16;
            #pragma unroll
            for (int ks = 0; ks < 4; ks++) {
                unsigned a[4];
                ldsm_x4(a, &h1b[(rowb + lrow) * HLD2 + ks * 16 + lkof]);
                #pragma unroll
                for (int ni = 0; ni < 2; ni++) {
                    unsigned bv[2];
                    const __half* bp = &s.aW2t[(ni * 8 + qr) * HLD2 + ks * 16 + 2 * qc];
                    bv[0] = *reinterpret_cast<const unsigned*>(bp);
                    bv[1] = *reinterpret_cast<const unsigned*>(bp + 8);
                    mma_f16(acc2[ni], a, bv);
                }
            }
            float w0 = 0.f, w1 = 0.f;
            #pragma unroll
            for (int ni = 0; ni < 2; ni++) {
                const float g0 = s.aW3s[ni * 8 + 2 * qc];
                const float g1 = s.aW3s[ni * 8 + 2 * qc + 1];
                w0 += fmaxf(acc2[ni][0], 0.f) * g0 + fmaxf(acc2[ni][1], 0.f) * g1;
                w1 += fmaxf(acc2[ni][2], 0.f) * g0 + fmaxf(acc2[ni][3], 0.f) * g1;
            }
            w0 += __shfl_xor_sync(0xffffffffu, w0, 1);
            w0 += __shfl_xor_sync(0xffffffffu, w0, 2);
            w1 += __shfl_xor_sync(0xffffffffu, w1, 1);
            w1 += __shfl_xor_sync(0xffffffffu, w1, 2);
            if (qc == 0) {
                const int l0 = c * CH + warp * 16 + qr;
                const int l1 = l0 + 8;
                float e0 = 0.f, e1 = 0.f;
                if (l0 < LSEQ && s.seqs[l0] != 0) e0 = __expf(w0 + ab3v);
                if (l1 < LSEQ && s.seqs[l1] != 0) e1 = __expf(w1 + ab3v);
                s.sc[l0] = e0;
                s.sc[l1] = e1;
            }
        }
        // no trailing sync: h1 double buffer gives a 2-chunk reuse gap
    }
    __syncthreads();

    // ---- denom = sum sc ----
    {
        float sv = (tid < SEQPAD) ? s.sc[tid] : 0.f;
        #pragma unroll
        for (int off = 16; off >= 1; off >>= 1)
            sv += __shfl_xor_sync(0xffffffffu, sv, off);
        if (lane == 0) s.red[warp] = sv;
    }
    __syncthreads();
    if (tid == 0) {
        float ss = 0.f;
        #pragma unroll
        for (int w = 0; w < 8; w++) ss += s.red[w];
        s.denom = 1.f / ss;
    }

    // ---- pooling over resident h (half2, 8 row-groups of 28) ----
    {
        const int g = warp;                 // 0..7
        const int d2 = lane;                // half2 column
        float ax = 0.f, ay = 0.f;
        #pragma unroll 7
        for (int i = 0; i < 28; i++) {
            const int l = g * 28 + i;
            const float w = s.sc[l];
            const __half2 hv = *reinterpret_cast<const __half2*>(&s.h[l * HLD2 + 2 * d2]);
            ax += w * __low2float(hv);
            ay += w * __high2float(hv);
        }
        s.part8[g][2 * d2]     = ax;
        s.part8[g][2 * d2 + 1] = ay;
    }
    __syncthreads();
    if (tid < 64) {
        float acc = 0.f;
        #pragma unroll
        for (int g = 0; g < 8; g++) acc += s.part8[g][tid];
        s.poolred[tid] = acc * s.denom;
    }
    __syncthreads();

    // ---- write feature row (fp32 + fp16 padded) ----
    {
        const int item = iid[b];
        float v = 0.f;
        if (tid < CONCAT) {
            if      (tid < 64)  v = userE[(long)uid[b] * 64 + tid];
            else if (tid < 128) v = itemE[(long)item * 64 + (tid - 64)];
            else if (tid < 144) v = catE[(long)cid[b] * 16 + (tid - 128)];
            else if (tid < 152) v = durE[(long)did[b] * 8 + (tid - 144)];
            else if (tid < 177) v = udense[(long)b * 25 + (tid - 152)];
            else if (tid < 180) v = idense[(long)b * 3 + (tid - 177)];
            else                v = s.poolred[tid - 180];
            Sout[(long)b * CONCAT + tid] = v;
        }
        Shout[(long)b * KPAD + tid] = __float2half(v);
    }
}

// ---------------------------------------------------------------------------
// Kernel 2: batched fp16 GEMM + bias + ReLU (unchanged, passing)
// ---------------------------------------------------------------------------
#define TBM 128
#define TBN 128
#define TBK 16
#define NSTG 4
#define HLG 24

#define HGEMM_SMEM ((NSTG * TBM * HLG + NSTG * TBN * HLG) * 2)

template <bool OUT_HALF>
__global__ void __launch_bounds__(256, 2)
hgemm_bias_relu(const __half* __restrict__ A, const __half* __restrict__ Bt,
                const float* __restrict__ bias, void* __restrict__ Cout,
                int M, int N,
                size_t sA, size_t sB, size_t sBias, size_t sC)
{
    extern __shared__ __half smemh[];
    __half* As = smemh;
    __half* Bs = smemh + NSTG * TBM * HLG;

    const int z = blockIdx.z;
    A += (size_t)z * sA; Bt += (size_t)z * sB;
    bias += (size_t)z * sBias;

    const int m0 = blockIdx.y * TBM;
    const int n0 = blockIdx.x * TBN;
    const int tid = threadIdx.x;
    const int lane = tid & 31;
    const int warp = tid >> 5;
    const int wr = warp >> 2;
    const int wc = warp & 3;
    const int qr = lane >> 2;
    const int qc = lane & 3;

    const int nk = KPAD / TBK;

    const int l_row = tid >> 1;
    const int l_hc  = (tid & 1) * 8;

    auto load_stage = [&](int st, int k0) {
        __half* as = As + st * TBM * HLG;
        __half* bs = Bs + st * TBN * HLG;
        cp_async16(&as[l_row * HLG + l_hc], A  + (size_t)(m0 + l_row) * KPAD + k0 + l_hc);
        cp_async16(&bs[l_row * HLG + l_hc], Bt + (size_t)(n0 + l_row) * KPAD + k0 + l_hc);
    };

    float acc[4][4][4];
    #pragma unroll
    for (int i = 0; i < 4; i++)
        #pragma unroll
        for (int j = 0; j < 4; j++)
            #pragma unroll
            for (int e = 0; e < 4; e++) acc[i][j][e] = 0.f;

    #pragma unroll
    for (int s0 = 0; s0 < NSTG - 1; s0++) {
        load_stage(s0, s0 * TBK);
        cp_commit();
    }

    for (int kt = 0; kt < nk; kt++) {
        cp_wait<NSTG - 2>();
        __syncthreads();

        const int knext = kt + NSTG - 1;
        if (knext < nk) load_stage(knext % NSTG, knext * TBK);
        cp_commit();

        const __half* as = As + (kt % NSTG) * TBM * HLG;
        const __half* bs = Bs + (kt % NSTG) * TBN * HLG;

        unsigned a[4][4], bfr[4][2];
        #pragma unroll
        for (int mi = 0; mi < 4; mi++) {
            const int r = wr * 64 + mi * 16 + qr;
            a[mi][0] = *reinterpret_cast<const unsigned*>(as + r * HLG + 2 * qc);
            a[mi][1] = *reinterpret_cast<const unsigned*>(as + (r + 8) * HLG + 2 * qc);
            a[mi][2] = *reinterpret_cast<const unsigned*>(as + r * HLG + 2 * qc + 8);
            a[mi][3] = *reinterpret_cast<const unsigned*>(as + (r + 8) * HLG + 2 * qc + 8);
        }
        #pragma unroll
        for (int ni = 0; ni < 4; ni++) {
            const int n = wc * 32 + ni * 8 + qr;
            bfr[ni][0] = *reinterpret_cast<const unsigned*>(bs + n * HLG + 2 * qc);
            bfr[ni][1] = *reinterpret_cast<const unsigned*>(bs + n * HLG + 2 * qc + 8);
        }
        #pragma unroll
        for (int mi = 0; mi < 4; mi++)
            #pragma unroll
            for (int ni = 0; ni < 4; ni++)
                mma_f16(acc[mi][ni], a[mi], bfr[ni]);

        __syncthreads();
    }

    #pragma unroll
    for (int mi = 0; mi < 4; mi++) {
        #pragma unroll
        for (int ni = 0; ni < 4; ni++) {
            const int gm = m0 + wr * 64 + mi * 16 + qr;
            const int gn = n0 + wc * 32 + ni * 8 + qc * 2;
            const float b0 = bias[gn], b1 = bias[gn + 1];
            const float v0 = fmaxf(acc[mi][ni][0] + b0, 0.f);
            const float v1 = fmaxf(acc[mi][ni][1] + b1, 0.f);
            const float v2 = fmaxf(acc[mi][ni][2] + b0, 0.f);
            const float v3 = fmaxf(acc[mi][ni][3] + b1, 0.f);
            if (OUT_HALF) {
                __half* C = (__half*)Cout + (size_t)z * sC;
                *reinterpret_cast<__half2*>(C + (size_t)gm * N + gn) =
                    __floats2half2_rn(v0, v1);
                *reinterpret_cast<__half2*>(C + (size_t)(gm + 8) * N + gn) =
                    __floats2half2_rn(v2, v3);
            } else {
                float* C = (float*)Cout + (size_t)z * sC;
                *reinterpret_cast<float2*>(C + (size_t)gm * N + gn) = make_float2(v0, v1);
                *reinterpret_cast<float2*>(C + (size_t)(gm + 8) * N + gn) = make_float2(v2, v3);
            }
        }
    }
}

// ---------------------------------------------------------------------------
// Kernel 3: gates (softmax) + expert mix + towers + sigmoid (unchanged)
// ---------------------------------------------------------------------------
__global__ void __launch_bounds__(256)
head_kernel(const float* __restrict__ S, const float* __restrict__ eo,
            const float* __restrict__ gW, const float* __restrict__ gb,
            const float* __restrict__ tW1, const float* __restrict__ tb1,
            const float* __restrict__ tW2, const float* __restrict__ tb2,
            const float* __restrict__ tW3, const float* __restrict__ tb3,
            float* __restrict__ out)
{
    __shared__ float Srow[4][CONCAT];
    __shared__ float gate[4][16];
    __shared__ float ti[4][NTASK][EOUT];
    __shared__ float x1[4][NTASK][64];
    __shared__ float x2[4][NTASK][32];

    const int g = threadIdx.x >> 6;
    const int lane = threadIdx.x & 63;
    const int b = blockIdx.x * 4 + g;

    for (int c = lane; c < CONCAT; c += 64) Srow[g][c] = S[(long)b * CONCAT + c];
    __syncthreads();

    {
        const int o = lane >> 2;
        const int q = lane & 3;
        const int t = o >> 3, e = o & 7;
        const int c0 = q * 61;
        float acc = 0.f;
        #pragma unroll 8
        for (int c = c0; c < c0 + 61; c++)
            acc += Srow[g][c] * __ldg(&gW[((long)t * CONCAT + c) * 8 + e]);
        acc += __shfl_xor_sync(0xffffffffu, acc, 1);
        acc += __shfl_xor_sync(0xffffffffu, acc, 2);
        if (q == 0) gate[g][o] = acc + gb[t * 8 + e];
    }
    __syncthreads();
    if (lane < 2) {
        const int t = lane;
        float mx = -3.4e38f;
        for (int e = 0; e < 8; e++) mx = fmaxf(mx, gate[g][t * 8 + e]);
        float sum = 0.f, ex[8];
        for (int e = 0; e < 8; e++) { ex[e] = __expf(gate[g][t * 8 + e] - mx); sum += ex[e]; }
        const float is = 1.f / sum;
        for (int e = 0; e < 8; e++) gate[g][t * 8 + e] = ex[e] * is;
    }
    __syncthreads();

    {
        const int t = lane >> 5;
        const int o = (lane & 31) * 4;
        float4 acc = make_float4(0.f, 0.f, 0.f, 0.f);
        #pragma unroll
        for (int e = 0; e < 8; e++) {
            const float gv = gate[g][t * 8 + e];
            const float4 v = *reinterpret_cast<const float4*>(
                eo + ((long)e * BATCH + b) * EOUT + o);
            acc.x += gv * v.x; acc.y += gv * v.y;
            acc.z += gv * v.z; acc.w += gv * v.w;
        }
        *reinterpret_cast<float4*>(&ti[g][t][o]) = acc;
    }
    __syncthreads();

    for (int idx = lane; idx < NTASK * 64; idx += 64) {
        const int t = idx >> 6, j = idx & 63;
        float acc = tb1[t * 64 + j];
        #pragma unroll 8
        for (int o = 0; o < 128; o++)
            acc += ti[g][t][o] * __ldg(&tW1[((long)t * 128 + o) * 64 + j]);
        x1[g][t][j] = fmaxf(acc, 0.f);
    }
    __syncthreads();

    {
        const int t = lane >> 5, m = lane & 31;
        float acc = tb2[t * 32 + m];
        #pragma unroll 8
        for (int j = 0; j < 64; j++)
            acc += x1[g][t][j] * __ldg(&tW2[(t * 64 + j) * 32 + m]);
        x2[g][t][m] = fmaxf(acc, 0.f);
    }
    __syncthreads();

    if (lane < 2) {
        const int t = lane;
        float acc = tb3[t];
        #pragma unroll
        for (int m = 0; m < 32; m++) acc += x2[g][t][m] * tW3[t * 32 + m];
        out[(long)t * BATCH + b] = 1.f / (1.f + __expf(-acc));
    }
}

// ---------------------------------------------------------------------------
// Launch
// ---------------------------------------------------------------------------
extern "C" void kernel_launch(void* const* d_in, const int* in_sizes, int n_in,
                              void* d_out, int out_size)
{
    const int*   uid    = (const int*)  d_in[0];
    const int*   iid    = (const int*)  d_in[1];
    const int*   cid    = (const int*)  d_in[2];
    const int*   did    = (const int*)  d_in[3];
    const float* udense = (const float*)d_in[4];
    const float* idense = (const float*)d_in[5];
    const int*   hseq   = (const int*)  d_in[6];
    const float* userE  = (const float*)d_in[7];
    const float* itemE  = (const float*)d_in[8];
    const float* catE   = (const float*)d_in[9];
    const float* durE   = (const float*)d_in[10];
    const float* histE  = (const float*)d_in[11];
    const float* Wproj  = (const float*)d_in[12];
    const float* aW1    = (const float*)d_in[13];
    const float* ab1    = (const float*)d_in[14];
    const float* aW2    = (const float*)d_in[15];
    const float* ab2    = (const float*)d_in[16];
    const float* aW3    = (const float*)d_in[17];
    const float* ab3    = (const float*)d_in[18];
    const float* eW1    = (const float*)d_in[19];
    const float* eb1    = (const float*)d_in[20];
    const float* eW2    = (const float*)d_in[21];
    const float* eb2    = (const float*)d_in[22];
    const float* gW     = (const float*)d_in[23];
    const float* gb     = (const float*)d_in[24];
    const float* tW1    = (const float*)d_in[25];
    const float* tb1    = (const float*)d_in[26];
    const float* tW2    = (const float*)d_in[27];
    const float* tb2    = (const float*)d_in[28];
    const float* tW3    = (const float*)d_in[29];
    const float* tb3    = (const float*)d_in[30];
    float* out = (float*)d_out;

    float  *pS, *pEo, *pBase, *pWb;
    __half *pSh, *pEh, *pW1t, *pW2t, *pT16, *pPt, *pW3t, *pAW2t, *pH16;
    cudaGetSymbolAddress((void**)&pS,    g_S);
    cudaGetSymbolAddress((void**)&pSh,   g_Sh);
    cudaGetSymbolAddress((void**)&pEh,   g_ehh);
    cudaGetSymbolAddress((void**)&pEo,   g_eo);
    cudaGetSymbolAddress((void**)&pW1t,  g_W1t);
    cudaGetSymbolAddress((void**)&pW2t,  g_W2t);
    cudaGetSymbolAddress((void**)&pT16,  g_t16);
    cudaGetSymbolAddress((void**)&pBase, g_base);
    cudaGetSymbolAddress((void**)&pPt,   g_Pt);
    cudaGetSymbolAddress((void**)&pW3t,  g_W3t);
    cudaGetSymbolAddress((void**)&pAW2t, g_aW2t);
    cudaGetSymbolAddress((void**)&pWb,   g_Wb);
    cudaGetSymbolAddress((void**)&pH16,  g_hist16);

    const int attn_smem = (int)sizeof(AttnSmem);
    const int tb_smem   = (int)sizeof(TBSmem);
    cudaFuncSetAttribute(attn_kernel,  cudaFuncAttributeMaxDynamicSharedMemorySize, attn_smem);
    cudaFuncSetAttribute(tbase_kernel, cudaFuncAttributeMaxDynamicSharedMemorySize, tb_smem);
    cudaFuncSetAttribute(hgemm_bias_relu<true>,  cudaFuncAttributeMaxDynamicSharedMemorySize, HGEMM_SMEM);
    cudaFuncSetAttribute(hgemm_bias_relu<false>, cudaFuncAttributeMaxDynamicSharedMemorySize, HGEMM_SMEM);

    // K0: weight prep + history fp16 conversion + per-row t/base
    prep_weights<<<(N_PREP + 255) / 256, 256>>>(
        eW1, eW2, aW1, aW2, pW1t, pW2t, pPt, pW3t, pAW2t, pWb);
    conv_hist<<<(int)((N_HIST2 + 255) / 256), 256>>>(histE, pH16);
    tbase_kernel<<<BATCH / 64, 256, tb_smem>>>(
        iid, itemE, Wproj, pWb, ab1, pT16, pBase);

    // K1: attention + feature concat
    attn_kernel<<<BATCH, 256, attn_smem>>>(
        uid, iid, cid, did, udense, idense, hseq,
        userE, itemE, catE, durE, pH16,
        pT16, pBase, pPt, pW3t, pAW2t, aW3, ab3, ab2, pS, pSh);

    // K2a: eh = relu(S @ eW1 + eb1)
    hgemm_bias_relu<true><<<dim3(EHID / TBN, BATCH / TBM, NEXP), 256, HGEMM_SMEM>>>(
        pSh, pW1t, eb1, pEh,
        BATCH, EHID,
        (size_t)0, (size_t)EHID * KPAD, (size_t)EHID, (size_t)BATCH * EHID);

    // K2b: eo = relu(eh @ eW2 + eb2)
    hgemm_bias_relu<false><<<dim3(EOUT / TBN, BATCH / TBM, NEXP), 256, HGEMM_SMEM>>>(
        pEh, pW2t, eb2, pEo,
        BATCH, EOUT,
        (size_t)BATCH * EHID, (size_t)EOUT * KPAD, (size_t)EOUT, (size_t)BATCH * EOUT);

    // K3: gates + mix + towers + sigmoid
    head_kernel<<<BATCH / 4, 256>>>(
        pS, pEo, gW, gb, tW1, tb1, tW2, tb2, tW3, tb3, out);
}

// round 14
// speedup vs baseline: 2.5779x; 1.0328x over previous
#include <cuda_runtime.h>
#include <cuda_fp16.h>
#include <math.h>

// ---------------------------------------------------------------------------
// Problem constants
// ---------------------------------------------------------------------------
#define BATCH   16384
#define LSEQ    200
#define CONCAT  244
#define KPAD    256
#define NEXP    8
#define EHID    256
#define EOUT    128
#define NTASK   2
#define NITEMS1 100001
#define CH      32
#define NCH     7
#define SEQPAD  224
#define HLD2    72       // halves per row: h / h1 / Mt / aW2t
#define LLD     68       // fp32 leading dim (tbase kernel)

// ---------------------------------------------------------------------------
// Scratch (static device globals — no allocation allowed)
// ---------------------------------------------------------------------------
__device__ float  g_S   [(long)BATCH * CONCAT];
__device__ __half g_Sh  [(long)BATCH * KPAD];
__device__ __half g_ehh [(long)NEXP * BATCH * EHID];
__device__ float  g_eo  [(long)NEXP * BATCH * EOUT];
__device__ __half g_W1t [(long)NEXP * EHID * KPAD];
__device__ __half g_W2t [(long)NEXP * EOUT * KPAD];
__device__ __half g_t16 [(long)BATCH * 64];
__device__ float  g_base[(long)BATCH * 64];
__device__ __half g_hist16[(long)NITEMS1 * 64];
__device__ __half g_Pt  [64 * 64];                // [n][k]: aW1[64+k]-aW1[128+k]
__device__ __half g_W3t [64 * 64];                // [n][k]: aW1[192+k]
__device__ __half g_aW2t[16 * 64];                // [n][k]
__device__ float  g_Wb  [64 * 64];

// ---------------------------------------------------------------------------
// cp.async / ldmatrix / mma helpers
// ---------------------------------------------------------------------------
__device__ __forceinline__ void cp_async16(void* smem_dst, const void* gsrc) {
    unsigned sm = (unsigned)__cvta_generic_to_shared(smem_dst);
    asm volatile("cp.async.cg.shared.global [%0], [%1], 16;\n" :: "r"(sm), "l"(gsrc));
}
__device__ __forceinline__ void cp_commit() {
    asm volatile("cp.async.commit_group;\n");
}
template <int N>
__device__ __forceinline__ void cp_wait() {
    asm volatile("cp.async.wait_group %0;\n" :: "n"(N));
}
__device__ __forceinline__ void cp_wait_n(int n) {
    switch (n) {
        case 0: cp_wait<0>(); break;
        case 1: cp_wait<1>(); break;
        case 2: cp_wait<2>(); break;
        case 3: cp_wait<3>(); break;
        case 4: cp_wait<4>(); break;
        case 5: cp_wait<5>(); break;
        case 6: cp_wait<6>(); break;
        default: cp_wait<7>(); break;
    }
}

__device__ __forceinline__ void ldsm_x4(unsigned* r, const void* p) {
    unsigned addr = (unsigned)__cvta_generic_to_shared(p);
    asm volatile("ldmatrix.sync.aligned.m8n8.x4.shared.b16 {%0,%1,%2,%3}, [%4];\n"
                 : "=r"(r[0]), "=r"(r[1]), "=r"(r[2]), "=r"(r[3]) : "r"(addr));
}

__device__ __forceinline__ void mma_f16(float* d, const unsigned* a, const unsigned* b) {
    asm volatile(
        "mma.sync.aligned.m16n8k16.row.col.f32.f16.f16.f32 "
        "{%0,%1,%2,%3}, {%4,%5,%6,%7}, {%8,%9}, {%0,%1,%2,%3};\n"
        : "+f"(d[0]), "+f"(d[1]), "+f"(d[2]), "+f"(d[3])
        : "r"(a[0]), "r"(a[1]), "r"(a[2]), "r"(a[3]),
          "r"(b[0]), "r"(b[1]));
}

// ---------------------------------------------------------------------------
// Kernel 0: weight prep
// ---------------------------------------------------------------------------
#define N_W1T (NEXP * EHID * KPAD)
#define N_W2T (NEXP * EOUT * KPAD)
#define N_PT  (64 * 64)
#define N_W3  (64 * 64)
#define N_AW2 (16 * 64)
#define N_WB  (64 * 64)
#define N_PREP (N_W1T + N_W2T + N_PT + N_W3 + N_AW2 + N_WB)

__global__ void __launch_bounds__(256)
prep_weights(const float* __restrict__ eW1, const float* __restrict__ eW2,
             const float* __restrict__ aW1, const float* __restrict__ aW2,
             __half* __restrict__ W1t, __half* __restrict__ W2t,
             __half* __restrict__ Pt, __half* __restrict__ W3t,
             __half* __restrict__ aW2t, float* __restrict__ Wb)
{
    int i = blockIdx.x * 256 + threadIdx.x;
    if (i < N_W1T) {
        const int e = i >> 16, n = (i >> 8) & 255, k = i & 255;
        const float v = (k < CONCAT) ? eW1[((long)e * CONCAT + k) * EHID + n] : 0.f;
        W1t[i] = __float2half(v);
        return;
    }
    i -= N_W1T;
    if (i < N_W2T) {
        const int e = i >> 15, n = (i >> 8) & 127, k = i & 255;
        W2t[i] = __float2half(eW2[((long)e * EHID + k) * EOUT + n]);
        return;
    }
    i -= N_W2T;
    if (i < N_PT) {
        const int n = i >> 6, k = i & 63;
        Pt[i] = __float2half(aW1[(64 + k) * 64 + n] - aW1[(128 + k) * 64 + n]);
        return;
    }
    i -= N_PT;
    if (i < N_W3) {
        const int n = i >> 6, k = i & 63;
        W3t[i] = __float2half(aW1[(192 + k) * 64 + n]);
        return;
    }
    i -= N_W3;
    if (i < N_AW2) {
        const int n = i >> 6, k = i & 63;
        aW2t[i] = __float2half(aW2[k * 16 + n]);
        return;
    }
    i -= N_AW2;
    if (i < N_WB) {
        const int k = i >> 6, j = i & 63;
        Wb[i] = aW1[k * 64 + j] + aW1[(128 + k) * 64 + j];
    }
}

// ---------------------------------------------------------------------------
// Kernel 0c: convert histE to fp16
// ---------------------------------------------------------------------------
#define N_HIST2 ((long)NITEMS1 * 32)

__global__ void __launch_bounds__(256)
conv_hist(const float* __restrict__ histE, __half* __restrict__ h16)
{
    const long i = (long)blockIdx.x * 256 + threadIdx.x;
    if (i < N_HIST2) {
        const float2 v = reinterpret_cast<const float2*>(histE)[i];
        reinterpret_cast<__half2*>(h16)[i] = __floats2half2_rn(v.x, v.y);
    }
}

// ---------------------------------------------------------------------------
// Kernel 0b: per-row t = i_emb @ Wproj (fp16) and base = ab1 + t @ Wb
// ---------------------------------------------------------------------------
struct TBSmem {
    float Wp[64 * LLD];
    float Wbs[64 * LLD];
    float I[64 * LLD];
    float T[64 * LLD];
    int   ids[64];
};

__global__ void __launch_bounds__(256)
tbase_kernel(const int* __restrict__ iid, const float* __restrict__ itemE,
             const float* __restrict__ Wproj, const float* __restrict__ Wb,
             const float* __restrict__ ab1,
             __half* __restrict__ t16, float* __restrict__ base)
{
    extern __shared__ unsigned char smem_raw[];
    TBSmem& s = *reinterpret_cast<TBSmem*>(smem_raw);
    const int tid = threadIdx.x;
    const int b0 = blockIdx.x * 64;

    if (tid < 64) s.ids[tid] = iid[b0 + tid];
    #pragma unroll
    for (int h = 0; h < 4; h++) {
        const int idx = tid + h * 256;
        const int k = idx >> 4, f = (idx & 15) * 4;
        cp_async16(&s.Wp[k * LLD + f],  Wproj + k * 64 + f);
        cp_async16(&s.Wbs[k * LLD + f], Wb    + k * 64 + f);
    }
    cp_commit();
    __syncthreads();
    #pragma unroll
    for (int h = 0; h < 4; h++) {
        const int idx = tid + h * 256;
        const int r = idx >> 4, f = (idx & 15) * 4;
        cp_async16(&s.I[r * LLD + f], itemE + (long)s.ids[r] * 64 + f);
    }
    cp_commit();
    cp_wait<0>();
    __syncthreads();

    const int r = tid >> 2;
    const int jg = (tid & 3) * 16;
    {
        float acc[16];
        #pragma unroll
        for (int j = 0; j < 16; j++) acc[j] = 0.f;
        #pragma unroll 4
        for (int k = 0; k < 64; k++) {
            const float ik = s.I[r * LLD + k];
            #pragma unroll
            for (int j = 0; j < 16; j++) acc[j] += ik * s.Wp[k * LLD + jg + j];
        }
        #pragma unroll
        for (int j = 0; j < 16; j++) {
            s.T[r * LLD + jg + j] = acc[j];
            t16[(long)(b0 + r) * 64 + jg + j] = __float2half(acc[j]);
        }
    }
    __syncthreads();
    {
        float acc[16];
        #pragma unroll
        for (int j = 0; j < 16; j++) acc[j] = ab1[jg + j];
        #pragma unroll 4
        for (int k = 0; k < 64; k++) {
            const float tk = s.T[r * LLD + k];
            #pragma unroll
            for (int j = 0; j < 16; j++) acc[j] += tk * s.Wbs[k * LLD + jg + j];
        }
        #pragma unroll
        for (int j = 0; j < 16; j++)
            base[(long)(b0 + r) * 64 + jg + j] = acc[j];
    }
}

// ---------------------------------------------------------------------------
// Kernel 1: DIN attention — fused per-row M (fp16, smem), 2m x 4n warp grid,
// ldmatrix A-loads, register-resident M fragments. ~55 KB smem, 4 blocks/SM.
// ---------------------------------------------------------------------------
struct AttnSmem {
    __half h[SEQPAD * HLD2];       // resident history (32.3 KB)
    __half h1[2][CH * HLD2];       // layer1 out double buffer (9.2 KB); tail scratch
    __half Mt[64 * HLD2];          // fused M^T [n][k] (9.2 KB)
    __half aW2t[16 * HLD2];        // (2.3 KB)
    __half2 t2s[32];
    float base[64];
    float sc[SEQPAD];
    float aW3s[16];
    float ab2s[16];
    float red[8];
    float denom;
    int   seqs[SEQPAD];
};

__global__ void __launch_bounds__(256, 4)
attn_kernel(const int* __restrict__ uid, const int* __restrict__ iid,
            const int* __restrict__ cid, const int* __restrict__ did,
            const float* __restrict__ udense, const float* __restrict__ idense,
            const int* __restrict__ hseq,
            const float* __restrict__ userE, const float* __restrict__ itemE,
            const float* __restrict__ catE,  const float* __restrict__ durE,
            const __half* __restrict__ hist16,
            const __half* __restrict__ t16, const float* __restrict__ baseg,
            const __half* __restrict__ Ptg, const __half* __restrict__ W3tg,
            const __half* __restrict__ aW2tg,
            const float* __restrict__ aW3, const float* __restrict__ ab3,
            const float* __restrict__ ab2,
            float* __restrict__ Sout, __half* __restrict__ Shout)
{
    extern __shared__ unsigned char smem_raw[];
    AttnSmem& s = *reinterpret_cast<AttnSmem*>(smem_raw);

    const int b    = blockIdx.x;
    const int tid  = threadIdx.x;
    const int lane = tid & 31;
    const int warp = tid >> 5;
    const int qr   = lane >> 2;
    const int qc   = lane & 3;

    // ---- group 0: stage aW2t ----
    if (tid < 128) {
        const int n = tid >> 3, k8 = (tid & 7) * 8;
        cp_async16(&s.aW2t[n * HLD2 + k8], aW2tg + n * 64 + k8);
    }
    cp_commit();

    // ---- per-row constants + sequence ids ----
    if (tid < 32)
        s.t2s[tid] = reinterpret_cast<const __half2*>(t16 + (long)b * 64)[tid];
    if (tid < 64) s.base[tid] = baseg[(long)b * 64 + tid];
    if (tid < 16) { s.aW3s[tid] = aW3[tid]; s.ab2s[tid] = ab2[tid]; }
    if (tid < SEQPAD) s.seqs[tid] = (tid < LSEQ) ? hseq[(long)b * LSEQ + tid] : 0;
    __syncthreads();    // seqs + t2s visible

    // ---- groups 1..7: all chunk gathers (fp16, 256 transfers each) ----
    #pragma unroll
    for (int ch = 0; ch < NCH; ch++) {
        const int r = tid >> 3;
        const int f8 = (tid & 7) * 8;
        const int sid = s.seqs[ch * CH + r];
        cp_async16(&s.h[(ch * CH + r) * HLD2 + f8], hist16 + (long)sid * 64 + f8);
        cp_commit();
    }

    // ---- build fused M^T[n][k] = Pt + t[k]*W3t  (half2, L2-hot global in) ----
    for (int i = tid; i < 64 * 32; i += 256) {
        const int n = i >> 5, k2 = i & 31;
        const __half2 p = *reinterpret_cast<const __half2*>(Ptg  + n * 64 + 2 * k2);
        const __half2 w = *reinterpret_cast<const __half2*>(W3tg + n * 64 + 2 * k2);
        *reinterpret_cast<__half2*>(&s.Mt[n * HLD2 + 2 * k2]) = __hfma2(s.t2s[k2], w, p);
    }
    __syncthreads();    // Mt visible

    // ---- hoist M fragments for this warp's n16 (16 regs) ----
    const int wm = warp & 1;          // m16 tile within chunk
    const int wn = warp >> 1;         // n16 tile (0..3)
    unsigned bM[4][2][2];
    #pragma unroll
    for (int ks = 0; ks < 4; ks++)
        #pragma unroll
        for (int ni = 0; ni < 2; ni++) {
            const __half* bp = &s.Mt[(wn * 16 + ni * 8 + qr) * HLD2 + ks * 16 + 2 * qc];
            bM[ks][ni][0] = *reinterpret_cast<const unsigned*>(bp);
            bM[ks][ni][1] = *reinterpret_cast<const unsigned*>(bp + 8);
        }

    const float ab3v = ab3[0];
    const int lrow = (lane & 7) + ((lane >> 3) & 1) * 8;
    const int lkof = (lane >> 4) * 8;

    // ---- chunk loop ----
    #pragma unroll
    for (int c = 0; c < NCH; c++) {
        cp_wait_n(NCH - 1 - c);
        __syncthreads();

        // layer 1: h1 = relu(h @ M + base); warp = (wm m16-tile, wn n16-tile)
        {
            const int n8 = wn * 16;
            float acc[2][4];
            #pragma unroll
            for (int ni = 0; ni < 2; ni++) {
                const int nn = n8 + ni * 8;
                acc[ni][0] = s.base[nn + 2 * qc];
                acc[ni][1] = s.base[nn + 2 * qc + 1];
                acc[ni][2] = acc[ni][0];
                acc[ni][3] = acc[ni][1];
            }
            const int rowb = c * CH + wm * 16;
            #pragma unroll
            for (int ks = 0; ks < 4; ks++) {
                unsigned a[4];
                ldsm_x4(a, &s.h[(rowb + lrow) * HLD2 + ks * 16 + lkof]);
                mma_f16(acc[0], a, bM[ks][0]);
                mma_f16(acc[1], a, bM[ks][1]);
            }
            __half* h1b = s.h1[c & 1];
            const int rr = wm * 16 + qr;
            #pragma unroll
            for (int ni = 0; ni < 2; ni++) {
                const int nn = n8 + ni * 8;
                *reinterpret_cast<__half2*>(&h1b[rr * HLD2 + nn + 2 * qc]) =
                    __floats2half2_rn(fmaxf(acc[ni][0], 0.f), fmaxf(acc[ni][1], 0.f));
                *reinterpret_cast<__half2*>(&h1b[(rr + 8) * HLD2 + nn + 2 * qc]) =
                    __floats2half2_rn(fmaxf(acc[ni][2], 0.f), fmaxf(acc[ni][3], 0.f));
            }
        }
        __syncthreads();

        // layer 2 (mma) + layer 3 (registers): warps 0,1
        if (warp < 2) {
            const __half* h1b = s.h1[c & 1];
            float acc2[2][4];
            #pragma unroll
            for (int ni = 0; ni < 2; ni++) {
                acc2[ni][0] = s.ab2s[ni * 8 + 2 * qc];
                acc2[ni][1] = s.ab2s[ni * 8 + 2 * qc + 1];
                acc2[ni][2] = acc2[ni][0];
                acc2[ni][3] = acc2[ni][1];
            }
            const int rowb = warp * 16;
            #pragma unroll
            for (int ks = 0; ks < 4; ks++) {
                unsigned a[4];
                ldsm_x4(a, &h1b[(rowb + lrow) * HLD2 + ks * 16 + lkof]);
                #pragma unroll
                for (int ni = 0; ni < 2; ni++) {
                    unsigned bv[2];
                    const __half* bp = &s.aW2t[(ni * 8 + qr) * HLD2 + ks * 16 + 2 * qc];
                    bv[0] = *reinterpret_cast<const unsigned*>(bp);
                    bv[1] = *reinterpret_cast<const unsigned*>(bp + 8);
                    mma_f16(acc2[ni], a, bv);
                }
            }
            float w0 = 0.f, w1 = 0.f;
            #pragma unroll
            for (int ni = 0; ni < 2; ni++) {
                const float g0 = s.aW3s[ni * 8 + 2 * qc];
                const float g1 = s.aW3s[ni * 8 + 2 * qc + 1];
                w0 += fmaxf(acc2[ni][0], 0.f) * g0 + fmaxf(acc2[ni][1], 0.f) * g1;
                w1 += fmaxf(acc2[ni][2], 0.f) * g0 + fmaxf(acc2[ni][3], 0.f) * g1;
            }
            w0 += __shfl_xor_sync(0xffffffffu, w0, 1);
            w0 += __shfl_xor_sync(0xffffffffu, w0, 2);
            w1 += __shfl_xor_sync(0xffffffffu, w1, 1);
            w1 += __shfl_xor_sync(0xffffffffu, w1, 2);
            if (qc == 0) {
                const int l0 = c * CH + warp * 16 + qr;
                const int l1 = l0 + 8;
                float e0 = 0.f, e1 = 0.f;
                if (l0 < LSEQ && s.seqs[l0] != 0) e0 = __expf(w0 + ab3v);
                if (l1 < LSEQ && s.seqs[l1] != 0) e1 = __expf(w1 + ab3v);
                s.sc[l0] = e0;
                s.sc[l1] = e1;
            }
        }
        // no trailing sync: h1 double buffer + next-chunk barrier order reuse
    }
    __syncthreads();

    // ---- denom = sum sc ----
    {
        float sv = (tid < SEQPAD) ? s.sc[tid] : 0.f;
        #pragma unroll
        for (int off = 16; off >= 1; off >>= 1)
            sv += __shfl_xor_sync(0xffffffffu, sv, off);
        if (lane == 0) s.red[warp] = sv;
    }
    __syncthreads();
    if (tid == 0) {
        float ss = 0.f;
        #pragma unroll
        for (int w = 0; w < 8; w++) ss += s.red[w];
        s.denom = 1.f / ss;
    }

    // ---- pooling over resident h (half2); scratch aliased onto dead h1 ----
    float* part8   = reinterpret_cast<float*>(s.h1);   // 8 x 64 floats
    float* poolred = part8 + 8 * 64;                   // 64 floats
    {
        const int g = warp;
        const int d2 = lane;
        float ax = 0.f, ay = 0.f;
        #pragma unroll 7
        for (int i = 0; i < 28; i++) {
            const int l = g * 28 + i;
            const float w = s.sc[l];
            const __half2 hv = *reinterpret_cast<const __half2*>(&s.h[l * HLD2 + 2 * d2]);
            ax += w * __low2float(hv);
            ay += w * __high2float(hv);
        }
        part8[g * 64 + 2 * d2]     = ax;
        part8[g * 64 + 2 * d2 + 1] = ay;
    }
    __syncthreads();
    if (tid < 64) {
        float acc = 0.f;
        #pragma unroll
        for (int g = 0; g < 8; g++) acc += part8[g * 64 + tid];
        poolred[tid] = acc * s.denom;
    }
    __syncthreads();

    // ---- write feature row (fp32 + fp16 padded) ----
    {
        const int item = iid[b];
        float v = 0.f;
        if (tid < CONCAT) {
            if      (tid < 64)  v = userE[(long)uid[b] * 64 + tid];
            else if (tid < 128) v = itemE[(long)item * 64 + (tid - 64)];
            else if (tid < 144) v = catE[(long)cid[b] * 16 + (tid - 128)];
            else if (tid < 152) v = durE[(long)did[b] * 8 + (tid - 144)];
            else if (tid < 177) v = udense[(long)b * 25 + (tid - 152)];
            else if (tid < 180) v = idense[(long)b * 3 + (tid - 177)];
            else                v = poolred[tid - 180];
            Sout[(long)b * CONCAT + tid] = v;
        }
        Shout[(long)b * KPAD + tid] = __float2half(v);
    }
}

// ---------------------------------------------------------------------------
// Kernel 2: batched fp16 GEMM + bias + ReLU (unchanged, passing)
// ---------------------------------------------------------------------------
#define TBM 128
#define TBN 128
#define TBK 16
#define NSTG 4
#define HLG 24

#define HGEMM_SMEM ((NSTG * TBM * HLG + NSTG * TBN * HLG) * 2)

template <bool OUT_HALF>
__global__ void __launch_bounds__(256, 2)
hgemm_bias_relu(const __half* __restrict__ A, const __half* __restrict__ Bt,
                const float* __restrict__ bias, void* __restrict__ Cout,
                int M, int N,
                size_t sA, size_t sB, size_t sBias, size_t sC)
{
    extern __shared__ __half smemh[];
    __half* As = smemh;
    __half* Bs = smemh + NSTG * TBM * HLG;

    const int z = blockIdx.z;
    A += (size_t)z * sA; Bt += (size_t)z * sB;
    bias += (size_t)z * sBias;

    const int m0 = blockIdx.y * TBM;
    const int n0 = blockIdx.x * TBN;
    const int tid = threadIdx.x;
    const int lane = tid & 31;
    const int warp = tid >> 5;
    const int wr = warp >> 2;
    const int wc = warp & 3;
    const int qr = lane >> 2;
    const int qc = lane & 3;

    const int nk = KPAD / TBK;

    const int l_row = tid >> 1;
    const int l_hc  = (tid & 1) * 8;

    auto load_stage = [&](int st, int k0) {
        __half* as = As + st * TBM * HLG;
        __half* bs = Bs + st * TBN * HLG;
        cp_async16(&as[l_row * HLG + l_hc], A  + (size_t)(m0 + l_row) * KPAD + k0 + l_hc);
        cp_async16(&bs[l_row * HLG + l_hc], Bt + (size_t)(n0 + l_row) * KPAD + k0 + l_hc);
    };

    float acc[4][4][4];
    #pragma unroll
    for (int i = 0; i < 4; i++)
        #pragma unroll
        for (int j = 0; j < 4; j++)
            #pragma unroll
            for (int e = 0; e < 4; e++) acc[i][j][e] = 0.f;

    #pragma unroll
    for (int s0 = 0; s0 < NSTG - 1; s0++) {
        load_stage(s0, s0 * TBK);
        cp_commit();
    }

    for (int kt = 0; kt < nk; kt++) {
        cp_wait<NSTG - 2>();
        __syncthreads();

        const int knext = kt + NSTG - 1;
        if (knext < nk) load_stage(knext % NSTG, knext * TBK);
        cp_commit();

        const __half* as = As + (kt % NSTG) * TBM * HLG;
        const __half* bs = Bs + (kt % NSTG) * TBN * HLG;

        unsigned a[4][4], bfr[4][2];
        #pragma unroll
        for (int mi = 0; mi < 4; mi++) {
            const int r = wr * 64 + mi * 16 + qr;
            a[mi][0] = *reinterpret_cast<const unsigned*>(as + r * HLG + 2 * qc);
            a[mi][1] = *reinterpret_cast<const unsigned*>(as + (r + 8) * HLG + 2 * qc);
            a[mi][2] = *reinterpret_cast<const unsigned*>(as + r * HLG + 2 * qc + 8);
            a[mi][3] = *reinterpret_cast<const unsigned*>(as + (r + 8) * HLG + 2 * qc + 8);
        }
        #pragma unroll
        for (int ni = 0; ni < 4; ni++) {
            const int n = wc * 32 + ni * 8 + qr;
            bfr[ni][0] = *reinterpret_cast<const unsigned*>(bs + n * HLG + 2 * qc);
            bfr[ni][1] = *reinterpret_cast<const unsigned*>(bs + n * HLG + 2 * qc + 8);
        }
        #pragma unroll
        for (int mi = 0; mi < 4; mi++)
            #pragma unroll
            for (int ni = 0; ni < 4; ni++)
                mma_f16(acc[mi][ni], a[mi], bfr[ni]);

        __syncthreads();
    }

    #pragma unroll
    for (int mi = 0; mi < 4; mi++) {
        #pragma unroll
        for (int ni = 0; ni < 4; ni++) {
            const int gm = m0 + wr * 64 + mi * 16 + qr;
            const int gn = n0 + wc * 32 + ni * 8 + qc * 2;
            const float b0 = bias[gn], b1 = bias[gn + 1];
            const float v0 = fmaxf(acc[mi][ni][0] + b0, 0.f);
            const float v1 = fmaxf(acc[mi][ni][1] + b1, 0.f);
            const float v2 = fmaxf(acc[mi][ni][2] + b0, 0.f);
            const float v3 = fmaxf(acc[mi][ni][3] + b1, 0.f);
            if (OUT_HALF) {
                __half* C = (__half*)Cout + (size_t)z * sC;
                *reinterpret_cast<__half2*>(C + (size_t)gm * N + gn) =
                    __floats2half2_rn(v0, v1);
                *reinterpret_cast<__half2*>(C + (size_t)(gm + 8) * N + gn) =
                    __floats2half2_rn(v2, v3);
            } else {
                float* C = (float*)Cout + (size_t)z * sC;
                *reinterpret_cast<float2*>(C + (size_t)gm * N + gn) = make_float2(v0, v1);
                *reinterpret_cast<float2*>(C + (size_t)(gm + 8) * N + gn) = make_float2(v2, v3);
            }
        }
    }
}

// ---------------------------------------------------------------------------
// Kernel 3: gates (softmax) + expert mix + towers + sigmoid (unchanged)
// ---------------------------------------------------------------------------
__global__ void __launch_bounds__(256)
head_kernel(const float* __restrict__ S, const float* __restrict__ eo,
            const float* __restrict__ gW, const float* __restrict__ gb,
            const float* __restrict__ tW1, const float* __restrict__ tb1,
            const float* __restrict__ tW2, const float* __restrict__ tb2,
            const float* __restrict__ tW3, const float* __restrict__ tb3,
            float* __restrict__ out)
{
    __shared__ float Srow[4][CONCAT];
    __shared__ float gate[4][16];
    __shared__ float ti[4][NTASK][EOUT];
    __shared__ float x1[4][NTASK][64];
    __shared__ float x2[4][NTASK][32];

    const int g = threadIdx.x >> 6;
    const int lane = threadIdx.x & 63;
    const int b = blockIdx.x * 4 + g;

    for (int c = lane; c < CONCAT; c += 64) Srow[g][c] = S[(long)b * CONCAT + c];
    __syncthreads();

    {
        const int o = lane >> 2;
        const int q = lane & 3;
        const int t = o >> 3, e = o & 7;
        const int c0 = q * 61;
        float acc = 0.f;
        #pragma unroll 8
        for (int c = c0; c < c0 + 61; c++)
            acc += Srow[g][c] * __ldg(&gW[((long)t * CONCAT + c) * 8 + e]);
        acc += __shfl_xor_sync(0xffffffffu, acc, 1);
        acc += __shfl_xor_sync(0xffffffffu, acc, 2);
        if (q == 0) gate[g][o] = acc + gb[t * 8 + e];
    }
    __syncthreads();
    if (lane < 2) {
        const int t = lane;
        float mx = -3.4e38f;
        for (int e = 0; e < 8; e++) mx = fmaxf(mx, gate[g][t * 8 + e]);
        float sum = 0.f, ex[8];
        for (int e = 0; e < 8; e++) { ex[e] = __expf(gate[g][t * 8 + e] - mx); sum += ex[e]; }
        const float is = 1.f / sum;
        for (int e = 0; e < 8; e++) gate[g][t * 8 + e] = ex[e] * is;
    }
    __syncthreads();

    {
        const int t = lane >> 5;
        const int o = (lane & 31) * 4;
        float4 acc = make_float4(0.f, 0.f, 0.f, 0.f);
        #pragma unroll
        for (int e = 0; e < 8; e++) {
            const float gv = gate[g][t * 8 + e];
            const float4 v = *reinterpret_cast<const float4*>(
                eo + ((long)e * BATCH + b) * EOUT + o);
            acc.x += gv * v.x; acc.y += gv * v.y;
            acc.z += gv * v.z; acc.w += gv * v.w;
        }
        *reinterpret_cast<float4*>(&ti[g][t][o]) = acc;
    }
    __syncthreads();

    for (int idx = lane; idx < NTASK * 64; idx += 64) {
        const int t = idx >> 6, j = idx & 63;
        float acc = tb1[t * 64 + j];
        #pragma unroll 8
        for (int o = 0; o < 128; o++)
            acc += ti[g][t][o] * __ldg(&tW1[((long)t * 128 + o) * 64 + j]);
        x1[g][t][j] = fmaxf(acc, 0.f);
    }
    __syncthreads();

    {
        const int t = lane >> 5, m = lane & 31;
        float acc = tb2[t * 32 + m];
        #pragma unroll 8
        for (int j = 0; j < 64; j++)
            acc += x1[g][t][j] * __ldg(&tW2[(t * 64 + j) * 32 + m]);
        x2[g][t][m] = fmaxf(acc, 0.f);
    }
    __syncthreads();

    if (lane < 2) {
        const int t = lane;
        float acc = tb3[t];
        #pragma unroll
        for (int m = 0; m < 32; m++) acc += x2[g][t][m] * tW3[t * 32 + m];
        out[(long)t * BATCH + b] = 1.f / (1.f + __expf(-acc));
    }
}

// ---------------------------------------------------------------------------
// Launch
// ---------------------------------------------------------------------------
extern "C" void kernel_launch(void* const* d_in, const int* in_sizes, int n_in,
                              void* d_out, int out_size)
{
    const int*   uid    = (const int*)  d_in[0];
    const int*   iid    = (const int*)  d_in[1];
    const int*   cid    = (const int*)  d_in[2];
    const int*   did    = (const int*)  d_in[3];
    const float* udense = (const float*)d_in[4];
    const float* idense = (const float*)d_in[5];
    const int*   hseq   = (const int*)  d_in[6];
    const float* userE  = (const float*)d_in[7];
    const float* itemE  = (const float*)d_in[8];
    const float* catE   = (const float*)d_in[9];
    const float* durE   = (const float*)d_in[10];
    const float* histE  = (const float*)d_in[11];
    const float* Wproj  = (const float*)d_in[12];
    const float* aW1    = (const float*)d_in[13];
    const float* ab1    = (const float*)d_in[14];
    const float* aW2    = (const float*)d_in[15];
    const float* ab2    = (const float*)d_in[16];
    const float* aW3    = (const float*)d_in[17];
    const float* ab3    = (const float*)d_in[18];
    const float* eW1    = (const float*)d_in[19];
    const float* eb1    = (const float*)d_in[20];
    const float* eW2    = (const float*)d_in[21];
    const float* eb2    = (const float*)d_in[22];
    const float* gW     = (const float*)d_in[23];
    const float* gb     = (const float*)d_in[24];
    const float* tW1    = (const float*)d_in[25];
    const float* tb1    = (const float*)d_in[26];
    const float* tW2    = (const float*)d_in[27];
    const float* tb2    = (const float*)d_in[28];
    const float* tW3    = (const float*)d_in[29];
    const float* tb3    = (const float*)d_in[30];
    float* out = (float*)d_out;

    float  *pS, *pEo, *pBase, *pWb;
    __half *pSh, *pEh, *pW1t, *pW2t, *pT16, *pPt, *pW3t, *pAW2t, *pH16;
    cudaGetSymbolAddress((void**)&pS,    g_S);
    cudaGetSymbolAddress((void**)&pSh,   g_Sh);
    cudaGetSymbolAddress((void**)&pEh,   g_ehh);
    cudaGetSymbolAddress((void**)&pEo,   g_eo);
    cudaGetSymbolAddress((void**)&pW1t,  g_W1t);
    cudaGetSymbolAddress((void**)&pW2t,  g_W2t);
    cudaGetSymbolAddress((void**)&pT16,  g_t16);
    cudaGetSymbolAddress((void**)&pBase, g_base);
    cudaGetSymbolAddress((void**)&pPt,   g_Pt);
    cudaGetSymbolAddress((void**)&pW3t,  g_W3t);
    cudaGetSymbolAddress((void**)&pAW2t, g_aW2t);
    cudaGetSymbolAddress((void**)&pWb,   g_Wb);
    cudaGetSymbolAddress((void**)&pH16,  g_hist16);

    const int attn_smem = (int)sizeof(AttnSmem);
    const int tb_smem   = (int)sizeof(TBSmem);
    cudaFuncSetAttribute(attn_kernel,  cudaFuncAttributeMaxDynamicSharedMemorySize, attn_smem);
    cudaFuncSetAttribute(tbase_kernel, cudaFuncAttributeMaxDynamicSharedMemorySize, tb_smem);
    cudaFuncSetAttribute(hgemm_bias_relu<true>,  cudaFuncAttributeMaxDynamicSharedMemorySize, HGEMM_SMEM);
    cudaFuncSetAttribute(hgemm_bias_relu<false>, cudaFuncAttributeMaxDynamicSharedMemorySize, HGEMM_SMEM);

    // K0: weight prep + history fp16 conversion + per-row t/base
    prep_weights<<<(N_PREP + 255) / 256, 256>>>(
        eW1, eW2, aW1, aW2, pW1t, pW2t, pPt, pW3t, pAW2t, pWb);
    conv_hist<<<(int)((N_HIST2 + 255) / 256), 256>>>(histE, pH16);
    tbase_kernel<<<BATCH / 64, 256, tb_smem>>>(
        iid, itemE, Wproj, pWb, ab1, pT16, pBase);

    // K1: attention + feature concat
    attn_kernel<<<BATCH, 256, attn_smem>>>(
        uid, iid, cid, did, udense, idense, hseq,
        userE, itemE, catE, durE, pH16,
        pT16, pBase, pPt, pW3t, pAW2t, aW3, ab3, ab2, pS, pSh);

    // K2a: eh = relu(S @ eW1 + eb1)
    hgemm_bias_relu<true><<<dim3(EHID / TBN, BATCH / TBM, NEXP), 256, HGEMM_SMEM>>>(
        pSh, pW1t, eb1, pEh,
        BATCH, EHID,
        (size_t)0, (size_t)EHID * KPAD, (size_t)EHID, (size_t)BATCH * EHID);

    // K2b: eo = relu(eh @ eW2 + eb2)
    hgemm_bias_relu<false><<<dim3(EOUT / TBN, BATCH / TBM, NEXP), 256, HGEMM_SMEM>>>(
        pEh, pW2t, eb2, pEo,
        BATCH, EOUT,
        (size_t)BATCH * EHID, (size_t)EOUT * KPAD, (size_t)EOUT, (size_t)BATCH * EOUT);

    // K3: gates + mix + towers + sigmoid
    head_kernel<<<BATCH / 4, 256>>>(
        pS, pEo, gW, gb, tW1, tb1, tW2, tb2, tW3, tb3, out);
}

// round 15
// speedup vs baseline: 2.6090x; 1.0120x over previous
#include <cuda_runtime.h>
#include <cuda_fp16.h>
#include <math.h>

// ---------------------------------------------------------------------------
// Problem constants
// ---------------------------------------------------------------------------
#define BATCH   16384
#define LSEQ    200
#define CONCAT  244
#define KPAD    256
#define NEXP    8
#define EHID    256
#define EOUT    128
#define NTASK   2
#define NITEMS1 100001
#define CH      32
#define NCH     7
#define SEQPAD  224
#define HLD2    72
#define LLD     68

// ---------------------------------------------------------------------------
// Scratch (static device globals — no allocation allowed)
// ---------------------------------------------------------------------------
__device__ float  g_S   [(long)BATCH * CONCAT];
__device__ __half g_Sh  [(long)BATCH * KPAD];
__device__ __half g_ehh [(long)NEXP * BATCH * EHID];
__device__ float  g_eo  [(long)NEXP * BATCH * EOUT];
__device__ __half g_W1t [(long)NEXP * EHID * KPAD];
__device__ __half g_W2t [(long)NEXP * EOUT * KPAD];
__device__ __half g_t16 [(long)BATCH * 64];
__device__ float  g_base[(long)BATCH * 64];
__device__ __half g_hist16[(long)NITEMS1 * 64];
__device__ __half g_Pt  [64 * 64];
__device__ __half g_W3t [64 * 64];
__device__ __half g_aW2t[16 * 64];
__device__ float  g_Wb  [64 * 64];

// ---------------------------------------------------------------------------
// cp.async / ldmatrix / mma helpers
// ---------------------------------------------------------------------------
__device__ __forceinline__ void cp_async16(void* smem_dst, const void* gsrc) {
    unsigned sm = (unsigned)__cvta_generic_to_shared(smem_dst);
    asm volatile("cp.async.cg.shared.global [%0], [%1], 16;\n" :: "r"(sm), "l"(gsrc));
}
__device__ __forceinline__ void cp_commit() {
    asm volatile("cp.async.commit_group;\n");
}
template <int N>
__device__ __forceinline__ void cp_wait() {
    asm volatile("cp.async.wait_group %0;\n" :: "n"(N));
}
__device__ __forceinline__ void cp_wait_n(int n) {
    switch (n) {
        case 0: cp_wait<0>(); break;
        case 1: cp_wait<1>(); break;
        case 2: cp_wait<2>(); break;
        case 3: cp_wait<3>(); break;
        case 4: cp_wait<4>(); break;
        case 5: cp_wait<5>(); break;
        case 6: cp_wait<6>(); break;
        default: cp_wait<7>(); break;
    }
}

__device__ __forceinline__ void ldsm_x4(unsigned* r, const void* p) {
    unsigned addr = (unsigned)__cvta_generic_to_shared(p);
    asm volatile("ldmatrix.sync.aligned.m8n8.x4.shared.b16 {%0,%1,%2,%3}, [%4];\n"
                 : "=r"(r[0]), "=r"(r[1]), "=r"(r[2]), "=r"(r[3]) : "r"(addr));
}

__device__ __forceinline__ void mma_f16(float* d, const unsigned* a, const unsigned* b) {
    asm volatile(
        "mma.sync.aligned.m16n8k16.row.col.f32.f16.f16.f32 "
        "{%0,%1,%2,%3}, {%4,%5,%6,%7}, {%8,%9}, {%0,%1,%2,%3};\n"
        : "+f"(d[0]), "+f"(d[1]), "+f"(d[2]), "+f"(d[3])
        : "r"(a[0]), "r"(a[1]), "r"(a[2]), "r"(a[3]),
          "r"(b[0]), "r"(b[1]));
}

// ---------------------------------------------------------------------------
// Kernel 0: weight prep
// ---------------------------------------------------------------------------
#define N_W1T (NEXP * EHID * KPAD)
#define N_W2T (NEXP * EOUT * KPAD)
#define N_PT  (64 * 64)
#define N_W3  (64 * 64)
#define N_AW2 (16 * 64)
#define N_WB  (64 * 64)
#define N_PREP (N_W1T + N_W2T + N_PT + N_W3 + N_AW2 + N_WB)

__global__ void __launch_bounds__(256)
prep_weights(const float* __restrict__ eW1, const float* __restrict__ eW2,
             const float* __restrict__ aW1, const float* __restrict__ aW2,
             __half* __restrict__ W1t, __half* __restrict__ W2t,
             __half* __restrict__ Pt, __half* __restrict__ W3t,
             __half* __restrict__ aW2t, float* __restrict__ Wb)
{
    int i = blockIdx.x * 256 + threadIdx.x;
    if (i < N_W1T) {
        const int e = i >> 16, n = (i >> 8) & 255, k = i & 255;
        const float v = (k < CONCAT) ? eW1[((long)e * CONCAT + k) * EHID + n] : 0.f;
        W1t[i] = __float2half(v);
        return;
    }
    i -= N_W1T;
    if (i < N_W2T) {
        const int e = i >> 15, n = (i >> 8) & 127, k = i & 255;
        W2t[i] = __float2half(eW2[((long)e * EHID + k) * EOUT + n]);
        return;
    }
    i -= N_W2T;
    if (i < N_PT) {
        const int n = i >> 6, k = i & 63;
        Pt[i] = __float2half(aW1[(64 + k) * 64 + n] - aW1[(128 + k) * 64 + n]);
        return;
    }
    i -= N_PT;
    if (i < N_W3) {
        const int n = i >> 6, k = i & 63;
        W3t[i] = __float2half(aW1[(192 + k) * 64 + n]);
        return;
    }
    i -= N_W3;
    if (i < N_AW2) {
        const int n = i >> 6, k = i & 63;
        aW2t[i] = __float2half(aW2[k * 16 + n]);
        return;
    }
    i -= N_AW2;
    if (i < N_WB) {
        const int k = i >> 6, j = i & 63;
        Wb[i] = aW1[k * 64 + j] + aW1[(128 + k) * 64 + j];
    }
}

// ---------------------------------------------------------------------------
// Kernel 0c: convert histE to fp16
// ---------------------------------------------------------------------------
#define N_HIST2 ((long)NITEMS1 * 32)

__global__ void __launch_bounds__(256)
conv_hist(const float* __restrict__ histE, __half* __restrict__ h16)
{
    const long i = (long)blockIdx.x * 256 + threadIdx.x;
    if (i < N_HIST2) {
        const float2 v = reinterpret_cast<const float2*>(histE)[i];
        reinterpret_cast<__half2*>(h16)[i] = __floats2half2_rn(v.x, v.y);
    }
}

// ---------------------------------------------------------------------------
// Kernel 0b: per-row t = i_emb @ Wproj (fp16) and base = ab1 + t @ Wb
// ---------------------------------------------------------------------------
struct TBSmem {
    float Wp[64 * LLD];
    float Wbs[64 * LLD];
    float I[64 * LLD];
    float T[64 * LLD];
    int   ids[64];
};

__global__ void __launch_bounds__(256)
tbase_kernel(const int* __restrict__ iid, const float* __restrict__ itemE,
             const float* __restrict__ Wproj, const float* __restrict__ Wb,
             const float* __restrict__ ab1,
             __half* __restrict__ t16, float* __restrict__ base)
{
    extern __shared__ unsigned char smem_raw[];
    TBSmem& s = *reinterpret_cast<TBSmem*>(smem_raw);
    const int tid = threadIdx.x;
    const int b0 = blockIdx.x * 64;

    if (tid < 64) s.ids[tid] = iid[b0 + tid];
    #pragma unroll
    for (int h = 0; h < 4; h++) {
        const int idx = tid + h * 256;
        const int k = idx >> 4, f = (idx & 15) * 4;
        cp_async16(&s.Wp[k * LLD + f],  Wproj + k * 64 + f);
        cp_async16(&s.Wbs[k * LLD + f], Wb    + k * 64 + f);
    }
    cp_commit();
    __syncthreads();
    #pragma unroll
    for (int h = 0; h < 4; h++) {
        const int idx = tid + h * 256;
        const int r = idx >> 4, f = (idx & 15) * 4;
        cp_async16(&s.I[r * LLD + f], itemE + (long)s.ids[r] * 64 + f);
    }
    cp_commit();
    cp_wait<0>();
    __syncthreads();

    const int r = tid >> 2;
    const int jg = (tid & 3) * 16;
    {
        float acc[16];
        #pragma unroll
        for (int j = 0; j < 16; j++) acc[j] = 0.f;
        #pragma unroll 4
        for (int k = 0; k < 64; k++) {
            const float ik = s.I[r * LLD + k];
            #pragma unroll
            for (int j = 0; j < 16; j++) acc[j] += ik * s.Wp[k * LLD + jg + j];
        }
        #pragma unroll
        for (int j = 0; j < 16; j++) {
            s.T[r * LLD + jg + j] = acc[j];
            t16[(long)(b0 + r) * 64 + jg + j] = __float2half(acc[j]);
        }
    }
    __syncthreads();
    {
        float acc[16];
        #pragma unroll
        for (int j = 0; j < 16; j++) acc[j] = ab1[jg + j];
        #pragma unroll 4
        for (int k = 0; k < 64; k++) {
            const float tk = s.T[r * LLD + k];
            #pragma unroll
            for (int j = 0; j < 16; j++) acc[j] += tk * s.Wbs[k * LLD + jg + j];
        }
        #pragma unroll
        for (int j = 0; j < 16; j++)
            base[(long)(b0 + r) * 64 + jg + j] = acc[j];
    }
}

// ---------------------------------------------------------------------------
// Kernel 1: DIN attention — fused M, phase-paired chunks (2 chunks/barrier),
// layer2 on 4 warps. ~55 KB smem, 4 blocks/SM.
// ---------------------------------------------------------------------------
struct AttnSmem {
    __half h[SEQPAD * HLD2];       // resident history (32.3 KB)
    __half h1[2][CH * HLD2];       // layer1 out (both chunks of phase) (9.2 KB)
    __half Mt[64 * HLD2];          // fused M^T [n][k] (9.2 KB)
    __half aW2t[16 * HLD2];        // (2.3 KB)
    __half2 t2s[32];
    float base[64];
    float sc[SEQPAD];
    float aW3s[16];
    float ab2s[16];
    float red[8];
    float denom;
    int   seqs[SEQPAD];
};

__global__ void __launch_bounds__(256, 4)
attn_kernel(const int* __restrict__ uid, const int* __restrict__ iid,
            const int* __restrict__ cid, const int* __restrict__ did,
            const float* __restrict__ udense, const float* __restrict__ idense,
            const int* __restrict__ hseq,
            const float* __restrict__ userE, const float* __restrict__ itemE,
            const float* __restrict__ catE,  const float* __restrict__ durE,
            const __half* __restrict__ hist16,
            const __half* __restrict__ t16, const float* __restrict__ baseg,
            const __half* __restrict__ Ptg, const __half* __restrict__ W3tg,
            const __half* __restrict__ aW2tg,
            const float* __restrict__ aW3, const float* __restrict__ ab3,
            const float* __restrict__ ab2,
            float* __restrict__ Sout, __half* __restrict__ Shout)
{
    extern __shared__ unsigned char smem_raw[];
    AttnSmem& s = *reinterpret_cast<AttnSmem*>(smem_raw);

    const int b    = blockIdx.x;
    const int tid  = threadIdx.x;
    const int lane = tid & 31;
    const int warp = tid >> 5;
    const int qr   = lane >> 2;
    const int qc   = lane & 3;

    // ---- group 0: stage aW2t ----
    if (tid < 128) {
        const int n = tid >> 3, k8 = (tid & 7) * 8;
        cp_async16(&s.aW2t[n * HLD2 + k8], aW2tg + n * 64 + k8);
    }
    cp_commit();

    // ---- per-row constants + sequence ids ----
    if (tid < 32)
        s.t2s[tid] = reinterpret_cast<const __half2*>(t16 + (long)b * 64)[tid];
    if (tid < 64) s.base[tid] = baseg[(long)b * 64 + tid];
    if (tid < 16) { s.aW3s[tid] = aW3[tid]; s.ab2s[tid] = ab2[tid]; }
    if (tid < SEQPAD) s.seqs[tid] = (tid < LSEQ) ? hseq[(long)b * LSEQ + tid] : 0;
    __syncthreads();

    // ---- groups 1..7: all chunk gathers ----
    #pragma unroll
    for (int ch = 0; ch < NCH; ch++) {
        const int r = tid >> 3;
        const int f8 = (tid & 7) * 8;
        const int sid = s.seqs[ch * CH + r];
        cp_async16(&s.h[(ch * CH + r) * HLD2 + f8], hist16 + (long)sid * 64 + f8);
        cp_commit();
    }

    // ---- build fused M^T[n][k] = Pt + t[k]*W3t ----
    for (int i = tid; i < 64 * 32; i += 256) {
        const int n = i >> 5, k2 = i & 31;
        const __half2 p = *reinterpret_cast<const __half2*>(Ptg  + n * 64 + 2 * k2);
        const __half2 w = *reinterpret_cast<const __half2*>(W3tg + n * 64 + 2 * k2);
        *reinterpret_cast<__half2*>(&s.Mt[n * HLD2 + 2 * k2]) = __hfma2(s.t2s[k2], w, p);
    }
    __syncthreads();

    // ---- hoist M fragments for this warp's n16 ----
    const int wm = warp & 1;
    const int wn = warp >> 1;
    unsigned bM[4][2][2];
    #pragma unroll
    for (int ks = 0; ks < 4; ks++)
        #pragma unroll
        for (int ni = 0; ni < 2; ni++) {
            const __half* bp = &s.Mt[(wn * 16 + ni * 8 + qr) * HLD2 + ks * 16 + 2 * qc];
            bM[ks][ni][0] = *reinterpret_cast<const unsigned*>(bp);
            bM[ks][ni][1] = *reinterpret_cast<const unsigned*>(bp + 8);
        }

    const float ab3v = ab3[0];
    const int lrow = (lane & 7) + ((lane >> 3) & 1) * 8;
    const int lkof = (lane >> 4) * 8;

    // ---- phase loop: 2 chunks per barrier pair ----
    #pragma unroll
    for (int p = 0; p < 4; p++) {
        const int c0v = 2 * p;
        const bool has2 = (p < 3);                  // chunk c0v+1 exists
        cp_wait_n(has2 ? (NCH - 2 - c0v) : 0);
        __syncthreads();

        // layer 1 for both chunks of the phase
        {
            const int n8 = wn * 16;
            #pragma unroll
            for (int j = 0; j < 2; j++) {
                if (j == 1 && !has2) break;
                const int cc = c0v + j;
                float acc[2][4];
                #pragma unroll
                for (int ni = 0; ni < 2; ni++) {
                    const int nn = n8 + ni * 8;
                    acc[ni][0] = s.base[nn + 2 * qc];
                    acc[ni][1] = s.base[nn + 2 * qc + 1];
                    acc[ni][2] = acc[ni][0];
                    acc[ni][3] = acc[ni][1];
                }
                const int rowb = cc * CH + wm * 16;
                #pragma unroll
                for (int ks = 0; ks < 4; ks++) {
                    unsigned a[4];
                    ldsm_x4(a, &s.h[(rowb + lrow) * HLD2 + ks * 16 + lkof]);
                    mma_f16(acc[0], a, bM[ks][0]);
                    mma_f16(acc[1], a, bM[ks][1]);
                }
                __half* h1b = s.h1[j];
                const int rr = wm * 16 + qr;
                #pragma unroll
                for (int ni = 0; ni < 2; ni++) {
                    const int nn = n8 + ni * 8;
                    *reinterpret_cast<__half2*>(&h1b[rr * HLD2 + nn + 2 * qc]) =
                        __floats2half2_rn(fmaxf(acc[ni][0], 0.f), fmaxf(acc[ni][1], 0.f));
                    *reinterpret_cast<__half2*>(&h1b[(rr + 8) * HLD2 + nn + 2 * qc]) =
                        __floats2half2_rn(fmaxf(acc[ni][2], 0.f), fmaxf(acc[ni][3], 0.f));
                }
            }
        }
        __syncthreads();

        // layer 2 + 3: 4 warps (2 per chunk); last phase only 2 warps
        const int nlw = has2 ? 4 : 2;
        if (warp < nlw) {
            const int j  = warp >> 1;               // chunk of the pair
            const int cc = c0v + j;
            const int wr16 = (warp & 1) * 16;
            const __half* h1b = s.h1[j];
            float acc2[2][4];
            #pragma unroll
            for (int ni = 0; ni < 2; ni++) {
                acc2[ni][0] = s.ab2s[ni * 8 + 2 * qc];
                acc2[ni][1] = s.ab2s[ni * 8 + 2 * qc + 1];
                acc2[ni][2] = acc2[ni][0];
                acc2[ni][3] = acc2[ni][1];
            }
            #pragma unroll
            for (int ks = 0; ks < 4; ks++) {
                unsigned a[4];
                ldsm_x4(a, &h1b[(wr16 + lrow) * HLD2 + ks * 16 + lkof]);
                #pragma unroll
                for (int ni = 0; ni < 2; ni++) {
                    unsigned bv[2];
                    const __half* bp = &s.aW2t[(ni * 8 + qr) * HLD2 + ks * 16 + 2 * qc];
                    bv[0] = *reinterpret_cast<const unsigned*>(bp);
                    bv[1] = *reinterpret_cast<const unsigned*>(bp + 8);
                    mma_f16(acc2[ni], a, bv);
                }
            }
            float w0 = 0.f, w1 = 0.f;
            #pragma unroll
            for (int ni = 0; ni < 2; ni++) {
                const float g0 = s.aW3s[ni * 8 + 2 * qc];
                const float g1 = s.aW3s[ni * 8 + 2 * qc + 1];
                w0 += fmaxf(acc2[ni][0], 0.f) * g0 + fmaxf(acc2[ni][1], 0.f) * g1;
                w1 += fmaxf(acc2[ni][2], 0.f) * g0 + fmaxf(acc2[ni][3], 0.f) * g1;
            }
            w0 += __shfl_xor_sync(0xffffffffu, w0, 1);
            w0 += __shfl_xor_sync(0xffffffffu, w0, 2);
            w1 += __shfl_xor_sync(0xffffffffu, w1, 1);
            w1 += __shfl_xor_sync(0xffffffffu, w1, 2);
            if (qc == 0) {
                const int l0 = cc * CH + wr16 + qr;
                const int l1 = l0 + 8;
                float e0 = 0.f, e1 = 0.f;
                if (l0 < LSEQ && s.seqs[l0] != 0) e0 = __expf(w0 + ab3v);
                if (l1 < LSEQ && s.seqs[l1] != 0) e1 = __expf(w1 + ab3v);
                s.sc[l0] = e0;
                s.sc[l1] = e1;
            }
        }
        __syncthreads();   // h1 protected before next phase overwrites
    }

    // ---- denom = sum sc ----
    {
        float sv = (tid < SEQPAD) ? s.sc[tid] : 0.f;
        #pragma unroll
        for (int off = 16; off >= 1; off >>= 1)
            sv += __shfl_xor_sync(0xffffffffu, sv, off);
        if (lane == 0) s.red[warp] = sv;
    }
    __syncthreads();
    if (tid == 0) {
        float ss = 0.f;
        #pragma unroll
        for (int w = 0; w < 8; w++) ss += s.red[w];
        s.denom = 1.f / ss;
    }

    // ---- pooling over resident h; scratch aliased onto dead h1 ----
    float* part8   = reinterpret_cast<float*>(s.h1);
    float* poolred = part8 + 8 * 64;
    {
        const int g = warp;
        const int d2 = lane;
        float ax = 0.f, ay = 0.f;
        #pragma unroll 7
        for (int i = 0; i < 28; i++) {
            const int l = g * 28 + i;
            const float w = s.sc[l];
            const __half2 hv = *reinterpret_cast<const __half2*>(&s.h[l * HLD2 + 2 * d2]);
            ax += w * __low2float(hv);
            ay += w * __high2float(hv);
        }
        part8[g * 64 + 2 * d2]     = ax;
        part8[g * 64 + 2 * d2 + 1] = ay;
    }
    __syncthreads();
    if (tid < 64) {
        float acc = 0.f;
        #pragma unroll
        for (int g = 0; g < 8; g++) acc += part8[g * 64 + tid];
        poolred[tid] = acc * s.denom;
    }
    __syncthreads();

    // ---- write feature row (fp32 + fp16 padded) ----
    {
        const int item = iid[b];
        float v = 0.f;
        if (tid < CONCAT) {
            if      (tid < 64)  v = userE[(long)uid[b] * 64 + tid];
            else if (tid < 128) v = itemE[(long)item * 64 + (tid - 64)];
            else if (tid < 144) v = catE[(long)cid[b] * 16 + (tid - 128)];
            else if (tid < 152) v = durE[(long)did[b] * 8 + (tid - 144)];
            else if (tid < 177) v = udense[(long)b * 25 + (tid - 152)];
            else if (tid < 180) v = idense[(long)b * 3 + (tid - 177)];
            else                v = poolred[tid - 180];
            Sout[(long)b * CONCAT + tid] = v;
        }
        Shout[(long)b * KPAD + tid] = __float2half(v);
    }
}

// ---------------------------------------------------------------------------
// Kernel 2: batched fp16 GEMM + bias + ReLU (unchanged, passing)
// ---------------------------------------------------------------------------
#define TBM 128
#define TBN 128
#define TBK 16
#define NSTG 4
#define HLG 24

#define HGEMM_SMEM ((NSTG * TBM * HLG + NSTG * TBN * HLG) * 2)

template <bool OUT_HALF>
__global__ void __launch_bounds__(256, 2)
hgemm_bias_relu(const __half* __restrict__ A, const __half* __restrict__ Bt,
                const float* __restrict__ bias, void* __restrict__ Cout,
                int M, int N,
                size_t sA, size_t sB, size_t sBias, size_t sC)
{
    extern __shared__ __half smemh[];
    __half* As = smemh;
    __half* Bs = smemh + NSTG * TBM * HLG;

    const int z = blockIdx.z;
    A += (size_t)z * sA; Bt += (size_t)z * sB;
    bias += (size_t)z * sBias;

    const int m0 = blockIdx.y * TBM;
    const int n0 = blockIdx.x * TBN;
    const int tid = threadIdx.x;
    const int lane = tid & 31;
    const int warp = tid >> 5;
    const int wr = warp >> 2;
    const int wc = warp & 3;
    const int qr = lane >> 2;
    const int qc = lane & 3;

    const int nk = KPAD / TBK;

    const int l_row = tid >> 1;
    const int l_hc  = (tid & 1) * 8;

    auto load_stage = [&](int st, int k0) {
        __half* as = As + st * TBM * HLG;
        __half* bs = Bs + st * TBN * HLG;
        cp_async16(&as[l_row * HLG + l_hc], A  + (size_t)(m0 + l_row) * KPAD + k0 + l_hc);
        cp_async16(&bs[l_row * HLG + l_hc], Bt + (size_t)(n0 + l_row) * KPAD + k0 + l_hc);
    };

    float acc[4][4][4];
    #pragma unroll
    for (int i = 0; i < 4; i++)
        #pragma unroll
        for (int j = 0; j < 4; j++)
            #pragma unroll
            for (int e = 0; e < 4; e++) acc[i][j][e] = 0.f;

    #pragma unroll
    for (int s0 = 0; s0 < NSTG - 1; s0++) {
        load_stage(s0, s0 * TBK);
        cp_commit();
    }

    for (int kt = 0; kt < nk; kt++) {
        cp_wait<NSTG - 2>();
        __syncthreads();

        const int knext = kt + NSTG - 1;
        if (knext < nk) load_stage(knext % NSTG, knext * TBK);
        cp_commit();

        const __half* as = As + (kt % NSTG) * TBM * HLG;
        const __half* bs = Bs + (kt % NSTG) * TBN * HLG;

        unsigned a[4][4], bfr[4][2];
        #pragma unroll
        for (int mi = 0; mi < 4; mi++) {
            const int r = wr * 64 + mi * 16 + qr;
            a[mi][0] = *reinterpret_cast<const unsigned*>(as + r * HLG + 2 * qc);
            a[mi][1] = *reinterpret_cast<const unsigned*>(as + (r + 8) * HLG + 2 * qc);
            a[mi][2] = *reinterpret_cast<const unsigned*>(as + r * HLG + 2 * qc + 8);
            a[mi][3] = *reinterpret_cast<const unsigned*>(as + (r + 8) * HLG + 2 * qc + 8);
        }
        #pragma unroll
        for (int ni = 0; ni < 4; ni++) {
            const int n = wc * 32 + ni * 8 + qr;
            bfr[ni][0] = *reinterpret_cast<const unsigned*>(bs + n * HLG + 2 * qc);
            bfr[ni][1] = *reinterpret_cast<const unsigned*>(bs + n * HLG + 2 * qc + 8);
        }
        #pragma unroll
        for (int mi = 0; mi < 4; mi++)
            #pragma unroll
            for (int ni = 0; ni < 4; ni++)
                mma_f16(acc[mi][ni], a[mi], bfr[ni]);

        __syncthreads();
    }

    #pragma unroll
    for (int mi = 0; mi < 4; mi++) {
        #pragma unroll
        for (int ni = 0; ni < 4; ni++) {
            const int gm = m0 + wr * 64 + mi * 16 + qr;
            const int gn = n0 + wc * 32 + ni * 8 + qc * 2;
            const float b0 = bias[gn], b1 = bias[gn + 1];
            const float v0 = fmaxf(acc[mi][ni][0] + b0, 0.f);
            const float v1 = fmaxf(acc[mi][ni][1] + b1, 0.f);
            const float v2 = fmaxf(acc[mi][ni][2] + b0, 0.f);
            const float v3 = fmaxf(acc[mi][ni][3] + b1, 0.f);
            if (OUT_HALF) {
                __half* C = (__half*)Cout + (size_t)z * sC;
                *reinterpret_cast<__half2*>(C + (size_t)gm * N + gn) =
                    __floats2half2_rn(v0, v1);
                *reinterpret_cast<__half2*>(C + (size_t)(gm + 8) * N + gn) =
                    __floats2half2_rn(v2, v3);
            } else {
                float* C = (float*)Cout + (size_t)z * sC;
                *reinterpret_cast<float2*>(C + (size_t)gm * N + gn) = make_float2(v0, v1);
                *reinterpret_cast<float2*>(C + (size_t)(gm + 8) * N + gn) = make_float2(v2, v3);
            }
        }
    }
}

// ---------------------------------------------------------------------------
// Kernel 3: gates + mix + towers + sigmoid — 4-way ILP accumulators
// ---------------------------------------------------------------------------
__global__ void __launch_bounds__(256)
head_kernel(const float* __restrict__ S, const float* __restrict__ eo,
            const float* __restrict__ gW, const float* __restrict__ gb,
            const float* __restrict__ tW1, const float* __restrict__ tb1,
            const float* __restrict__ tW2, const float* __restrict__ tb2,
            const float* __restrict__ tW3, const float* __restrict__ tb3,
            float* __restrict__ out)
{
    __shared__ float Srow[4][CONCAT];
    __shared__ float gate[4][16];
    __shared__ float ti[4][NTASK][EOUT];
    __shared__ float x1[4][NTASK][64];
    __shared__ float x2[4][NTASK][32];

    const int g = threadIdx.x >> 6;
    const int lane = threadIdx.x & 63;
    const int b = blockIdx.x * 4 + g;

    for (int c = lane; c < CONCAT; c += 64) Srow[g][c] = S[(long)b * CONCAT + c];
    __syncthreads();

    {
        const int o = lane >> 2;
        const int q = lane & 3;
        const int t = o >> 3, e = o & 7;
        const int c0 = q * 61;
        float a0 = 0.f, a1 = 0.f, a2 = 0.f, a3 = 0.f;
        #pragma unroll
        for (int i = 0; i < 60; i += 4) {
            a0 += Srow[g][c0 + i]     * __ldg(&gW[((long)t * CONCAT + c0 + i)     * 8 + e]);
            a1 += Srow[g][c0 + i + 1] * __ldg(&gW[((long)t * CONCAT + c0 + i + 1) * 8 + e]);
            a2 += Srow[g][c0 + i + 2] * __ldg(&gW[((long)t * CONCAT + c0 + i + 2) * 8 + e]);
            a3 += Srow[g][c0 + i + 3] * __ldg(&gW[((long)t * CONCAT + c0 + i + 3) * 8 + e]);
        }
        a0 += Srow[g][c0 + 60] * __ldg(&gW[((long)t * CONCAT + c0 + 60) * 8 + e]);
        float acc = (a0 + a1) + (a2 + a3);
        acc += __shfl_xor_sync(0xffffffffu, acc, 1);
        acc += __shfl_xor_sync(0xffffffffu, acc, 2);
        if (q == 0) gate[g][o] = acc + gb[t * 8 + e];
    }
    __syncthreads();
    if (lane < 2) {
        const int t = lane;
        float mx = -3.4e38f;
        for (int e = 0; e < 8; e++) mx = fmaxf(mx, gate[g][t * 8 + e]);
        float sum = 0.f, ex[8];
        for (int e = 0; e < 8; e++) { ex[e] = __expf(gate[g][t * 8 + e] - mx); sum += ex[e]; }
        const float is = 1.f / sum;
        for (int e = 0; e < 8; e++) gate[g][t * 8 + e] = ex[e] * is;
    }
    __syncthreads();

    {
        const int t = lane >> 5;
        const int o = (lane & 31) * 4;
        float4 acc = make_float4(0.f, 0.f, 0.f, 0.f);
        #pragma unroll
        for (int e = 0; e < 8; e++) {
            const float gv = gate[g][t * 8 + e];
            const float4 v = *reinterpret_cast<const float4*>(
                eo + ((long)e * BATCH + b) * EOUT + o);
            acc.x += gv * v.x; acc.y += gv * v.y;
            acc.z += gv * v.z; acc.w += gv * v.w;
        }
        *reinterpret_cast<float4*>(&ti[g][t][o]) = acc;
    }
    __syncthreads();

    for (int idx = lane; idx < NTASK * 64; idx += 64) {
        const int t = idx >> 6, j = idx & 63;
        float a0 = tb1[t * 64 + j], a1 = 0.f, a2 = 0.f, a3 = 0.f;
        #pragma unroll
        for (int o = 0; o < 128; o += 4) {
            a0 += ti[g][t][o]     * __ldg(&tW1[((long)t * 128 + o)     * 64 + j]);
            a1 += ti[g][t][o + 1] * __ldg(&tW1[((long)t * 128 + o + 1) * 64 + j]);
            a2 += ti[g][t][o + 2] * __ldg(&tW1[((long)t * 128 + o + 2) * 64 + j]);
            a3 += ti[g][t][o + 3] * __ldg(&tW1[((long)t * 128 + o + 3) * 64 + j]);
        }
        x1[g][t][j] = fmaxf((a0 + a1) + (a2 + a3), 0.f);
    }
    __syncthreads();

    {
        const int t = lane >> 5, m = lane & 31;
        float a0 = tb2[t * 32 + m], a1 = 0.f, a2 = 0.f, a3 = 0.f;
        #pragma unroll
        for (int j = 0; j < 64; j += 4) {
            a0 += x1[g][t][j]     * __ldg(&tW2[(t * 64 + j)     * 32 + m]);
            a1 += x1[g][t][j + 1] * __ldg(&tW2[(t * 64 + j + 1) * 32 + m]);
            a2 += x1[g][t][j + 2] * __ldg(&tW2[(t * 64 + j + 2) * 32 + m]);
            a3 += x1[g][t][j + 3] * __ldg(&tW2[(t * 64 + j + 3) * 32 + m]);
        }
        x2[g][t][m] = fmaxf((a0 + a1) + (a2 + a3), 0.f);
    }
    __syncthreads();

    if (lane < 2) {
        const int t = lane;
        float a0 = tb3[t], a1 = 0.f, a2 = 0.f, a3 = 0.f;
        #pragma unroll
        for (int m = 0; m < 32; m += 4) {
            a0 += x2[g][t][m]     * tW3[t * 32 + m];
            a1 += x2[g][t][m + 1] * tW3[t * 32 + m + 1];
            a2 += x2[g][t][m + 2] * tW3[t * 32 + m + 2];
            a3 += x2[g][t][m + 3] * tW3[t * 32 + m + 3];
        }
        const float acc = (a0 + a1) + (a2 + a3);
        out[(long)t * BATCH + b] = 1.f / (1.f + __expf(-acc));
    }
}

// ---------------------------------------------------------------------------
// Launch
// ---------------------------------------------------------------------------
extern "C" void kernel_launch(void* const* d_in, const int* in_sizes, int n_in,
                              void* d_out, int out_size)
{
    const int*   uid    = (const int*)  d_in[0];
    const int*   iid    = (const int*)  d_in[1];
    const int*   cid    = (const int*)  d_in[2];
    const int*   did    = (const int*)  d_in[3];
    const float* udense = (const float*)d_in[4];
    const float* idense = (const float*)d_in[5];
    const int*   hseq   = (const int*)  d_in[6];
    const float* userE  = (const float*)d_in[7];
    const float* itemE  = (const float*)d_in[8];
    const float* catE   = (const float*)d_in[9];
    const float* durE   = (const float*)d_in[10];
    const float* histE  = (const float*)d_in[11];
    const float* Wproj  = (const float*)d_in[12];
    const float* aW1    = (const float*)d_in[13];
    const float* ab1    = (const float*)d_in[14];
    const float* aW2    = (const float*)d_in[15];
    const float* ab2    = (const float*)d_in[16];
    const float* aW3    = (const float*)d_in[17];
    const float* ab3    = (const float*)d_in[18];
    const float* eW1    = (const float*)d_in[19];
    const float* eb1    = (const float*)d_in[20];
    const float* eW2    = (const float*)d_in[21];
    const float* eb2    = (const float*)d_in[22];
    const float* gW     = (const float*)d_in[23];
    const float* gb     = (const float*)d_in[24];
    const float* tW1    = (const float*)d_in[25];
    const float* tb1    = (const float*)d_in[26];
    const float* tW2    = (const float*)d_in[27];
    const float* tb2    = (const float*)d_in[28];
    const float* tW3    = (const float*)d_in[29];
    const float* tb3    = (const float*)d_in[30];
    float* out = (float*)d_out;

    float  *pS, *pEo, *pBase, *pWb;
    __half *pSh, *pEh, *pW1t, *pW2t, *pT16, *pPt, *pW3t, *pAW2t, *pH16;
    cudaGetSymbolAddress((void**)&pS,    g_S);
    cudaGetSymbolAddress((void**)&pSh,   g_Sh);
    cudaGetSymbolAddress((void**)&pEh,   g_ehh);
    cudaGetSymbolAddress((void**)&pEo,   g_eo);
    cudaGetSymbolAddress((void**)&pW1t,  g_W1t);
    cudaGetSymbolAddress((void**)&pW2t,  g_W2t);
    cudaGetSymbolAddress((void**)&pT16,  g_t16);
    cudaGetSymbolAddress((void**)&pBase, g_base);
    cudaGetSymbolAddress((void**)&pPt,   g_Pt);
    cudaGetSymbolAddress((void**)&pW3t,  g_W3t);
    cudaGetSymbolAddress((void**)&pAW2t, g_aW2t);
    cudaGetSymbolAddress((void**)&pWb,   g_Wb);
    cudaGetSymbolAddress((void**)&pH16,  g_hist16);

    const int attn_smem = (int)sizeof(AttnSmem);
    const int tb_smem   = (int)sizeof(TBSmem);
    cudaFuncSetAttribute(attn_kernel,  cudaFuncAttributeMaxDynamicSharedMemorySize, attn_smem);
    cudaFuncSetAttribute(tbase_kernel, cudaFuncAttributeMaxDynamicSharedMemorySize, tb_smem);
    cudaFuncSetAttribute(hgemm_bias_relu<true>,  cudaFuncAttributeMaxDynamicSharedMemorySize, HGEMM_SMEM);
    cudaFuncSetAttribute(hgemm_bias_relu<false>, cudaFuncAttributeMaxDynamicSharedMemorySize, HGEMM_SMEM);

    // K0: weight prep + history fp16 conversion + per-row t/base
    prep_weights<<<(N_PREP + 255) / 256, 256>>>(
        eW1, eW2, aW1, aW2, pW1t, pW2t, pPt, pW3t, pAW2t, pWb);
    conv_hist<<<(int)((N_HIST2 + 255) / 256), 256>>>(histE, pH16);
    tbase_kernel<<<BATCH / 64, 256, tb_smem>>>(
        iid, itemE, Wproj, pWb, ab1, pT16, pBase);

    // K1: attention + feature concat
    attn_kernel<<<BATCH, 256, attn_smem>>>(
        uid, iid, cid, did, udense, idense, hseq,
        userE, itemE, catE, durE, pH16,
        pT16, pBase, pPt, pW3t, pAW2t, aW3, ab3, ab2, pS, pSh);

    // K2a: eh = relu(S @ eW1 + eb1)
    hgemm_bias_relu<true><<<dim3(EHID / TBN, BATCH / TBM, NEXP), 256, HGEMM_SMEM>>>(
        pSh, pW1t, eb1, pEh,
        BATCH, EHID,
        (size_t)0, (size_t)EHID * KPAD, (size_t)EHID, (size_t)BATCH * EHID);

    // K2b: eo = relu(eh @ eW2 + eb2)
    hgemm_bias_relu<false><<<dim3(EOUT / TBN, BATCH / TBM, NEXP), 256, HGEMM_SMEM>>>(
        pEh, pW2t, eb2, pEo,
        BATCH, EOUT,
        (size_t)BATCH * EHID, (size_t)EOUT * KPAD, (size_t)EOUT, (size_t)BATCH * EOUT);

    // K3: gates + mix + towers + sigmoid
    head_kernel<<<BATCH / 4, 256>>>(
        pS, pEo, gW, gb, tW1, tb1, tW2, tb2, tW3, tb3, out);
}

// round 16
// speedup vs baseline: 2.6900x; 1.0311x over previous
#include <cuda_runtime.h>
#include <cuda_fp16.h>
#include <math.h>

// ---------------------------------------------------------------------------
// Problem constants
// ---------------------------------------------------------------------------
#define BATCH   16384
#define LSEQ    200
#define CONCAT  244
#define KPAD    256
#define NEXP    8
#define EHID    256
#define EOUT    128
#define NTASK   2
#define NITEMS1 100001
#define CH      32
#define NCH     7
#define SEQPAD  224
#define HLD2    72
#define LLD     68

// ---------------------------------------------------------------------------
// Scratch (static device globals — no allocation allowed)
// ---------------------------------------------------------------------------
__device__ float  g_S   [(long)BATCH * CONCAT];
__device__ __half g_Sh  [(long)BATCH * KPAD];
__device__ __half g_ehh [(long)NEXP * BATCH * EHID];
__device__ __half g_eo  [(long)NEXP * BATCH * EOUT];     // fp16 now
__device__ __half g_W1t [(long)NEXP * EHID * KPAD];
__device__ __half g_W2t [(long)NEXP * EOUT * KPAD];
__device__ __half g_t16 [(long)BATCH * 64];
__device__ float  g_base[(long)BATCH * 64];
__device__ __half g_hist16[(long)NITEMS1 * 64];
__device__ __half g_Pt  [64 * 64];
__device__ __half g_W3t [64 * 64];
__device__ __half g_aW2t[16 * 64];
__device__ float  g_Wb  [64 * 64];

// ---------------------------------------------------------------------------
// cp.async / ldmatrix / mma helpers
// ---------------------------------------------------------------------------
__device__ __forceinline__ void cp_async16(void* smem_dst, const void* gsrc) {
    unsigned sm = (unsigned)__cvta_generic_to_shared(smem_dst);
    asm volatile("cp.async.cg.shared.global [%0], [%1], 16;\n" :: "r"(sm), "l"(gsrc));
}
__device__ __forceinline__ void cp_commit() {
    asm volatile("cp.async.commit_group;\n");
}
template <int N>
__device__ __forceinline__ void cp_wait() {
    asm volatile("cp.async.wait_group %0;\n" :: "n"(N));
}
__device__ __forceinline__ void cp_wait_n(int n) {
    switch (n) {
        case 0: cp_wait<0>(); break;
        case 1: cp_wait<1>(); break;
        case 2: cp_wait<2>(); break;
        case 3: cp_wait<3>(); break;
        case 4: cp_wait<4>(); break;
        case 5: cp_wait<5>(); break;
        case 6: cp_wait<6>(); break;
        default: cp_wait<7>(); break;
    }
}

__device__ __forceinline__ void ldsm_x4(unsigned* r, const void* p) {
    unsigned addr = (unsigned)__cvta_generic_to_shared(p);
    asm volatile("ldmatrix.sync.aligned.m8n8.x4.shared.b16 {%0,%1,%2,%3}, [%4];\n"
                 : "=r"(r[0]), "=r"(r[1]), "=r"(r[2]), "=r"(r[3]) : "r"(addr));
}

__device__ __forceinline__ void mma_f16(float* d, const unsigned* a, const unsigned* b) {
    asm volatile(
        "mma.sync.aligned.m16n8k16.row.col.f32.f16.f16.f32 "
        "{%0,%1,%2,%3}, {%4,%5,%6,%7}, {%8,%9}, {%0,%1,%2,%3};\n"
        : "+f"(d[0]), "+f"(d[1]), "+f"(d[2]), "+f"(d[3])
        : "r"(a[0]), "r"(a[1]), "r"(a[2]), "r"(a[3]),
          "r"(b[0]), "r"(b[1]));
}

// ---------------------------------------------------------------------------
// Kernel 0: weight prep
// ---------------------------------------------------------------------------
#define N_W1T (NEXP * EHID * KPAD)
#define N_W2T (NEXP * EOUT * KPAD)
#define N_PT  (64 * 64)
#define N_W3  (64 * 64)
#define N_AW2 (16 * 64)
#define N_WB  (64 * 64)
#define N_PREP (N_W1T + N_W2T + N_PT + N_W3 + N_AW2 + N_WB)

__global__ void __launch_bounds__(256)
prep_weights(const float* __restrict__ eW1, const float* __restrict__ eW2,
             const float* __restrict__ aW1, const float* __restrict__ aW2,
             __half* __restrict__ W1t, __half* __restrict__ W2t,
             __half* __restrict__ Pt, __half* __restrict__ W3t,
             __half* __restrict__ aW2t, float* __restrict__ Wb)
{
    int i = blockIdx.x * 256 + threadIdx.x;
    if (i < N_W1T) {
        const int e = i >> 16, n = (i >> 8) & 255, k = i & 255;
        const float v = (k < CONCAT) ? eW1[((long)e * CONCAT + k) * EHID + n] : 0.f;
        W1t[i] = __float2half(v);
        return;
    }
    i -= N_W1T;
    if (i < N_W2T) {
        const int e = i >> 15, n = (i >> 8) & 127, k = i & 255;
        W2t[i] = __float2half(eW2[((long)e * EHID + k) * EOUT + n]);
        return;
    }
    i -= N_W2T;
    if (i < N_PT) {
        const int n = i >> 6, k = i & 63;
        Pt[i] = __float2half(aW1[(64 + k) * 64 + n] - aW1[(128 + k) * 64 + n]);
        return;
    }
    i -= N_PT;
    if (i < N_W3) {
        const int n = i >> 6, k = i & 63;
        W3t[i] = __float2half(aW1[(192 + k) * 64 + n]);
        return;
    }
    i -= N_W3;
    if (i < N_AW2) {
        const int n = i >> 6, k = i & 63;
        aW2t[i] = __float2half(aW2[k * 16 + n]);
        return;
    }
    i -= N_AW2;
    if (i < N_WB) {
        const int k = i >> 6, j = i & 63;
        Wb[i] = aW1[k * 64 + j] + aW1[(128 + k) * 64 + j];
    }
}

// ---------------------------------------------------------------------------
// Kernel 0c: convert histE to fp16
// ---------------------------------------------------------------------------
#define N_HIST2 ((long)NITEMS1 * 32)

__global__ void __launch_bounds__(256)
conv_hist(const float* __restrict__ histE, __half* __restrict__ h16)
{
    const long i = (long)blockIdx.x * 256 + threadIdx.x;
    if (i < N_HIST2) {
        const float2 v = reinterpret_cast<const float2*>(histE)[i];
        reinterpret_cast<__half2*>(h16)[i] = __floats2half2_rn(v.x, v.y);
    }
}

// ---------------------------------------------------------------------------
// Kernel 0b: per-row t = i_emb @ Wproj (fp16) and base = ab1 + t @ Wb
// ---------------------------------------------------------------------------
struct TBSmem {
    float Wp[64 * LLD];
    float Wbs[64 * LLD];
    float I[64 * LLD];
    float T[64 * LLD];
    int   ids[64];
};

__global__ void __launch_bounds__(256)
tbase_kernel(const int* __restrict__ iid, const float* __restrict__ itemE,
             const float* __restrict__ Wproj, const float* __restrict__ Wb,
             const float* __restrict__ ab1,
             __half* __restrict__ t16, float* __restrict__ base)
{
    extern __shared__ unsigned char smem_raw[];
    TBSmem& s = *reinterpret_cast<TBSmem*>(smem_raw);
    const int tid = threadIdx.x;
    const int b0 = blockIdx.x * 64;

    if (tid < 64) s.ids[tid] = iid[b0 + tid];
    #pragma unroll
    for (int h = 0; h < 4; h++) {
        const int idx = tid + h * 256;
        const int k = idx >> 4, f = (idx & 15) * 4;
        cp_async16(&s.Wp[k * LLD + f],  Wproj + k * 64 + f);
        cp_async16(&s.Wbs[k * LLD + f], Wb    + k * 64 + f);
    }
    cp_commit();
    __syncthreads();
    #pragma unroll
    for (int h = 0; h < 4; h++) {
        const int idx = tid + h * 256;
        const int r = idx >> 4, f = (idx & 15) * 4;
        cp_async16(&s.I[r * LLD + f], itemE + (long)s.ids[r] * 64 + f);
    }
    cp_commit();
    cp_wait<0>();
    __syncthreads();

    const int r = tid >> 2;
    const int jg = (tid & 3) * 16;
    {
        float acc[16];
        #pragma unroll
        for (int j = 0; j < 16; j++) acc[j] = 0.f;
        #pragma unroll 4
        for (int k = 0; k < 64; k++) {
            const float ik = s.I[r * LLD + k];
            #pragma unroll
            for (int j = 0; j < 16; j++) acc[j] += ik * s.Wp[k * LLD + jg + j];
        }
        #pragma unroll
        for (int j = 0; j < 16; j++) {
            s.T[r * LLD + jg + j] = acc[j];
            t16[(long)(b0 + r) * 64 + jg + j] = __float2half(acc[j]);
        }
    }
    __syncthreads();
    {
        float acc[16];
        #pragma unroll
        for (int j = 0; j < 16; j++) acc[j] = ab1[jg + j];
        #pragma unroll 4
        for (int k = 0; k < 64; k++) {
            const float tk = s.T[r * LLD + k];
            #pragma unroll
            for (int j = 0; j < 16; j++) acc[j] += tk * s.Wbs[k * LLD + jg + j];
        }
        #pragma unroll
        for (int j = 0; j < 16; j++)
            base[(long)(b0 + r) * 64 + jg + j] = acc[j];
    }
}

// ---------------------------------------------------------------------------
// Kernel 1: DIN attention — fused M, phase-paired chunks, pooling overlapped
// onto warps 4-7 during layer-2. ~55 KB smem, 4 blocks/SM.
// ---------------------------------------------------------------------------
struct AttnSmem {
    __half h[SEQPAD * HLD2];
    __half h1[2][CH * HLD2];       // tail: aliased as float scratch
    __half Mt[64 * HLD2];
    __half aW2t[16 * HLD2];
    __half2 t2s[32];
    float base[64];
    float sc[SEQPAD];
    float aW3s[16];
    float ab2s[16];
    float red[8];
    float denom;
    int   seqs[SEQPAD];
};

__global__ void __launch_bounds__(256, 4)
attn_kernel(const int* __restrict__ uid, const int* __restrict__ iid,
            const int* __restrict__ cid, const int* __restrict__ did,
            const float* __restrict__ udense, const float* __restrict__ idense,
            const int* __restrict__ hseq,
            const float* __restrict__ userE, const float* __restrict__ itemE,
            const float* __restrict__ catE,  const float* __restrict__ durE,
            const __half* __restrict__ hist16,
            const __half* __restrict__ t16, const float* __restrict__ baseg,
            const __half* __restrict__ Ptg, const __half* __restrict__ W3tg,
            const __half* __restrict__ aW2tg,
            const float* __restrict__ aW3, const float* __restrict__ ab3,
            const float* __restrict__ ab2,
            float* __restrict__ Sout, __half* __restrict__ Shout)
{
    extern __shared__ unsigned char smem_raw[];
    AttnSmem& s = *reinterpret_cast<AttnSmem*>(smem_raw);

    const int b    = blockIdx.x;
    const int tid  = threadIdx.x;
    const int lane = tid & 31;
    const int warp = tid >> 5;
    const int qr   = lane >> 2;
    const int qc   = lane & 3;

    if (tid < 128) {
        const int n = tid >> 3, k8 = (tid & 7) * 8;
        cp_async16(&s.aW2t[n * HLD2 + k8], aW2tg + n * 64 + k8);
    }
    cp_commit();

    if (tid < 32)
        s.t2s[tid] = reinterpret_cast<const __half2*>(t16 + (long)b * 64)[tid];
    if (tid < 64) s.base[tid] = baseg[(long)b * 64 + tid];
    if (tid < 16) { s.aW3s[tid] = aW3[tid]; s.ab2s[tid] = ab2[tid]; }
    if (tid < SEQPAD) s.seqs[tid] = (tid < LSEQ) ? hseq[(long)b * LSEQ + tid] : 0;
    __syncthreads();

    #pragma unroll
    for (int ch = 0; ch < NCH; ch++) {
        const int r = tid >> 3;
        const int f8 = (tid & 7) * 8;
        const int sid = s.seqs[ch * CH + r];
        cp_async16(&s.h[(ch * CH + r) * HLD2 + f8], hist16 + (long)sid * 64 + f8);
        cp_commit();
    }

    for (int i = tid; i < 64 * 32; i += 256) {
        const int n = i >> 5, k2 = i & 31;
        const __half2 p = *reinterpret_cast<const __half2*>(Ptg  + n * 64 + 2 * k2);
        const __half2 w = *reinterpret_cast<const __half2*>(W3tg + n * 64 + 2 * k2);
        *reinterpret_cast<__half2*>(&s.Mt[n * HLD2 + 2 * k2]) = __hfma2(s.t2s[k2], w, p);
    }
    __syncthreads();

    const int wm = warp & 1;
    const int wn = warp >> 1;
    unsigned bM[4][2][2];
    #pragma unroll
    for (int ks = 0; ks < 4; ks++)
        #pragma unroll
        for (int ni = 0; ni < 2; ni++) {
            const __half* bp = &s.Mt[(wn * 16 + ni * 8 + qr) * HLD2 + ks * 16 + 2 * qc];
            bM[ks][ni][0] = *reinterpret_cast<const unsigned*>(bp);
            bM[ks][ni][1] = *reinterpret_cast<const unsigned*>(bp + 8);
        }

    const float ab3v = ab3[0];
    const int lrow = (lane & 7) + ((lane >> 3) & 1) * 8;
    const int lkof = (lane >> 4) * 8;

    // register pooling partials (warps 4-7; each warp owns half2 column lane)
    float pax = 0.f, pay = 0.f;

    #pragma unroll
    for (int p = 0; p < 4; p++) {
        const int c0v = 2 * p;
        const bool has2 = (p < 3);
        cp_wait_n(has2 ? (NCH - 2 - c0v) : 0);
        __syncthreads();

        // layer 1 for both chunks of the phase (all 8 warps)
        {
            const int n8 = wn * 16;
            #pragma unroll
            for (int j = 0; j < 2; j++) {
                if (j == 1 && !has2) break;
                const int cc = c0v + j;
                float acc[2][4];
                #pragma unroll
                for (int ni = 0; ni < 2; ni++) {
                    const int nn = n8 + ni * 8;
                    acc[ni][0] = s.base[nn + 2 * qc];
                    acc[ni][1] = s.base[nn + 2 * qc + 1];
                    acc[ni][2] = acc[ni][0];
                    acc[ni][3] = acc[ni][1];
                }
                const int rowb = cc * CH + wm * 16;
                #pragma unroll
                for (int ks = 0; ks < 4; ks++) {
                    unsigned a[4];
                    ldsm_x4(a, &s.h[(rowb + lrow) * HLD2 + ks * 16 + lkof]);
                    mma_f16(acc[0], a, bM[ks][0]);
                    mma_f16(acc[1], a, bM[ks][1]);
                }
                __half* h1b = s.h1[j];
                const int rr = wm * 16 + qr;
                #pragma unroll
                for (int ni = 0; ni < 2; ni++) {
                    const int nn = n8 + ni * 8;
                    *reinterpret_cast<__half2*>(&h1b[rr * HLD2 + nn + 2 * qc]) =
                        __floats2half2_rn(fmaxf(acc[ni][0], 0.f), fmaxf(acc[ni][1], 0.f));
                    *reinterpret_cast<__half2*>(&h1b[(rr + 8) * HLD2 + nn + 2 * qc]) =
                        __floats2half2_rn(fmaxf(acc[ni][2], 0.f), fmaxf(acc[ni][3], 0.f));
                }
            }
        }
        __syncthreads();

        // warps 0-3: layer 2+3 for this phase ; warps 4-7: pooling for p-1
        const int nlw = has2 ? 4 : 2;
        if (warp < nlw) {
            const int j  = warp >> 1;
            const int cc = c0v + j;
            const int wr16 = (warp & 1) * 16;
            const __half* h1b = s.h1[j];
            float acc2[2][4];
            #pragma unroll
            for (int ni = 0; ni < 2; ni++) {
                acc2[ni][0] = s.ab2s[ni * 8 + 2 * qc];
                acc2[ni][1] = s.ab2s[ni * 8 + 2 * qc + 1];
                acc2[ni][2] = acc2[ni][0];
                acc2[ni][3] = acc2[ni][1];
            }
            #pragma unroll
            for (int ks = 0; ks < 4; ks++) {
                unsigned a[4];
                ldsm_x4(a, &h1b[(wr16 + lrow) * HLD2 + ks * 16 + lkof]);
                #pragma unroll
                for (int ni = 0; ni < 2; ni++) {
                    unsigned bv[2];
                    const __half* bp = &s.aW2t[(ni * 8 + qr) * HLD2 + ks * 16 + 2 * qc];
                    bv[0] = *reinterpret_cast<const unsigned*>(bp);
                    bv[1] = *reinterpret_cast<const unsigned*>(bp + 8);
                    mma_f16(acc2[ni], a, bv);
                }
            }
            float w0 = 0.f, w1 = 0.f;
            #pragma unroll
            for (int ni = 0; ni < 2; ni++) {
                const float g0 = s.aW3s[ni * 8 + 2 * qc];
                const float g1 = s.aW3s[ni * 8 + 2 * qc + 1];
                w0 += fmaxf(acc2[ni][0], 0.f) * g0 + fmaxf(acc2[ni][1], 0.f) * g1;
                w1 += fmaxf(acc2[ni][2], 0.f) * g0 + fmaxf(acc2[ni][3], 0.f) * g1;
            }
            w0 += __shfl_xor_sync(0xffffffffu, w0, 1);
            w0 += __shfl_xor_sync(0xffffffffu, w0, 2);
            w1 += __shfl_xor_sync(0xffffffffu, w1, 1);
            w1 += __shfl_xor_sync(0xffffffffu, w1, 2);
            if (qc == 0) {
                const int l0 = cc * CH + wr16 + qr;
                const int l1 = l0 + 8;
                float e0 = 0.f, e1 = 0.f;
                if (l0 < LSEQ && s.seqs[l0] != 0) e0 = __expf(w0 + ab3v);
                if (l1 < LSEQ && s.seqs[l1] != 0) e1 = __expf(w1 + ab3v);
                s.sc[l0] = e0;
                s.sc[l1] = e1;
            }
        } else if (warp >= 4 && p > 0) {
            // pooling for previous phase's 64 rows; warp owns 16 of them
            const int rbase = (p - 1) * 64 + (warp - 4) * 16;
            #pragma unroll
            for (int i = 0; i < 16; i++) {
                const int l = rbase + i;
                const float w = s.sc[l];
                const __half2 hv = *reinterpret_cast<const __half2*>(&s.h[l * HLD2 + 2 * lane]);
                pax += w * __low2float(hv);
                pay += w * __high2float(hv);
            }
        }
        __syncthreads();
    }

    // ---- tail pooling: phase 3's chunk 6 (rows 192..223), warps 4-7 ----
    if (warp >= 4) {
        const int rbase = 192 + (warp - 4) * 8;
        #pragma unroll
        for (int i = 0; i < 8; i++) {
            const int l = rbase + i;
            const float w = s.sc[l];
            const __half2 hv = *reinterpret_cast<const __half2*>(&s.h[l * HLD2 + 2 * lane]);
            pax += w * __low2float(hv);
            pay += w * __high2float(hv);
        }
    }

    // ---- denom = sum sc ----
    {
        float sv = (tid < SEQPAD) ? s.sc[tid] : 0.f;
        #pragma unroll
        for (int off = 16; off >= 1; off >>= 1)
            sv += __shfl_xor_sync(0xffffffffu, sv, off);
        if (lane == 0) s.red[warp] = sv;
    }
    __syncthreads();
    if (tid == 0) {
        float ss = 0.f;
        #pragma unroll
        for (int w = 0; w < 8; w++) ss += s.red[w];
        s.denom = 1.f / ss;
    }

    // ---- combine pooling partials (scratch aliased onto dead h1) ----
    float* part4   = reinterpret_cast<float*>(s.h1);   // 4 x 64 floats
    float* poolred = part4 + 4 * 64;                   // 64 floats
    if (warp >= 4) {
        part4[(warp - 4) * 64 + 2 * lane]     = pax;
        part4[(warp - 4) * 64 + 2 * lane + 1] = pay;
    }
    __syncthreads();
    if (tid < 64) {
        float acc = 0.f;
        #pragma unroll
        for (int g = 0; g < 4; g++) acc += part4[g * 64 + tid];
        poolred[tid] = acc * s.denom;
    }
    __syncthreads();

    // ---- write feature row (fp32 + fp16 padded) ----
    {
        const int item = iid[b];
        float v = 0.f;
        if (tid < CONCAT) {
            if      (tid < 64)  v = userE[(long)uid[b] * 64 + tid];
            else if (tid < 128) v = itemE[(long)item * 64 + (tid - 64)];
            else if (tid < 144) v = catE[(long)cid[b] * 16 + (tid - 128)];
            else if (tid < 152) v = durE[(long)did[b] * 8 + (tid - 144)];
            else if (tid < 177) v = udense[(long)b * 25 + (tid - 152)];
            else if (tid < 180) v = idense[(long)b * 3 + (tid - 177)];
            else                v = poolred[tid - 180];
            Sout[(long)b * CONCAT + tid] = v;
        }
        Shout[(long)b * KPAD + tid] = __float2half(v);
    }
}

// ---------------------------------------------------------------------------
// Kernel 2: batched fp16 GEMM + bias + ReLU — ldmatrix operand loads
// ---------------------------------------------------------------------------
#define TBM 128
#define TBN 128
#define TBK 16
#define NSTG 4
#define HLG 24

#define HGEMM_SMEM ((NSTG * TBM * HLG + NSTG * TBN * HLG) * 2)

template <bool OUT_HALF>
__global__ void __launch_bounds__(256, 2)
hgemm_bias_relu(const __half* __restrict__ A, const __half* __restrict__ Bt,
                const float* __restrict__ bias, void* __restrict__ Cout,
                int M, int N,
                size_t sA, size_t sB, size_t sBias, size_t sC)
{
    extern __shared__ __half smemh[];
    __half* As = smemh;
    __half* Bs = smemh + NSTG * TBM * HLG;

    const int z = blockIdx.z;
    A += (size_t)z * sA; Bt += (size_t)z * sB;
    bias += (size_t)z * sBias;

    const int m0 = blockIdx.y * TBM;
    const int n0 = blockIdx.x * TBN;
    const int tid = threadIdx.x;
    const int lane = tid & 31;
    const int warp = tid >> 5;
    const int wr = warp >> 2;
    const int wc = warp & 3;
    const int qr = lane >> 2;
    const int qc = lane & 3;
    const int lrow = (lane & 7) + ((lane >> 3) & 1) * 8;
    const int lkof = (lane >> 4) * 8;

    const int nk = KPAD / TBK;

    const int l_row = tid >> 1;
    const int l_hc  = (tid & 1) * 8;

    auto load_stage = [&](int st, int k0) {
        __half* as = As + st * TBM * HLG;
        __half* bs = Bs + st * TBN * HLG;
        cp_async16(&as[l_row * HLG + l_hc], A  + (size_t)(m0 + l_row) * KPAD + k0 + l_hc);
        cp_async16(&bs[l_row * HLG + l_hc], Bt + (size_t)(n0 + l_row) * KPAD + k0 + l_hc);
    };

    float acc[4][4][4];
    #pragma unroll
    for (int i = 0; i < 4; i++)
        #pragma unroll
        for (int j = 0; j < 4; j++)
            #pragma unroll
            for (int e = 0; e < 4; e++) acc[i][j][e] = 0.f;

    #pragma unroll
    for (int s0 = 0; s0 < NSTG - 1; s0++) {
        load_stage(s0, s0 * TBK);
        cp_commit();
    }

    for (int kt = 0; kt < nk; kt++) {
        cp_wait<NSTG - 2>();
        __syncthreads();

        const int knext = kt + NSTG - 1;
        if (knext < nk) load_stage(knext % NSTG, knext * TBK);
        cp_commit();

        const __half* as = As + (kt % NSTG) * TBM * HLG;
        const __half* bs = Bs + (kt % NSTG) * TBN * HLG;

        unsigned a[4][4], bfr[4][2];
        #pragma unroll
        for (int mi = 0; mi < 4; mi++)
            ldsm_x4(a[mi], &as[(wr * 64 + mi * 16 + lrow) * HLG + lkof]);
        #pragma unroll
        for (int nj = 0; nj < 2; nj++) {
            unsigned t4[4];
            ldsm_x4(t4, &bs[(wc * 32 + nj * 16 + lrow) * HLG + lkof]);
            bfr[nj * 2][0]     = t4[0];
            bfr[nj * 2][1]     = t4[2];
            bfr[nj * 2 + 1][0] = t4[1];
            bfr[nj * 2 + 1][1] = t4[3];
        }
        #pragma unroll
        for (int mi = 0; mi < 4; mi++)
            #pragma unroll
            for (int ni = 0; ni < 4; ni++)
                mma_f16(acc[mi][ni], a[mi], bfr[ni]);

        __syncthreads();
    }

    #pragma unroll
    for (int mi = 0; mi < 4; mi++) {
        #pragma unroll
        for (int ni = 0; ni < 4; ni++) {
            const int gm = m0 + wr * 64 + mi * 16 + qr;
            const int gn = n0 + wc * 32 + ni * 8 + qc * 2;
            const float b0 = bias[gn], b1 = bias[gn + 1];
            const float v0 = fmaxf(acc[mi][ni][0] + b0, 0.f);
            const float v1 = fmaxf(acc[mi][ni][1] + b1, 0.f);
            const float v2 = fmaxf(acc[mi][ni][2] + b0, 0.f);
            const float v3 = fmaxf(acc[mi][ni][3] + b1, 0.f);
            if (OUT_HALF) {
                __half* C = (__half*)Cout + (size_t)z * sC;
                *reinterpret_cast<__half2*>(C + (size_t)gm * N + gn) =
                    __floats2half2_rn(v0, v1);
                *reinterpret_cast<__half2*>(C + (size_t)(gm + 8) * N + gn) =
                    __floats2half2_rn(v2, v3);
            } else {
                float* C = (float*)Cout + (size_t)z * sC;
                *reinterpret_cast<float2*>(C + (size_t)gm * N + gn) = make_float2(v0, v1);
                *reinterpret_cast<float2*>(C + (size_t)(gm + 8) * N + gn) = make_float2(v2, v3);
            }
        }
    }
}

// ---------------------------------------------------------------------------
// Kernel 3: gates + mix + towers + sigmoid (eo now fp16)
// ---------------------------------------------------------------------------
__global__ void __launch_bounds__(256)
head_kernel(const float* __restrict__ S, const __half* __restrict__ eo,
            const float* __restrict__ gW, const float* __restrict__ gb,
            const float* __restrict__ tW1, const float* __restrict__ tb1,
            const float* __restrict__ tW2, const float* __restrict__ tb2,
            const float* __restrict__ tW3, const float* __restrict__ tb3,
            float* __restrict__ out)
{
    __shared__ float Srow[4][CONCAT];
    __shared__ float gate[4][16];
    __shared__ float ti[4][NTASK][EOUT];
    __shared__ float x1[4][NTASK][64];
    __shared__ float x2[4][NTASK][32];

    const int g = threadIdx.x >> 6;
    const int lane = threadIdx.x & 63;
    const int b = blockIdx.x * 4 + g;

    for (int c = lane; c < CONCAT; c += 64) Srow[g][c] = S[(long)b * CONCAT + c];
    __syncthreads();

    {
        const int o = lane >> 2;
        const int q = lane & 3;
        const int t = o >> 3, e = o & 7;
        const int c0 = q * 61;
        float a0 = 0.f, a1 = 0.f, a2 = 0.f, a3 = 0.f;
        #pragma unroll
        for (int i = 0; i < 60; i += 4) {
            a0 += Srow[g][c0 + i]     * __ldg(&gW[((long)t * CONCAT + c0 + i)     * 8 + e]);
            a1 += Srow[g][c0 + i + 1] * __ldg(&gW[((long)t * CONCAT + c0 + i + 1) * 8 + e]);
            a2 += Srow[g][c0 + i + 2] * __ldg(&gW[((long)t * CONCAT + c0 + i + 2) * 8 + e]);
            a3 += Srow[g][c0 + i + 3] * __ldg(&gW[((long)t * CONCAT + c0 + i + 3) * 8 + e]);
        }
        a0 += Srow[g][c0 + 60] * __ldg(&gW[((long)t * CONCAT + c0 + 60) * 8 + e]);
        float acc = (a0 + a1) + (a2 + a3);
        acc += __shfl_xor_sync(0xffffffffu, acc, 1);
        acc += __shfl_xor_sync(0xffffffffu, acc, 2);
        if (q == 0) gate[g][o] = acc + gb[t * 8 + e];
    }
    __syncthreads();
    if (lane < 2) {
        const int t = lane;
        float mx = -3.4e38f;
        for (int e = 0; e < 8; e++) mx = fmaxf(mx, gate[g][t * 8 + e]);
        float sum = 0.f, ex[8];
        for (int e = 0; e < 8; e++) { ex[e] = __expf(gate[g][t * 8 + e] - mx); sum += ex[e]; }
        const float is = 1.f / sum;
        for (int e = 0; e < 8; e++) gate[g][t * 8 + e] = ex[e] * is;
    }
    __syncthreads();

    {
        const int t = lane >> 5;
        const int o = (lane & 31) * 4;
        float4 acc = make_float4(0.f, 0.f, 0.f, 0.f);
        #pragma unroll
        for (int e = 0; e < 8; e++) {
            const float gv = gate[g][t * 8 + e];
            const __half2* ep = reinterpret_cast<const __half2*>(
                eo + ((long)e * BATCH + b) * EOUT + o);
            const __half2 v01 = ep[0], v23 = ep[1];
            acc.x += gv * __low2float(v01);
            acc.y += gv * __high2float(v01);
            acc.z += gv * __low2float(v23);
            acc.w += gv * __high2float(v23);
        }
        *reinterpret_cast<float4*>(&ti[g][t][o]) = acc;
    }
    __syncthreads();

    for (int idx = lane; idx < NTASK * 64; idx += 64) {
        const int t = idx >> 6, j = idx & 63;
        float a0 = tb1[t * 64 + j], a1 = 0.f, a2 = 0.f, a3 = 0.f;
        #pragma unroll
        for (int o = 0; o < 128; o += 4) {
            a0 += ti[g][t][o]     * __ldg(&tW1[((long)t * 128 + o)     * 64 + j]);
            a1 += ti[g][t][o + 1] * __ldg(&tW1[((long)t * 128 + o + 1) * 64 + j]);
            a2 += ti[g][t][o + 2] * __ldg(&tW1[((long)t * 128 + o + 2) * 64 + j]);
            a3 += ti[g][t][o + 3] * __ldg(&tW1[((long)t * 128 + o + 3) * 64 + j]);
        }
        x1[g][t][j] = fmaxf((a0 + a1) + (a2 + a3), 0.f);
    }
    __syncthreads();

    {
        const int t = lane >> 5, m = lane & 31;
        float a0 = tb2[t * 32 + m], a1 = 0.f, a2 = 0.f, a3 = 0.f;
        #pragma unroll
        for (int j = 0; j < 64; j += 4) {
            a0 += x1[g][t][j]     * __ldg(&tW2[(t * 64 + j)     * 32 + m]);
            a1 += x1[g][t][j + 1] * __ldg(&tW2[(t * 64 + j + 1) * 32 + m]);
            a2 += x1[g][t][j + 2] * __ldg(&tW2[(t * 64 + j + 2) * 32 + m]);
            a3 += x1[g][t][j + 3] * __ldg(&tW2[(t * 64 + j + 3) * 32 + m]);
        }
        x2[g][t][m] = fmaxf((a0 + a1) + (a2 + a3), 0.f);
    }
    __syncthreads();

    if (lane < 2) {
        const int t = lane;
        float a0 = tb3[t], a1 = 0.f, a2 = 0.f, a3 = 0.f;
        #pragma unroll
        for (int m = 0; m < 32; m += 4) {
            a0 += x2[g][t][m]     * tW3[t * 32 + m];
            a1 += x2[g][t][m + 1] * tW3[t * 32 + m + 1];
            a2 += x2[g][t][m + 2] * tW3[t * 32 + m + 2];
            a3 += x2[g][t][m + 3] * tW3[t * 32 + m + 3];
        }
        const float acc = (a0 + a1) + (a2 + a3);
        out[(long)t * BATCH + b] = 1.f / (1.f + __expf(-acc));
    }
}

// ---------------------------------------------------------------------------
// Launch
// ---------------------------------------------------------------------------
extern "C" void kernel_launch(void* const* d_in, const int* in_sizes, int n_in,
                              void* d_out, int out_size)
{
    const int*   uid    = (const int*)  d_in[0];
    const int*   iid    = (const int*)  d_in[1];
    const int*   cid    = (const int*)  d_in[2];
    const int*   did    = (const int*)  d_in[3];
    const float* udense = (const float*)d_in[4];
    const float* idense = (const float*)d_in[5];
    const int*   hseq   = (const int*)  d_in[6];
    const float* userE  = (const float*)d_in[7];
    const float* itemE  = (const float*)d_in[8];
    const float* catE   = (const float*)d_in[9];
    const float* durE   = (const float*)d_in[10];
    const float* histE  = (const float*)d_in[11];
    const float* Wproj  = (const float*)d_in[12];
    const float* aW1    = (const float*)d_in[13];
    const float* ab1    = (const float*)d_in[14];
    const float* aW2    = (const float*)d_in[15];
    const float* ab2    = (const float*)d_in[16];
    const float* aW3    = (const float*)d_in[17];
    const float* ab3    = (const float*)d_in[18];
    const float* eW1    = (const float*)d_in[19];
    const float* eb1    = (const float*)d_in[20];
    const float* eW2    = (const float*)d_in[21];
    const float* eb2    = (const float*)d_in[22];
    const float* gW     = (const float*)d_in[23];
    const float* gb     = (const float*)d_in[24];
    const float* tW1    = (const float*)d_in[25];
    const float* tb1    = (const float*)d_in[26];
    const float* tW2    = (const float*)d_in[27];
    const float* tb2    = (const float*)d_in[28];
    const float* tW3    = (const float*)d_in[29];
    const float* tb3    = (const float*)d_in[30];
    float* out = (float*)d_out;

    float  *pS, *pBase, *pWb;
    __half *pSh, *pEh, *pEo, *pW1t, *pW2t, *pT16, *pPt, *pW3t, *pAW2t, *pH16;
    cudaGetSymbolAddress((void**)&pS,    g_S);
    cudaGetSymbolAddress((void**)&pSh,   g_Sh);
    cudaGetSymbolAddress((void**)&pEh,   g_ehh);
    cudaGetSymbolAddress((void**)&pEo,   g_eo);
    cudaGetSymbolAddress((void**)&pW1t,  g_W1t);
    cudaGetSymbolAddress((void**)&pW2t,  g_W2t);
    cudaGetSymbolAddress((void**)&pT16,  g_t16);
    cudaGetSymbolAddress((void**)&pBase, g_base);
    cudaGetSymbolAddress((void**)&pPt,   g_Pt);
    cudaGetSymbolAddress((void**)&pW3t,  g_W3t);
    cudaGetSymbolAddress((void**)&pAW2t, g_aW2t);
    cudaGetSymbolAddress((void**)&pWb,   g_Wb);
    cudaGetSymbolAddress((void**)&pH16,  g_hist16);

    const int attn_smem = (int)sizeof(AttnSmem);
    const int tb_smem   = (int)sizeof(TBSmem);
    cudaFuncSetAttribute(attn_kernel,  cudaFuncAttributeMaxDynamicSharedMemorySize, attn_smem);
    cudaFuncSetAttribute(tbase_kernel, cudaFuncAttributeMaxDynamicSharedMemorySize, tb_smem);
    cudaFuncSetAttribute(hgemm_bias_relu<true>,  cudaFuncAttributeMaxDynamicSharedMemorySize, HGEMM_SMEM);
    cudaFuncSetAttribute(hgemm_bias_relu<false>, cudaFuncAttributeMaxDynamicSharedMemorySize, HGEMM_SMEM);

    // K0: weight prep + history fp16 conversion + per-row t/base
    prep_weights<<<(N_PREP + 255) / 256, 256>>>(
        eW1, eW2, aW1, aW2, pW1t, pW2t, pPt, pW3t, pAW2t, pWb);
    conv_hist<<<(int)((N_HIST2 + 255) / 256), 256>>>(histE, pH16);
    tbase_kernel<<<BATCH / 64, 256, tb_smem>>>(
        iid, itemE, Wproj, pWb, ab1, pT16, pBase);

    // K1: attention + feature concat
    attn_kernel<<<BATCH, 256, attn_smem>>>(
        uid, iid, cid, did, udense, idense, hseq,
        userE, itemE, catE, durE, pH16,
        pT16, pBase, pPt, pW3t, pAW2t, aW3, ab3, ab2, pS, pSh);

    // K2a: eh = relu(S @ eW1 + eb1), fp16 out
    hgemm_bias_relu<true><<<dim3(EHID / TBN, BATCH / TBM, NEXP), 256, HGEMM_SMEM>>>(
        pSh, pW1t, eb1, pEh,
        BATCH, EHID,
        (size_t)0, (size_t)EHID * KPAD, (size_t)EHID, (size_t)BATCH * EHID);

    // K2b: eo = relu(eh @ eW2 + eb2), fp16 out
    hgemm_bias_relu<true><<<dim3(EOUT / TBN, BATCH / TBM, NEXP), 256, HGEMM_SMEM>>>(
        pEh, pW2t, eb2, pEo,
        BATCH, EOUT,
        (size_t)BATCH * EHID, (size_t)EOUT * KPAD, (size_t)EOUT, (size_t)BATCH * EOUT);

    // K3: gates + mix + towers + sigmoid
    head_kernel<<<BATCH / 4, 256>>>(
        pS, pEo, gW, gb, tW1, tb1, tW2, tb2, tW3, tb3, out);
}